// round 1
// baseline (speedup 1.0000x reference)
#include <cuda_runtime.h>
#include <math.h>
#include <stdint.h>
#include <stddef.h>

#define N1V 8192
#define N2V 8192
#define DD  1024
#define FF  800

#define BM 128
#define BN 128
#define BKT 16
#define TM 8
#define TN 8

// ---------------- scratch (device globals; no allocation allowed) ----------------
__device__ float g_raw[(size_t)N1V * N2V];    // raw logits, then overwritten with alpha2
__device__ float g_p1[(size_t)N1V * N2V];     // g_p1[i*N2+j] = alpha1[j,i]  ([K,M] layout for GEMM)
__device__ float g_att1[(size_t)N2V * DD];    // attended_m1
__device__ float g_att2[(size_t)N1V * DD];    // attended_m2
__device__ float g_rmax[N1V], g_rinv[N1V];
__device__ float g_cmax[N2V], g_cinv[N2V];
__device__ float g_spart1[8 * DD], g_spart2[8 * DD];   // partial column sums of att1/att2
__device__ float g_sumv1[DD], g_sumv2[DD];             // column sums (means * 8192)
__device__ float g_tpart1[64 * FF], g_tpart2[64 * FF]; // per-M-block tanh column sums

// ---------------- GEMM ----------------
// AMODE 0: A row-major [M,K].  AMODE 1: A row-major [K,M].
// BMODE 0: B row-major [N,K] (C = A.Bt).  BMODE 1: B row-major [K,N].
// EPI 0: store C.  EPI 1: v=tanh(acc+bias[n]); deterministic per-block column sums -> colpart[by*N+n]
template<int AMODE, int BMODE, int EPI>
__global__ __launch_bounds__(256, 2)
void gemm_kernel(const float* __restrict__ A, const float* __restrict__ B,
                 float* __restrict__ C, int M, int N, int K,
                 const float* __restrict__ bias, float* __restrict__ colpart)
{
    __shared__ float As[2][BKT][BM + 4];
    __shared__ float Bs[2][BKT][BN + 4];

    const int tid  = threadIdx.x;
    const int m0   = blockIdx.y * BM;
    const int n0   = blockIdx.x * BN;
    const int trow = (tid >> 4) * TM;
    const int tcol = (tid & 15) * TN;

    float acc[TM][TN];
#pragma unroll
    for (int i = 0; i < TM; i++)
#pragma unroll
        for (int j = 0; j < TN; j++) acc[i][j] = 0.f;

    float4 ra[2], rb[2];
    const int ntiles = K / BKT;

    auto gload = [&](int k0) {
#pragma unroll
        for (int i = 0; i < 2; i++) {
            int idx = tid + i * 256;
            if (AMODE == 0) {
                int m = idx >> 2, k4 = (idx & 3) << 2;
                ra[i] = *reinterpret_cast<const float4*>(A + (size_t)(m0 + m) * K + k0 + k4);
            } else {
                int k = idx >> 5, m4 = (idx & 31) << 2;
                ra[i] = *reinterpret_cast<const float4*>(A + (size_t)(k0 + k) * M + m0 + m4);
            }
            if (BMODE == 0) {
                int n = idx >> 2, k4 = (idx & 3) << 2;
                if (n0 + n < N)
                    rb[i] = *reinterpret_cast<const float4*>(B + (size_t)(n0 + n) * K + k0 + k4);
                else
                    rb[i] = make_float4(0.f, 0.f, 0.f, 0.f);
            } else {
                int k = idx >> 5, n4 = (idx & 31) << 2;
                rb[i] = *reinterpret_cast<const float4*>(B + (size_t)(k0 + k) * N + n0 + n4);
            }
        }
    };
    auto sstore = [&](int buf) {
#pragma unroll
        for (int i = 0; i < 2; i++) {
            int idx = tid + i * 256;
            if (AMODE == 0) {
                int m = idx >> 2, k4 = (idx & 3) << 2;
                As[buf][k4 + 0][m] = ra[i].x;
                As[buf][k4 + 1][m] = ra[i].y;
                As[buf][k4 + 2][m] = ra[i].z;
                As[buf][k4 + 3][m] = ra[i].w;
            } else {
                int k = idx >> 5, m4 = (idx & 31) << 2;
                *reinterpret_cast<float4*>(&As[buf][k][m4]) = ra[i];
            }
            if (BMODE == 0) {
                int n = idx >> 2, k4 = (idx & 3) << 2;
                Bs[buf][k4 + 0][n] = rb[i].x;
                Bs[buf][k4 + 1][n] = rb[i].y;
                Bs[buf][k4 + 2][n] = rb[i].z;
                Bs[buf][k4 + 3][n] = rb[i].w;
            } else {
                int k = idx >> 5, n4 = (idx & 31) << 2;
                *reinterpret_cast<float4*>(&Bs[buf][k][n4]) = rb[i];
            }
        }
    };

    gload(0);
    sstore(0);
    __syncthreads();

    int buf = 0;
    for (int t = 0; t < ntiles; t++) {
        if (t + 1 < ntiles) gload((t + 1) * BKT);
#pragma unroll
        for (int kk = 0; kk < BKT; kk++) {
            float a[TM], b[TN];
            *reinterpret_cast<float4*>(&a[0]) = *reinterpret_cast<const float4*>(&As[buf][kk][trow]);
            *reinterpret_cast<float4*>(&a[4]) = *reinterpret_cast<const float4*>(&As[buf][kk][trow + 4]);
            *reinterpret_cast<float4*>(&b[0]) = *reinterpret_cast<const float4*>(&Bs[buf][kk][tcol]);
            *reinterpret_cast<float4*>(&b[4]) = *reinterpret_cast<const float4*>(&Bs[buf][kk][tcol + 4]);
#pragma unroll
            for (int i = 0; i < TM; i++)
#pragma unroll
                for (int j = 0; j < TN; j++)
                    acc[i][j] = fmaf(a[i], b[j], acc[i][j]);
        }
        if (t + 1 < ntiles) {
            buf ^= 1;
            sstore(buf);
            __syncthreads();
        }
    }

    if (EPI == 0) {
#pragma unroll
        for (int i = 0; i < TM; i++) {
            float* cp = C + (size_t)(m0 + trow + i) * N + n0 + tcol;
            *reinterpret_cast<float4*>(cp)     = make_float4(acc[i][0], acc[i][1], acc[i][2], acc[i][3]);
            *reinterpret_cast<float4*>(cp + 4) = make_float4(acc[i][4], acc[i][5], acc[i][6], acc[i][7]);
        }
    } else {
        // tanh + deterministic column sums
        float p[TN];
#pragma unroll
        for (int j = 0; j < TN; j++) p[j] = 0.f;
#pragma unroll
        for (int j = 0; j < TN; j++) {
            int n = n0 + tcol + j;
            if (n < N) {
                float bj = bias[n];
#pragma unroll
                for (int i = 0; i < TM; i++)
                    p[j] += tanhf(acc[i][j] + bj);
            }
        }
        __syncthreads();
        float (*sh)[BN + 4] = reinterpret_cast<float (*)[BN + 4]>(&As[0][0][0]);
        int ty = tid >> 4;
#pragma unroll
        for (int j = 0; j < TN; j++) sh[ty][tcol + j] = p[j];
        __syncthreads();
        if (tid < BN && (n0 + tid) < N) {
            float s = 0.f;
#pragma unroll
            for (int w = 0; w < 16; w++) s += sh[w][tid];
            colpart[(size_t)blockIdx.y * N + n0 + tid] = s;
        }
    }
}

// ---------------- softmax statistics ----------------
__global__ void row_stats_kernel()
{
    int row = blockIdx.x;
    const float* r = g_raw + (size_t)row * N2V;
    int tid = threadIdx.x;
    float m = -1e30f, s = 0.f;
#pragma unroll 4
    for (int j = tid; j < N2V; j += 256) {
        float v = r[j];
        float mn = fmaxf(m, v);
        s = s * __expf(m - mn) + __expf(v - mn);
        m = mn;
    }
#pragma unroll
    for (int o = 16; o; o >>= 1) {
        float mo = __shfl_xor_sync(0xffffffffu, m, o);
        float so = __shfl_xor_sync(0xffffffffu, s, o);
        float mn = fmaxf(m, mo);
        s = s * __expf(m - mn) + so * __expf(mo - mn);
        m = mn;
    }
    __shared__ float sm[8], ss[8];
    if ((tid & 31) == 0) { sm[tid >> 5] = m; ss[tid >> 5] = s; }
    __syncthreads();
    if (tid == 0) {
        float M = sm[0], S = ss[0];
        for (int w = 1; w < 8; w++) {
            float mn = fmaxf(M, sm[w]);
            S = S * __expf(M - mn) + ss[w] * __expf(sm[w] - mn);
            M = mn;
        }
        g_rmax[row] = M;
        g_rinv[row] = 1.0f / S;
    }
}

__global__ void col_stats_kernel()
{
    int lane = threadIdx.x & 31;
    int c = blockIdx.x * 32 + lane;
    int stripe = threadIdx.x >> 5;
    float m = -1e30f, s = 0.f;
#pragma unroll 4
    for (int r = stripe; r < N1V; r += 8) {
        float v = g_raw[(size_t)r * N2V + c];
        float mn = fmaxf(m, v);
        s = s * __expf(m - mn) + __expf(v - mn);
        m = mn;
    }
    __shared__ float sm[8][33], ss[8][33];
    sm[stripe][lane] = m;
    ss[stripe][lane] = s;
    __syncthreads();
    if (threadIdx.x < 32) {
        float M = sm[0][threadIdx.x], S = ss[0][threadIdx.x];
#pragma unroll
        for (int w = 1; w < 8; w++) {
            float mn = fmaxf(M, sm[w][threadIdx.x]);
            S = S * __expf(M - mn) + ss[w][threadIdx.x] * __expf(sm[w][threadIdx.x] - mn);
            M = mn;
        }
        int cc = blockIdx.x * 32 + threadIdx.x;
        g_cmax[cc] = M;
        g_cinv[cc] = 1.0f / S;
    }
}

// read raw, write alpha2 in place + alpha1 values (transposed layout) to g_p1
__global__ void softmax_mat_kernel()
{
    int v4 = blockIdx.x * 256 + threadIdx.x;   // one float4 each; grid = 65536
    int row  = v4 >> 11;                       // 2048 float4 per row
    int col4 = v4 & 2047;
    float4* rawp = reinterpret_cast<float4*>(g_raw) + (size_t)v4;
    float4 r = *rawp;
    float rm = g_rmax[row], ri = g_rinv[row];
    float4 cm = *(reinterpret_cast<const float4*>(g_cmax) + col4);
    float4 ci = *(reinterpret_cast<const float4*>(g_cinv) + col4);
    float4 a2, a1;
    a2.x = __expf(r.x - rm) * ri;  a2.y = __expf(r.y - rm) * ri;
    a2.z = __expf(r.z - rm) * ri;  a2.w = __expf(r.w - rm) * ri;
    a1.x = __expf(r.x - cm.x) * ci.x;  a1.y = __expf(r.y - cm.y) * ci.y;
    a1.z = __expf(r.z - cm.z) * ci.z;  a1.w = __expf(r.w - cm.w) * ci.w;
    *rawp = a2;
    *(reinterpret_cast<float4*>(g_p1) + (size_t)v4) = a1;
}

// ---------------- column sums of attended matrices ----------------
__global__ void col_sum_kernel(const float* __restrict__ a, float* __restrict__ part)
{
    int lane = threadIdx.x & 31;
    int c = blockIdx.x * 32 + lane;
    int stripe = threadIdx.x >> 5;
    int r0 = blockIdx.y * (N1V / 8);  // 1024-row chunk
    float s = 0.f;
#pragma unroll 4
    for (int r = 0; r < 1024; r += 8)
        s += a[(size_t)(r0 + r + stripe) * DD + c];
    __shared__ float sh[8][33];
    sh[stripe][lane] = s;
    __syncthreads();
    if (threadIdx.x < 32) {
        float t = 0.f;
#pragma unroll
        for (int w = 0; w < 8; w++) t += sh[w][threadIdx.x];
        part[blockIdx.y * DD + blockIdx.x * 32 + threadIdx.x] = t;
    }
}

__global__ void sumv_kernel()
{
    int i = blockIdx.x * 256 + threadIdx.x;
    if (i < DD) {
        float s = 0.f;
#pragma unroll
        for (int w = 0; w < 8; w++) s += g_spart1[w * DD + i];
        g_sumv1[i] = s;
    } else if (i < 2 * DD) {
        int c = i - DD;
        float s = 0.f;
#pragma unroll
        for (int w = 0; w < 8; w++) s += g_spart2[w * DD + c];
        g_sumv2[c] = s;
    }
}

// ---------------- finalize: filters (matvec) + output ----------------
__global__ void finalize_kernel(const float* __restrict__ Wf1, const float* __restrict__ bf1,
                                const float* __restrict__ Wf2, const float* __restrict__ bf2,
                                float* __restrict__ out)
{
    int g = blockIdx.x * 8 + (threadIdx.x >> 5);  // warp per output element; grid 200
    int lane = threadIdx.x & 31;
    const float inv = 1.0f / 8192.0f;
    if (g < FF) {
        const float* w = Wf1 + (size_t)g * DD;
        float d = 0.f;
        for (int l = lane; l < DD; l += 32) d += w[l] * g_sumv2[l];
#pragma unroll
        for (int o = 16; o; o >>= 1) d += __shfl_xor_sync(0xffffffffu, d, o);
        if (lane == 0) {
            float filt = 1.0f / (1.0f + __expf(-(d * inv + bf1[g])));
            float t = 0.f;
            for (int b = 0; b < 64; b++) t += g_tpart1[b * FF + g];
            out[g] = t * inv * filt;
        }
    } else {
        int f = g - FF;
        const float* w = Wf2 + (size_t)f * DD;
        float d = 0.f;
        for (int l = lane; l < DD; l += 32) d += w[l] * g_sumv1[l];
#pragma unroll
        for (int o = 16; o; o >>= 1) d += __shfl_xor_sync(0xffffffffu, d, o);
        if (lane == 0) {
            float filt = 1.0f / (1.0f + __expf(-(d * inv + bf2[f])));
            float t = 0.f;
            for (int b = 0; b < 64; b++) t += g_tpart2[b * FF + f];
            out[FF + f] = t * inv * filt;
        }
    }
}

// ---------------- launch ----------------
extern "C" void kernel_launch(void* const* d_in, const int* in_sizes, int n_in,
                              void* d_out, int out_size)
{
    const float* m1  = (const float*)d_in[0];
    const float* m2  = (const float*)d_in[1];
    const float* Wf1 = (const float*)d_in[2];
    const float* bf1 = (const float*)d_in[3];
    const float* Wf2 = (const float*)d_in[4];
    const float* bf2 = (const float*)d_in[5];
    const float* W1  = (const float*)d_in[6];
    const float* b1  = (const float*)d_in[7];
    const float* W2  = (const float*)d_in[8];
    const float* b2  = (const float*)d_in[9];
    float* out = (float*)d_out;

    float *raw, *p1, *att1, *att2, *spart1, *spart2, *tpart1, *tpart2;
    cudaGetSymbolAddress((void**)&raw,    g_raw);
    cudaGetSymbolAddress((void**)&p1,     g_p1);
    cudaGetSymbolAddress((void**)&att1,   g_att1);
    cudaGetSymbolAddress((void**)&att2,   g_att2);
    cudaGetSymbolAddress((void**)&spart1, g_spart1);
    cudaGetSymbolAddress((void**)&spart2, g_spart2);
    cudaGetSymbolAddress((void**)&tpart1, g_tpart1);
    cudaGetSymbolAddress((void**)&tpart2, g_tpart2);

    // 1) raw = m1 @ m2^T   [8192 x 8192]
    gemm_kernel<0, 0, 0><<<dim3(N2V / BN, N1V / BM), 256>>>(
        m1, m2, raw, N1V, N2V, DD, nullptr, nullptr);

    // 2) softmax stats (rows and cols), then materialize alpha2 (in place) + alpha1 (g_p1)
    row_stats_kernel<<<N1V, 256>>>();
    col_stats_kernel<<<N2V / 32, 256>>>();
    softmax_mat_kernel<<<((size_t)N1V * N2V / 4) / 256, 256>>>();

    // 3) attended_m2 = alpha2 @ m2   [8192 x 1024], K = 8192
    gemm_kernel<0, 1, 0><<<dim3(DD / BN, N1V / BM), 256>>>(
        raw, m2, att2, N1V, DD, N2V, nullptr, nullptr);

    // 4) attended_m1 = alpha1 @ m1   [8192 x 1024], K = 8192 (A is [K,M] layout)
    gemm_kernel<1, 1, 0><<<dim3(DD / BN, N2V / BM), 256>>>(
        p1, m1, att1, N2V, DD, N1V, nullptr, nullptr);

    // 5) column sums of attended matrices (for filters)
    col_sum_kernel<<<dim3(DD / 32, 8), 256>>>(att1, spart1);
    col_sum_kernel<<<dim3(DD / 32, 8), 256>>>(att2, spart2);
    sumv_kernel<<<8, 256>>>();

    // 6) transformed = tanh(att @ W^T + b), fused column-sum epilogue
    gemm_kernel<0, 0, 1><<<dim3((FF + BN - 1) / BN, N2V / BM), 256>>>(
        att1, W1, nullptr, N2V, FF, DD, b1, tpart1);
    gemm_kernel<0, 0, 1><<<dim3((FF + BN - 1) / BN, N1V / BM), 256>>>(
        att2, W2, nullptr, N1V, FF, DD, b2, tpart2);

    // 7) filters + outputs
    finalize_kernel<<<200, 256>>>(Wf1, bf1, Wf2, bf2, out);
}

// round 2
// speedup vs baseline: 1.0005x; 1.0005x over previous
#include <cuda_runtime.h>
#include <math.h>
#include <stdint.h>
#include <stddef.h>

#define N1V 8192
#define N2V 8192
#define DD  1024
#define FF  800

#define BM 128
#define BN 128
#define BKT 16
#define TM 8
#define TN 8

// ---------------- scratch (device globals; no allocation allowed) ----------------
__device__ float g_raw[(size_t)N1V * N2V];    // raw logits, then overwritten with alpha2
__device__ float g_p1[(size_t)N1V * N2V];     // g_p1[i*N2+j] = alpha1[j,i]  ([K,M] layout for GEMM)
__device__ float g_att1[(size_t)N2V * DD];    // attended_m1
__device__ float g_att2[(size_t)N1V * DD];    // attended_m2
__device__ float g_rmax[N1V], g_rinv[N1V];
__device__ float g_cmax[N2V], g_cinv[N2V];
__device__ float g_spart1[8 * DD], g_spart2[8 * DD];   // partial column sums of att1/att2
__device__ float g_sumv1[DD], g_sumv2[DD];             // column sums (means * 8192)
__device__ float g_tpart1[64 * FF], g_tpart2[64 * FF]; // per-M-block tanh column sums

// ---------------- GEMM ----------------
// AMODE 0: A row-major [M,K].  AMODE 1: A row-major [K,M].
// BMODE 0: B row-major [N,K] (C = A.Bt).  BMODE 1: B row-major [K,N].
// EPI 0: store C.  EPI 1: v=tanh(acc+bias[n]); deterministic per-block column sums -> colpart[by*N+n]
template<int AMODE, int BMODE, int EPI>
__global__ __launch_bounds__(256, 2)
void gemm_kernel(const float* __restrict__ A, const float* __restrict__ B,
                 float* __restrict__ C, int M, int N, int K,
                 const float* __restrict__ bias, float* __restrict__ colpart)
{
    __shared__ float As[2][BKT][BM + 4];
    __shared__ float Bs[2][BKT][BN + 4];

    const int tid  = threadIdx.x;
    const int m0   = blockIdx.y * BM;
    const int n0   = blockIdx.x * BN;
    const int trow = (tid >> 4) * TM;
    const int tcol = (tid & 15) * TN;

    float acc[TM][TN];
#pragma unroll
    for (int i = 0; i < TM; i++)
#pragma unroll
        for (int j = 0; j < TN; j++) acc[i][j] = 0.f;

    float4 ra[2], rb[2];
    const int ntiles = K / BKT;

    auto gload = [&](int k0) {
#pragma unroll
        for (int i = 0; i < 2; i++) {
            int idx = tid + i * 256;
            if (AMODE == 0) {
                int m = idx >> 2, k4 = (idx & 3) << 2;
                ra[i] = *reinterpret_cast<const float4*>(A + (size_t)(m0 + m) * K + k0 + k4);
            } else {
                int k = idx >> 5, m4 = (idx & 31) << 2;
                ra[i] = *reinterpret_cast<const float4*>(A + (size_t)(k0 + k) * M + m0 + m4);
            }
            if (BMODE == 0) {
                int n = idx >> 2, k4 = (idx & 3) << 2;
                if (n0 + n < N)
                    rb[i] = *reinterpret_cast<const float4*>(B + (size_t)(n0 + n) * K + k0 + k4);
                else
                    rb[i] = make_float4(0.f, 0.f, 0.f, 0.f);
            } else {
                int k = idx >> 5, n4 = (idx & 31) << 2;
                rb[i] = *reinterpret_cast<const float4*>(B + (size_t)(k0 + k) * N + n0 + n4);
            }
        }
    };
    auto sstore = [&](int buf) {
#pragma unroll
        for (int i = 0; i < 2; i++) {
            int idx = tid + i * 256;
            if (AMODE == 0) {
                int m = idx >> 2, k4 = (idx & 3) << 2;
                As[buf][k4 + 0][m] = ra[i].x;
                As[buf][k4 + 1][m] = ra[i].y;
                As[buf][k4 + 2][m] = ra[i].z;
                As[buf][k4 + 3][m] = ra[i].w;
            } else {
                int k = idx >> 5, m4 = (idx & 31) << 2;
                *reinterpret_cast<float4*>(&As[buf][k][m4]) = ra[i];
            }
            if (BMODE == 0) {
                int n = idx >> 2, k4 = (idx & 3) << 2;
                Bs[buf][k4 + 0][n] = rb[i].x;
                Bs[buf][k4 + 1][n] = rb[i].y;
                Bs[buf][k4 + 2][n] = rb[i].z;
                Bs[buf][k4 + 3][n] = rb[i].w;
            } else {
                int k = idx >> 5, n4 = (idx & 31) << 2;
                *reinterpret_cast<float4*>(&Bs[buf][k][n4]) = rb[i];
            }
        }
    };

    gload(0);
    sstore(0);
    __syncthreads();

    int buf = 0;
    for (int t = 0; t < ntiles; t++) {
        if (t + 1 < ntiles) gload((t + 1) * BKT);
#pragma unroll
        for (int kk = 0; kk < BKT; kk++) {
            float a[TM], b[TN];
            *reinterpret_cast<float4*>(&a[0]) = *reinterpret_cast<const float4*>(&As[buf][kk][trow]);
            *reinterpret_cast<float4*>(&a[4]) = *reinterpret_cast<const float4*>(&As[buf][kk][trow + 4]);
            *reinterpret_cast<float4*>(&b[0]) = *reinterpret_cast<const float4*>(&Bs[buf][kk][tcol]);
            *reinterpret_cast<float4*>(&b[4]) = *reinterpret_cast<const float4*>(&Bs[buf][kk][tcol + 4]);
#pragma unroll
            for (int i = 0; i < TM; i++)
#pragma unroll
                for (int j = 0; j < TN; j++)
                    acc[i][j] = fmaf(a[i], b[j], acc[i][j]);
        }
        if (t + 1 < ntiles) {
            buf ^= 1;
            sstore(buf);
            __syncthreads();
        }
    }

    if (EPI == 0) {
#pragma unroll
        for (int i = 0; i < TM; i++) {
            float* cp = C + (size_t)(m0 + trow + i) * N + n0 + tcol;
            *reinterpret_cast<float4*>(cp)     = make_float4(acc[i][0], acc[i][1], acc[i][2], acc[i][3]);
            *reinterpret_cast<float4*>(cp + 4) = make_float4(acc[i][4], acc[i][5], acc[i][6], acc[i][7]);
        }
    } else {
        // tanh + deterministic column sums
        float p[TN];
#pragma unroll
        for (int j = 0; j < TN; j++) p[j] = 0.f;
#pragma unroll
        for (int j = 0; j < TN; j++) {
            int n = n0 + tcol + j;
            if (n < N) {
                float bj = bias[n];
#pragma unroll
                for (int i = 0; i < TM; i++)
                    p[j] += tanhf(acc[i][j] + bj);
            }
        }
        __syncthreads();
        float (*sh)[BN + 4] = reinterpret_cast<float (*)[BN + 4]>(&As[0][0][0]);
        int ty = tid >> 4;
#pragma unroll
        for (int j = 0; j < TN; j++) sh[ty][tcol + j] = p[j];
        __syncthreads();
        if (tid < BN && (n0 + tid) < N) {
            float s = 0.f;
#pragma unroll
            for (int w = 0; w < 16; w++) s += sh[w][tid];
            colpart[(size_t)blockIdx.y * N + n0 + tid] = s;
        }
    }
}

// ---------------- softmax statistics ----------------
__global__ void row_stats_kernel()
{
    int row = blockIdx.x;
    const float* r = g_raw + (size_t)row * N2V;
    int tid = threadIdx.x;
    float m = -1e30f, s = 0.f;
#pragma unroll 4
    for (int j = tid; j < N2V; j += 256) {
        float v = r[j];
        float mn = fmaxf(m, v);
        s = s * __expf(m - mn) + __expf(v - mn);
        m = mn;
    }
#pragma unroll
    for (int o = 16; o; o >>= 1) {
        float mo = __shfl_xor_sync(0xffffffffu, m, o);
        float so = __shfl_xor_sync(0xffffffffu, s, o);
        float mn = fmaxf(m, mo);
        s = s * __expf(m - mn) + so * __expf(mo - mn);
        m = mn;
    }
    __shared__ float sm[8], ss[8];
    if ((tid & 31) == 0) { sm[tid >> 5] = m; ss[tid >> 5] = s; }
    __syncthreads();
    if (tid == 0) {
        float M = sm[0], S = ss[0];
        for (int w = 1; w < 8; w++) {
            float mn = fmaxf(M, sm[w]);
            S = S * __expf(M - mn) + ss[w] * __expf(sm[w] - mn);
            M = mn;
        }
        g_rmax[row] = M;
        g_rinv[row] = 1.0f / S;
    }
}

__global__ void col_stats_kernel()
{
    int lane = threadIdx.x & 31;
    int c = blockIdx.x * 32 + lane;
    int stripe = threadIdx.x >> 5;
    float m = -1e30f, s = 0.f;
#pragma unroll 4
    for (int r = stripe; r < N1V; r += 8) {
        float v = g_raw[(size_t)r * N2V + c];
        float mn = fmaxf(m, v);
        s = s * __expf(m - mn) + __expf(v - mn);
        m = mn;
    }
    __shared__ float sm[8][33], ss[8][33];
    sm[stripe][lane] = m;
    ss[stripe][lane] = s;
    __syncthreads();
    if (threadIdx.x < 32) {
        float M = sm[0][threadIdx.x], S = ss[0][threadIdx.x];
#pragma unroll
        for (int w = 1; w < 8; w++) {
            float mn = fmaxf(M, sm[w][threadIdx.x]);
            S = S * __expf(M - mn) + ss[w][threadIdx.x] * __expf(sm[w][threadIdx.x] - mn);
            M = mn;
        }
        int cc = blockIdx.x * 32 + threadIdx.x;
        g_cmax[cc] = M;
        g_cinv[cc] = 1.0f / S;
    }
}

// read raw, write alpha2 in place + alpha1 values (transposed layout) to g_p1
__global__ void softmax_mat_kernel()
{
    int v4 = blockIdx.x * 256 + threadIdx.x;   // one float4 each; grid = 65536
    int row  = v4 >> 11;                       // 2048 float4 per row
    int col4 = v4 & 2047;
    float4* rawp = reinterpret_cast<float4*>(g_raw) + (size_t)v4;
    float4 r = *rawp;
    float rm = g_rmax[row], ri = g_rinv[row];
    float4 cm = *(reinterpret_cast<const float4*>(g_cmax) + col4);
    float4 ci = *(reinterpret_cast<const float4*>(g_cinv) + col4);
    float4 a2, a1;
    a2.x = __expf(r.x - rm) * ri;  a2.y = __expf(r.y - rm) * ri;
    a2.z = __expf(r.z - rm) * ri;  a2.w = __expf(r.w - rm) * ri;
    a1.x = __expf(r.x - cm.x) * ci.x;  a1.y = __expf(r.y - cm.y) * ci.y;
    a1.z = __expf(r.z - cm.z) * ci.z;  a1.w = __expf(r.w - cm.w) * ci.w;
    *rawp = a2;
    *(reinterpret_cast<float4*>(g_p1) + (size_t)v4) = a1;
}

// ---------------- column sums of attended matrices ----------------
__global__ void col_sum_kernel(const float* __restrict__ a, float* __restrict__ part)
{
    int lane = threadIdx.x & 31;
    int c = blockIdx.x * 32 + lane;
    int stripe = threadIdx.x >> 5;
    int r0 = blockIdx.y * (N1V / 8);  // 1024-row chunk
    float s = 0.f;
#pragma unroll 4
    for (int r = 0; r < 1024; r += 8)
        s += a[(size_t)(r0 + r + stripe) * DD + c];
    __shared__ float sh[8][33];
    sh[stripe][lane] = s;
    __syncthreads();
    if (threadIdx.x < 32) {
        float t = 0.f;
#pragma unroll
        for (int w = 0; w < 8; w++) t += sh[w][threadIdx.x];
        part[blockIdx.y * DD + blockIdx.x * 32 + threadIdx.x] = t;
    }
}

__global__ void sumv_kernel()
{
    int i = blockIdx.x * 256 + threadIdx.x;
    if (i < DD) {
        float s = 0.f;
#pragma unroll
        for (int w = 0; w < 8; w++) s += g_spart1[w * DD + i];
        g_sumv1[i] = s;
    } else if (i < 2 * DD) {
        int c = i - DD;
        float s = 0.f;
#pragma unroll
        for (int w = 0; w < 8; w++) s += g_spart2[w * DD + c];
        g_sumv2[c] = s;
    }
}

// ---------------- finalize: filters (matvec) + output ----------------
__global__ void finalize_kernel(const float* __restrict__ Wf1, const float* __restrict__ bf1,
                                const float* __restrict__ Wf2, const float* __restrict__ bf2,
                                float* __restrict__ out)
{
    int g = blockIdx.x * 8 + (threadIdx.x >> 5);  // warp per output element; grid 200
    int lane = threadIdx.x & 31;
    const float inv = 1.0f / 8192.0f;
    if (g < FF) {
        const float* w = Wf1 + (size_t)g * DD;
        float d = 0.f;
        for (int l = lane; l < DD; l += 32) d += w[l] * g_sumv2[l];
#pragma unroll
        for (int o = 16; o; o >>= 1) d += __shfl_xor_sync(0xffffffffu, d, o);
        if (lane == 0) {
            float filt = 1.0f / (1.0f + __expf(-(d * inv + bf1[g])));
            float t = 0.f;
            for (int b = 0; b < 64; b++) t += g_tpart1[b * FF + g];
            out[g] = t * inv * filt;
        }
    } else {
        int f = g - FF;
        const float* w = Wf2 + (size_t)f * DD;
        float d = 0.f;
        for (int l = lane; l < DD; l += 32) d += w[l] * g_sumv1[l];
#pragma unroll
        for (int o = 16; o; o >>= 1) d += __shfl_xor_sync(0xffffffffu, d, o);
        if (lane == 0) {
            float filt = 1.0f / (1.0f + __expf(-(d * inv + bf2[f])));
            float t = 0.f;
            for (int b = 0; b < 64; b++) t += g_tpart2[b * FF + f];
            out[FF + f] = t * inv * filt;
        }
    }
}

// ---------------- launch ----------------
extern "C" void kernel_launch(void* const* d_in, const int* in_sizes, int n_in,
                              void* d_out, int out_size)
{
    const float* m1  = (const float*)d_in[0];
    const float* m2  = (const float*)d_in[1];
    const float* Wf1 = (const float*)d_in[2];
    const float* bf1 = (const float*)d_in[3];
    const float* Wf2 = (const float*)d_in[4];
    const float* bf2 = (const float*)d_in[5];
    const float* W1  = (const float*)d_in[6];
    const float* b1  = (const float*)d_in[7];
    const float* W2  = (const float*)d_in[8];
    const float* b2  = (const float*)d_in[9];
    float* out = (float*)d_out;

    float *raw, *p1, *att1, *att2, *spart1, *spart2, *tpart1, *tpart2;
    cudaGetSymbolAddress((void**)&raw,    g_raw);
    cudaGetSymbolAddress((void**)&p1,     g_p1);
    cudaGetSymbolAddress((void**)&att1,   g_att1);
    cudaGetSymbolAddress((void**)&att2,   g_att2);
    cudaGetSymbolAddress((void**)&spart1, g_spart1);
    cudaGetSymbolAddress((void**)&spart2, g_spart2);
    cudaGetSymbolAddress((void**)&tpart1, g_tpart1);
    cudaGetSymbolAddress((void**)&tpart2, g_tpart2);

    // 1) raw = m1 @ m2^T   [8192 x 8192]
    gemm_kernel<0, 0, 0><<<dim3(N2V / BN, N1V / BM), 256>>>(
        m1, m2, raw, N1V, N2V, DD, nullptr, nullptr);

    // 2) softmax stats (rows and cols), then materialize alpha2 (in place) + alpha1 (g_p1)
    row_stats_kernel<<<N1V, 256>>>();
    col_stats_kernel<<<N2V / 32, 256>>>();
    softmax_mat_kernel<<<((size_t)N1V * N2V / 4) / 256, 256>>>();

    // 3) attended_m2 = alpha2 @ m2   [8192 x 1024], K = 8192
    gemm_kernel<0, 1, 0><<<dim3(DD / BN, N1V / BM), 256>>>(
        raw, m2, att2, N1V, DD, N2V, nullptr, nullptr);

    // 4) attended_m1 = alpha1 @ m1   [8192 x 1024], K = 8192 (A is [K,M] layout)
    gemm_kernel<1, 1, 0><<<dim3(DD / BN, N2V / BM), 256>>>(
        p1, m1, att1, N2V, DD, N1V, nullptr, nullptr);

    // 5) column sums of attended matrices (for filters)
    col_sum_kernel<<<dim3(DD / 32, 8), 256>>>(att1, spart1);
    col_sum_kernel<<<dim3(DD / 32, 8), 256>>>(att2, spart2);
    sumv_kernel<<<8, 256>>>();

    // 6) transformed = tanh(att @ W^T + b), fused column-sum epilogue
    gemm_kernel<0, 0, 1><<<dim3((FF + BN - 1) / BN, N2V / BM), 256>>>(
        att1, W1, nullptr, N2V, FF, DD, b1, tpart1);
    gemm_kernel<0, 0, 1><<<dim3((FF + BN - 1) / BN, N1V / BM), 256>>>(
        att2, W2, nullptr, N1V, FF, DD, b2, tpart2);

    // 7) filters + outputs
    finalize_kernel<<<200, 256>>>(Wf1, bf1, Wf2, bf2, out);
}

// round 4
// speedup vs baseline: 2.4450x; 2.4437x over previous
#include <cuda_runtime.h>
#include <cuda_fp16.h>
#include <math.h>
#include <stdint.h>
#include <stddef.h>

#define N1V 8192
#define N2V 8192
#define DD  1024
#define FF  800

// ======================= scratch (device globals) =======================
__device__ float g_raw [(size_t)N1V * N2V];   // raw logits, then alpha2 in place
__device__ float g_a1t [(size_t)N2V * N1V];   // alpha1 row-major [j, i]
__device__ float g_m1t [(size_t)DD * N1V];    // m1^T
__device__ float g_m2t [(size_t)DD * N2V];    // m2^T
__device__ float g_att1[(size_t)N2V * DD];
__device__ float g_att2[(size_t)N1V * DD];
__device__ float g_rmax[N1V], g_rinv[N1V];
__device__ float g_cmax[N2V], g_cinv[N2V];
__device__ float g_spart1[8 * DD], g_spart2[8 * DD];
__device__ float g_sumv1[DD], g_sumv2[DD];
__device__ float g_tpart1[896 * 64], g_tpart2[896 * 64];

// ======================= mma.sync helpers =======================
static __device__ __forceinline__ uint32_t smem_u32(const void* p) {
    uint32_t a;
    asm("{ .reg .u64 t; cvta.to.shared.u64 t, %1; cvt.u32.u64 %0, t; }" : "=r"(a) : "l"(p));
    return a;
}
static __device__ __forceinline__ void ldsm_x4(uint32_t& r0, uint32_t& r1, uint32_t& r2, uint32_t& r3, uint32_t addr) {
    asm volatile("ldmatrix.sync.aligned.m8n8.x4.shared.b16 {%0,%1,%2,%3}, [%4];"
                 : "=r"(r0), "=r"(r1), "=r"(r2), "=r"(r3) : "r"(addr));
}
static __device__ __forceinline__ void mma16816(float* d, const uint32_t* a, uint32_t b0, uint32_t b1) {
    asm volatile("mma.sync.aligned.m16n8k16.row.col.f32.f16.f16.f32 "
                 "{%0,%1,%2,%3}, {%4,%5,%6,%7}, {%8,%9}, {%0,%1,%2,%3};"
                 : "+f"(d[0]), "+f"(d[1]), "+f"(d[2]), "+f"(d[3])
                 : "r"(a[0]), "r"(a[1]), "r"(a[2]), "r"(a[3]), "r"(b0), "r"(b1));
}
static __device__ __forceinline__ void split4(float4 x, uint2& hi, uint2& lo) {
    __half2 h0 = __floats2half2_rn(x.x, x.y);
    __half2 h1 = __floats2half2_rn(x.z, x.w);
    float2 f0 = __half22float2(h0), f1 = __half22float2(h1);
    __half2 l0 = __floats2half2_rn(x.x - f0.x, x.y - f0.y);
    __half2 l1 = __floats2half2_rn(x.z - f1.x, x.w - f1.y);
    hi.x = *reinterpret_cast<uint32_t*>(&h0);
    hi.y = *reinterpret_cast<uint32_t*>(&h1);
    lo.x = *reinterpret_cast<uint32_t*>(&l0);
    lo.y = *reinterpret_cast<uint32_t*>(&l1);
}

// ======================= HMMA GEMM =======================
// C[M,N] = sum_k A[m,k]*B[n,k]; A [M,K] k-contig fp32, B [N,K] k-contig fp32.
// fp16 hi/lo 3-term emulation, fp32 accum. BM=BN=128, BK=32, 256 threads.
// EPI 0: store C fp32 (ldc).  EPI 1: tanh(acc + bias[m]) summed over n-tile
//        -> tpart[m * gridDim.x + blockIdx.x]; rows >= Mvalid skipped.
// smem stage (bytes): Ah@0 Al@10240 Bh@20480 Bl@30720, stage size 40960, x2.
#define STG 40960
#define GEMM_SMEM (2 * STG)

template<int EPI>
__global__ __launch_bounds__(256, 1)
void hgemm(const float* __restrict__ A, const float* __restrict__ B,
           float* __restrict__ C, long ldc, int K, int NT, int Mvalid,
           const float* __restrict__ bias, float* __restrict__ tpart)
{
    extern __shared__ char smem[];
    const uint32_t sbase = smem_u32(smem);
    const int tid = threadIdx.x, lane = tid & 31, wid = tid >> 5;
    const int warp_m = wid & 1;       // 2 x 64 rows
    const int warp_n = wid >> 1;      // 4 x 32 cols
    const int m0 = blockIdx.y * 128;
    const int n0 = blockIdx.x * 128;

    // ldmatrix per-lane selectors
    const int arow = lane & 15, acol = (lane >> 4) << 3;
    const int brow = (lane & 7) + ((lane & 16) >> 1);
    const int bcol = lane & 8;

    float acc[4][4][4];
#pragma unroll
    for (int i = 0; i < 4; i++)
#pragma unroll
        for (int j = 0; j < 4; j++)
#pragma unroll
            for (int k = 0; k < 4; k++) acc[i][j][k] = 0.f;

    float4 ra[4], rb[4];

    auto gload = [&](int k0) {
#pragma unroll
        for (int i = 0; i < 4; i++) {
            int idx = tid + i * 256;
            int r = idx >> 3, c4 = (idx & 7) << 2;
            if (m0 + r < Mvalid)
                ra[i] = *reinterpret_cast<const float4*>(A + (size_t)(m0 + r) * K + k0 + c4);
            else
                ra[i] = make_float4(0.f, 0.f, 0.f, 0.f);
            rb[i] = *reinterpret_cast<const float4*>(B + (size_t)(n0 + r) * K + k0 + c4);
        }
    };
    auto sstore = [&](int buf) {
        char* sb = smem + buf * STG;
#pragma unroll
        for (int i = 0; i < 4; i++) {
            int idx = tid + i * 256;
            int r = idx >> 3, c4 = (idx & 7) << 2;
            uint32_t off = (uint32_t)(r * 40 + c4) * 2;
            uint2 hi, lo;
            split4(ra[i], hi, lo);
            *reinterpret_cast<uint2*>(sb + off)         = hi;
            *reinterpret_cast<uint2*>(sb + 10240 + off) = lo;
            split4(rb[i], hi, lo);
            *reinterpret_cast<uint2*>(sb + 20480 + off) = hi;
            *reinterpret_cast<uint2*>(sb + 30720 + off) = lo;
        }
    };

    gload(0);
    sstore(0);
    __syncthreads();

    int buf = 0;
    for (int t = 0; t < NT; t++) {
        if (t + 1 < NT) gload((t + 1) * 32);
        uint32_t sa = sbase + buf * STG;
#pragma unroll
        for (int ks = 0; ks < 2; ks++) {
            uint32_t ah[4][4], al[4][4];
#pragma unroll
            for (int mf = 0; mf < 4; mf++) {
                uint32_t addr = sa + (uint32_t)((warp_m * 64 + mf * 16 + arow) * 40 + ks * 16 + acol) * 2;
                ldsm_x4(ah[mf][0], ah[mf][1], ah[mf][2], ah[mf][3], addr);
                ldsm_x4(al[mf][0], al[mf][1], al[mf][2], al[mf][3], addr + 10240);
            }
            uint32_t bh[2][4], bl[2][4];
#pragma unroll
            for (int nf2 = 0; nf2 < 2; nf2++) {
                uint32_t addr = sa + 20480 + (uint32_t)((warp_n * 32 + nf2 * 16 + brow) * 40 + ks * 16 + bcol) * 2;
                ldsm_x4(bh[nf2][0], bh[nf2][1], bh[nf2][2], bh[nf2][3], addr);
                ldsm_x4(bl[nf2][0], bl[nf2][1], bl[nf2][2], bl[nf2][3], addr + 10240);
            }
#pragma unroll
            for (int mf = 0; mf < 4; mf++)
#pragma unroll
                for (int nf = 0; nf < 4; nf++) {
                    int nf2 = nf >> 1, o = (nf & 1) * 2;
                    mma16816(acc[mf][nf], ah[mf], bh[nf2][o], bh[nf2][o + 1]);
                    mma16816(acc[mf][nf], ah[mf], bl[nf2][o], bl[nf2][o + 1]);
                    mma16816(acc[mf][nf], al[mf], bh[nf2][o], bh[nf2][o + 1]);
                }
        }
        if (t + 1 < NT) {
            buf ^= 1;
            sstore(buf);
            __syncthreads();
        }
    }

    const int gr = lane >> 2, q = lane & 3;
    if (EPI == 0) {
#pragma unroll
        for (int mf = 0; mf < 4; mf++)
#pragma unroll
            for (int nf = 0; nf < 4; nf++) {
                int row = m0 + warp_m * 64 + mf * 16 + gr;
                int col = n0 + warp_n * 32 + nf * 8 + q * 2;
                float2 v0 = make_float2(acc[mf][nf][0], acc[mf][nf][1]);
                float2 v1 = make_float2(acc[mf][nf][2], acc[mf][nf][3]);
                *reinterpret_cast<float2*>(C + (size_t)row * ldc + col)       = v0;
                *reinterpret_cast<float2*>(C + (size_t)(row + 8) * ldc + col) = v1;
            }
    } else {
        float rs[8];
#pragma unroll
        for (int k = 0; k < 8; k++) rs[k] = 0.f;
#pragma unroll
        for (int mf = 0; mf < 4; mf++) {
            int row = m0 + warp_m * 64 + mf * 16 + gr;
            float bj0 = (row < Mvalid)     ? bias[row]     : 0.f;
            float bj1 = (row + 8 < Mvalid) ? bias[row + 8] : 0.f;
#pragma unroll
            for (int nf = 0; nf < 4; nf++) {
                rs[mf * 2]     += tanhf(acc[mf][nf][0] + bj0) + tanhf(acc[mf][nf][1] + bj0);
                rs[mf * 2 + 1] += tanhf(acc[mf][nf][2] + bj1) + tanhf(acc[mf][nf][3] + bj1);
            }
        }
#pragma unroll
        for (int o = 1; o < 4; o <<= 1)
#pragma unroll
            for (int k = 0; k < 8; k++) rs[k] += __shfl_xor_sync(0xffffffffu, rs[k], o);
        __syncthreads();
        float* red = reinterpret_cast<float*>(smem);   // [128][4]
        if (q == 0) {
#pragma unroll
            for (int mf = 0; mf < 4; mf++) {
                int lr = warp_m * 64 + mf * 16 + gr;
                red[lr * 4 + warp_n]       = rs[mf * 2];
                red[(lr + 8) * 4 + warp_n] = rs[mf * 2 + 1];
            }
        }
        __syncthreads();
        if (tid < 128) {
            float s = red[tid * 4] + red[tid * 4 + 1] + red[tid * 4 + 2] + red[tid * 4 + 3];
            int f = m0 + tid;
            if (f < Mvalid) tpart[(size_t)f * gridDim.x + blockIdx.x] = s;
        }
    }
}

// ======================= transpose [R,C] -> [C,R] =======================
__global__ void transpose_kernel(const float* __restrict__ src, float* __restrict__ dst,
                                 int R, int C)
{
    __shared__ float t[32][33];
    int tx = threadIdx.x & 31, ty = threadIdx.x >> 5;
    int x = blockIdx.x * 32 + tx;
    int yb = blockIdx.y * 32;
#pragma unroll
    for (int r = 0; r < 4; r++) t[ty + r * 8][tx] = src[(size_t)(yb + ty + r * 8) * C + x];
    __syncthreads();
    int xo = yb + tx;
#pragma unroll
    for (int r = 0; r < 4; r++)
        dst[(size_t)(blockIdx.x * 32 + ty + r * 8) * R + xo] = t[tx][ty + r * 8];
}

// ======================= softmax statistics =======================
__global__ void row_stats_kernel()
{
    int row = blockIdx.x;
    const float* r = g_raw + (size_t)row * N2V;
    int tid = threadIdx.x;
    float m = -1e30f, s = 0.f;
#pragma unroll 4
    for (int j = tid; j < N2V; j += 256) {
        float v = r[j];
        float mn = fmaxf(m, v);
        s = s * __expf(m - mn) + __expf(v - mn);
        m = mn;
    }
#pragma unroll
    for (int o = 16; o; o >>= 1) {
        float mo = __shfl_xor_sync(0xffffffffu, m, o);
        float so = __shfl_xor_sync(0xffffffffu, s, o);
        float mn = fmaxf(m, mo);
        s = s * __expf(m - mn) + so * __expf(mo - mn);
        m = mn;
    }
    __shared__ float sm[8], ss[8];
    if ((tid & 31) == 0) { sm[tid >> 5] = m; ss[tid >> 5] = s; }
    __syncthreads();
    if (tid == 0) {
        float M = sm[0], S = ss[0];
        for (int w = 1; w < 8; w++) {
            float mn = fmaxf(M, sm[w]);
            S = S * __expf(M - mn) + ss[w] * __expf(sm[w] - mn);
            M = mn;
        }
        g_rmax[row] = M;
        g_rinv[row] = 1.0f / S;
    }
}

__global__ void col_stats_kernel()
{
    int lane = threadIdx.x & 31;
    int c = blockIdx.x * 32 + lane;
    int stripe = threadIdx.x >> 5;
    float m = -1e30f, s = 0.f;
#pragma unroll 4
    for (int r = stripe; r < N1V; r += 8) {
        float v = g_raw[(size_t)r * N2V + c];
        float mn = fmaxf(m, v);
        s = s * __expf(m - mn) + __expf(v - mn);
        m = mn;
    }
    __shared__ float sm[8][33], ss[8][33];
    sm[stripe][lane] = m;
    ss[stripe][lane] = s;
    __syncthreads();
    if (threadIdx.x < 32) {
        float M = sm[0][threadIdx.x], S = ss[0][threadIdx.x];
#pragma unroll
        for (int w = 1; w < 8; w++) {
            float mn = fmaxf(M, sm[w][threadIdx.x]);
            S = S * __expf(M - mn) + ss[w][threadIdx.x] * __expf(sm[w][threadIdx.x] - mn);
            M = mn;
        }
        int cc = blockIdx.x * 32 + threadIdx.x;
        g_cmax[cc] = M;
        g_cinv[cc] = 1.0f / S;
    }
}

// alpha2 in place; alpha1 transposed to g_a1t[j,i]
__global__ void alpha_kernel()
{
    __shared__ float t[32][33];
    int tx = threadIdx.x & 31, ty = threadIdx.x >> 5;
    int i0 = blockIdx.y * 32, j0 = blockIdx.x * 32;
    int j = j0 + tx;
    float cm = g_cmax[j], ci = g_cinv[j];
#pragma unroll
    for (int r = 0; r < 4; r++) {
        int i = i0 + ty + r * 8;
        size_t off = (size_t)i * N2V + j;
        float v = g_raw[off];
        g_raw[off] = __expf(v - g_rmax[i]) * g_rinv[i];
        t[ty + r * 8][tx] = __expf(v - cm) * ci;
    }
    __syncthreads();
    int xo = i0 + tx;
#pragma unroll
    for (int r = 0; r < 4; r++) {
        int jr = j0 + ty + r * 8;
        g_a1t[(size_t)jr * N1V + xo] = t[tx][ty + r * 8];
    }
}

// ======================= column sums of attended matrices =======================
__global__ void col_sum_kernel(const float* __restrict__ a, float* __restrict__ part)
{
    int lane = threadIdx.x & 31;
    int c = blockIdx.x * 32 + lane;
    int stripe = threadIdx.x >> 5;
    int r0 = blockIdx.y * (N1V / 8);
    float s = 0.f;
#pragma unroll 4
    for (int r = 0; r < 1024; r += 8)
        s += a[(size_t)(r0 + r + stripe) * DD + c];
    __shared__ float sh[8][33];
    sh[stripe][lane] = s;
    __syncthreads();
    if (threadIdx.x < 32) {
        float tsum = 0.f;
#pragma unroll
        for (int w = 0; w < 8; w++) tsum += sh[w][threadIdx.x];
        part[blockIdx.y * DD + blockIdx.x * 32 + threadIdx.x] = tsum;
    }
}

__global__ void sumv_kernel()
{
    int i = blockIdx.x * 256 + threadIdx.x;
    if (i < DD) {
        float s = 0.f;
#pragma unroll
        for (int w = 0; w < 8; w++) s += g_spart1[w * DD + i];
        g_sumv1[i] = s;
    } else if (i < 2 * DD) {
        int c = i - DD;
        float s = 0.f;
#pragma unroll
        for (int w = 0; w < 8; w++) s += g_spart2[w * DD + c];
        g_sumv2[c] = s;
    }
}

// ======================= finalize =======================
__global__ void finalize_kernel(const float* __restrict__ Wf1, const float* __restrict__ bf1,
                                const float* __restrict__ Wf2, const float* __restrict__ bf2,
                                float* __restrict__ out)
{
    int g = blockIdx.x * 8 + (threadIdx.x >> 5);
    int lane = threadIdx.x & 31;
    const float inv = 1.0f / 8192.0f;
    if (g < FF) {
        const float* w = Wf1 + (size_t)g * DD;
        float d = 0.f;
        for (int l = lane; l < DD; l += 32) d += w[l] * g_sumv2[l];
#pragma unroll
        for (int o = 16; o; o >>= 1) d += __shfl_xor_sync(0xffffffffu, d, o);
        if (lane == 0) {
            float filt = 1.0f / (1.0f + __expf(-(d * inv + bf1[g])));
            float t = 0.f;
#pragma unroll
            for (int b = 0; b < 64; b++) t += g_tpart1[g * 64 + b];
            out[g] = t * inv * filt;
        }
    } else if (g < 2 * FF) {
        int f = g - FF;
        const float* w = Wf2 + (size_t)f * DD;
        float d = 0.f;
        for (int l = lane; l < DD; l += 32) d += w[l] * g_sumv1[l];
#pragma unroll
        for (int o = 16; o; o >>= 1) d += __shfl_xor_sync(0xffffffffu, d, o);
        if (lane == 0) {
            float filt = 1.0f / (1.0f + __expf(-(d * inv + bf2[f])));
            float t = 0.f;
#pragma unroll
            for (int b = 0; b < 64; b++) t += g_tpart2[f * 64 + b];
            out[FF + f] = t * inv * filt;
        }
    }
}

// ======================= launch =======================
extern "C" void kernel_launch(void* const* d_in, const int* in_sizes, int n_in,
                              void* d_out, int out_size)
{
    const float* m1  = (const float*)d_in[0];
    const float* m2  = (const float*)d_in[1];
    const float* Wf1 = (const float*)d_in[2];
    const float* bf1 = (const float*)d_in[3];
    const float* Wf2 = (const float*)d_in[4];
    const float* bf2 = (const float*)d_in[5];
    const float* W1  = (const float*)d_in[6];
    const float* b1  = (const float*)d_in[7];
    const float* W2  = (const float*)d_in[8];
    const float* b2  = (const float*)d_in[9];
    float* out = (float*)d_out;

    float *raw, *a1t, *m1t, *m2t, *att1, *att2, *spart1, *spart2, *tpart1, *tpart2;
    cudaGetSymbolAddress((void**)&raw,    g_raw);
    cudaGetSymbolAddress((void**)&a1t,    g_a1t);
    cudaGetSymbolAddress((void**)&m1t,    g_m1t);
    cudaGetSymbolAddress((void**)&m2t,    g_m2t);
    cudaGetSymbolAddress((void**)&att1,   g_att1);
    cudaGetSymbolAddress((void**)&att2,   g_att2);
    cudaGetSymbolAddress((void**)&spart1, g_spart1);
    cudaGetSymbolAddress((void**)&spart2, g_spart2);
    cudaGetSymbolAddress((void**)&tpart1, g_tpart1);
    cudaGetSymbolAddress((void**)&tpart2, g_tpart2);

    cudaFuncSetAttribute(hgemm<0>, cudaFuncAttributeMaxDynamicSharedMemorySize, GEMM_SMEM);
    cudaFuncSetAttribute(hgemm<1>, cudaFuncAttributeMaxDynamicSharedMemorySize, GEMM_SMEM);

    // 0) input transposes (K-contiguous B operands for the alpha-GEMMs)
    transpose_kernel<<<dim3(DD / 32, N1V / 32), 256>>>(m1, m1t, N1V, DD);
    transpose_kernel<<<dim3(DD / 32, N2V / 32), 256>>>(m2, m2t, N2V, DD);

    // 1) raw = m1 @ m2^T  [8192 x 8192], K=1024
    hgemm<0><<<dim3(N2V / 128, N1V / 128), 256, GEMM_SMEM>>>(
        m1, m2, raw, N2V, DD, DD / 32, N1V, nullptr, nullptr);

    // 2) softmax stats + materialize alpha2 (in place) and alpha1^T
    row_stats_kernel<<<N1V, 256>>>();
    col_stats_kernel<<<N2V / 32, 256>>>();
    alpha_kernel<<<dim3(N2V / 32, N1V / 32), 256>>>();

    // 3) attended_m2 = alpha2 @ m2  [8192 x 1024], K=8192
    hgemm<0><<<dim3(DD / 128, N1V / 128), 256, GEMM_SMEM>>>(
        raw, m2t, att2, DD, N2V, N2V / 32, N1V, nullptr, nullptr);

    // 4) attended_m1 = alpha1 @ m1  [8192 x 1024], K=8192
    hgemm<0><<<dim3(DD / 128, N2V / 128), 256, GEMM_SMEM>>>(
        a1t, m1t, att1, DD, N1V, N1V / 32, N2V, nullptr, nullptr);

    // 5) column sums of attended matrices (filter means)
    col_sum_kernel<<<dim3(DD / 32, 8), 256>>>(att1, spart1);
    col_sum_kernel<<<dim3(DD / 32, 8), 256>>>(att2, spart2);
    sumv_kernel<<<8, 256>>>();

    // 6) transformed sums: [F x N] = W @ att^T with fused tanh+rowsum epilogue
    hgemm<1><<<dim3(N2V / 128, 7), 256, GEMM_SMEM>>>(
        W1, att1, nullptr, 0, DD, DD / 32, FF, b1, tpart1);
    hgemm<1><<<dim3(N1V / 128, 7), 256, GEMM_SMEM>>>(
        W2, att2, nullptr, 0, DD, DD / 32, FF, b2, tpart2);

    // 7) filters + outputs
    finalize_kernel<<<200, 256>>>(Wf1, bf1, Wf2, bf2, out);
}

// round 5
// speedup vs baseline: 2.9808x; 1.2191x over previous
#include <cuda_runtime.h>
#include <cuda_fp16.h>
#include <math.h>
#include <stdint.h>
#include <stddef.h>

#define N1V 8192
#define N2V 8192
#define DD  1024
#define FF  800
#define FPAD 896

// ======================= scratch (device globals) =======================
__device__ float  g_raw [(size_t)N1V * N2V];    // raw logits (fp32, kept)
__device__ __half g_a2h [(size_t)N1V * N2V];    // alpha2 fp16 (hi only)
__device__ __half g_a1th[(size_t)N2V * N1V];    // alpha1^T fp16 (hi only)
__device__ __half g_m1h[(size_t)N1V * DD], g_m1l[(size_t)N1V * DD];
__device__ __half g_m2h[(size_t)N2V * DD], g_m2l[(size_t)N2V * DD];
__device__ __half g_m1th[(size_t)DD * N1V], g_m1tl[(size_t)DD * N1V];
__device__ __half g_m2th[(size_t)DD * N2V], g_m2tl[(size_t)DD * N2V];
__device__ __half g_att1h[(size_t)N2V * DD], g_att1l[(size_t)N2V * DD];
__device__ __half g_att2h[(size_t)N1V * DD], g_att2l[(size_t)N1V * DD];
__device__ __half g_w1h[FPAD * DD], g_w1l[FPAD * DD];
__device__ __half g_w2h[FPAD * DD], g_w2l[FPAD * DD];
__device__ float g_rmax[N1V], g_rinv[N1V];
__device__ float g_cmax[N2V], g_cinv[N2V];
__device__ float g_cpart1[64 * DD], g_cpart2[64 * DD];
__device__ float g_sumv1[DD], g_sumv2[DD];
__device__ float g_tpart1[FPAD * 64], g_tpart2[FPAD * 64];

// ======================= asm helpers =======================
static __device__ __forceinline__ uint32_t smem_u32(const void* p) {
    uint32_t a;
    asm("{ .reg .u64 t; cvta.to.shared.u64 t, %1; cvt.u32.u64 %0, t; }" : "=r"(a) : "l"(p));
    return a;
}
static __device__ __forceinline__ uint64_t gaddr(const void* p) {
    uint64_t a;
    asm("cvta.to.global.u64 %0, %1;" : "=l"(a) : "l"(p));
    return a;
}
static __device__ __forceinline__ void cpa16(uint32_t dst, uint64_t src) {
    asm volatile("cp.async.cg.shared.global [%0], [%1], 16;" :: "r"(dst), "l"(src));
}
static __device__ __forceinline__ void ldsm_x4(uint32_t& r0, uint32_t& r1, uint32_t& r2, uint32_t& r3, uint32_t addr) {
    asm volatile("ldmatrix.sync.aligned.m8n8.x4.shared.b16 {%0,%1,%2,%3}, [%4];"
                 : "=r"(r0), "=r"(r1), "=r"(r2), "=r"(r3) : "r"(addr));
}
static __device__ __forceinline__ void mma16816(float* d, const uint32_t* a, uint32_t b0, uint32_t b1) {
    asm volatile("mma.sync.aligned.m16n8k16.row.col.f32.f16.f16.f32 "
                 "{%0,%1,%2,%3}, {%4,%5,%6,%7}, {%8,%9}, {%0,%1,%2,%3};"
                 : "+f"(d[0]), "+f"(d[1]), "+f"(d[2]), "+f"(d[3])
                 : "r"(a[0]), "r"(a[1]), "r"(a[2]), "r"(a[3]), "r"(b0), "r"(b1));
}

// ======================= HMMA GEMM (pre-split fp16 hi/lo operands) =======================
// C[M,N] = sum_k A[m,k]*B[n,k]; operands fp16 k-contig, pre-split.
// TERMS=3: Ah*Bh + Ah*Bl + Al*Bh.  TERMS=2: Ah*Bh + Ah*Bl (A hi only).
// BM=BN=128, BK=32, 256 threads, 8 warps of 64x32, cp.async double-buffered.
// EPI 0: store C fp32 (width ldw).
// EPI 1: write OutH/OutL fp16 (width ldw) + per-block-row column sums -> cpart[by*DD + col].
// EPI 2: tanh(acc + bias[m]) row-summed over n tile -> tpart[m*gridDim.x + bx] (m < Mvalid).
template<int TERMS, int EPI>
__global__ void __launch_bounds__(256, (TERMS == 2) ? 2 : 1)
hgemm(const __half* __restrict__ Ah, const __half* __restrict__ Al,
      const __half* __restrict__ Bh, const __half* __restrict__ Bl,
      float* __restrict__ C, __half* __restrict__ OutH, __half* __restrict__ OutL,
      float* __restrict__ cpart, long ldw, int K, int NT, int Mvalid,
      const float* __restrict__ bias, float* __restrict__ tpart)
{
    extern __shared__ char smem[];
    const uint32_t sbase = smem_u32(smem);
    const int STGSZ = (TERMS == 3) ? 40960 : 30720;
    const int OBH   = (TERMS == 3) ? 20480 : 10240;
    const int tid = threadIdx.x, lane = tid & 31, wid = tid >> 5;
    const int warp_m = wid & 1;       // 2 x 64 rows
    const int warp_n = wid >> 1;      // 4 x 32 cols
    const int m0 = blockIdx.y * 128;
    const int n0 = blockIdx.x * 128;

    const int arow = lane & 15, acol = (lane >> 4) << 3;
    const int brow = (lane & 7) + ((lane & 16) >> 1);
    const int bcol = lane & 8;

    const uint64_t gAh = gaddr(Ah);
    const uint64_t gAl = (TERMS == 3) ? gaddr(Al) : 0ull;
    const uint64_t gBh = gaddr(Bh);
    const uint64_t gBl = gaddr(Bl);

    float acc[4][4][4];
#pragma unroll
    for (int i = 0; i < 4; i++)
#pragma unroll
        for (int j = 0; j < 4; j++)
#pragma unroll
            for (int k = 0; k < 4; k++) acc[i][j][k] = 0.f;

    auto load_stage = [&](int kt, int bufi) {
        const int k0 = kt * 32;
        uint32_t sb = sbase + bufi * STGSZ;
#pragma unroll
        for (int i = 0; i < 2; i++) {
            int idx = tid + i * 256;
            int r = idx >> 2, c = (idx & 3) << 3;
            uint32_t doff = (uint32_t)(r * 40 + c) * 2;
            uint64_t aoff = ((uint64_t)(m0 + r) * K + k0 + c) * 2;
            uint64_t boff = ((uint64_t)(n0 + r) * K + k0 + c) * 2;
            cpa16(sb + doff, gAh + aoff);
            if (TERMS == 3) cpa16(sb + 10240 + doff, gAl + aoff);
            cpa16(sb + OBH + doff, gBh + boff);
            cpa16(sb + OBH + 10240 + doff, gBl + boff);
        }
        asm volatile("cp.async.commit_group;" ::: "memory");
    };

    load_stage(0, 0);
    int buf = 0;
    for (int t = 0; t < NT; t++) {
        if (t + 1 < NT) {
            load_stage(t + 1, buf ^ 1);
            asm volatile("cp.async.wait_group 1;" ::: "memory");
        } else {
            asm volatile("cp.async.wait_group 0;" ::: "memory");
        }
        __syncthreads();
        uint32_t sa = sbase + buf * STGSZ;
#pragma unroll
        for (int ks = 0; ks < 2; ks++) {
            uint32_t ah[4][4], al[4][4];
#pragma unroll
            for (int mf = 0; mf < 4; mf++) {
                uint32_t addr = sa + (uint32_t)((warp_m * 64 + mf * 16 + arow) * 40 + ks * 16 + acol) * 2;
                ldsm_x4(ah[mf][0], ah[mf][1], ah[mf][2], ah[mf][3], addr);
                if (TERMS == 3)
                    ldsm_x4(al[mf][0], al[mf][1], al[mf][2], al[mf][3], addr + 10240);
            }
            uint32_t bh[2][4], bl[2][4];
#pragma unroll
            for (int nf2 = 0; nf2 < 2; nf2++) {
                uint32_t addr = sa + OBH + (uint32_t)((warp_n * 32 + nf2 * 16 + brow) * 40 + ks * 16 + bcol) * 2;
                ldsm_x4(bh[nf2][0], bh[nf2][1], bh[nf2][2], bh[nf2][3], addr);
                ldsm_x4(bl[nf2][0], bl[nf2][1], bl[nf2][2], bl[nf2][3], addr + 10240);
            }
#pragma unroll
            for (int mf = 0; mf < 4; mf++)
#pragma unroll
                for (int nf = 0; nf < 4; nf++) {
                    int nf2 = nf >> 1, o = (nf & 1) * 2;
                    mma16816(acc[mf][nf], ah[mf], bh[nf2][o], bh[nf2][o + 1]);
                    mma16816(acc[mf][nf], ah[mf], bl[nf2][o], bl[nf2][o + 1]);
                    if (TERMS == 3)
                        mma16816(acc[mf][nf], al[mf], bh[nf2][o], bh[nf2][o + 1]);
                }
        }
        __syncthreads();
        buf ^= 1;
    }

    const int gr = lane >> 2, q = lane & 3;
    if (EPI == 0) {
#pragma unroll
        for (int mf = 0; mf < 4; mf++)
#pragma unroll
            for (int nf = 0; nf < 4; nf++) {
                int row = m0 + warp_m * 64 + mf * 16 + gr;
                int col = n0 + warp_n * 32 + nf * 8 + q * 2;
                *reinterpret_cast<float2*>(C + (size_t)row * ldw + col) =
                    make_float2(acc[mf][nf][0], acc[mf][nf][1]);
                *reinterpret_cast<float2*>(C + (size_t)(row + 8) * ldw + col) =
                    make_float2(acc[mf][nf][2], acc[mf][nf][3]);
            }
    } else if (EPI == 1) {
        float cs[4][2];
#pragma unroll
        for (int nf = 0; nf < 4; nf++) { cs[nf][0] = 0.f; cs[nf][1] = 0.f; }
#pragma unroll
        for (int mf = 0; mf < 4; mf++)
#pragma unroll
            for (int nf = 0; nf < 4; nf++) {
                int row = m0 + warp_m * 64 + mf * 16 + gr;
                int col = n0 + warp_n * 32 + nf * 8 + q * 2;
                float v0 = acc[mf][nf][0], v1 = acc[mf][nf][1];
                float v2 = acc[mf][nf][2], v3 = acc[mf][nf][3];
                __half2 h0 = __floats2half2_rn(v0, v1);
                __half2 l0 = __floats2half2_rn(v0 - __low2float(h0), v1 - __high2float(h0));
                __half2 h1 = __floats2half2_rn(v2, v3);
                __half2 l1 = __floats2half2_rn(v2 - __low2float(h1), v3 - __high2float(h1));
                *reinterpret_cast<__half2*>(OutH + (size_t)row * ldw + col)       = h0;
                *reinterpret_cast<__half2*>(OutL + (size_t)row * ldw + col)       = l0;
                *reinterpret_cast<__half2*>(OutH + (size_t)(row + 8) * ldw + col) = h1;
                *reinterpret_cast<__half2*>(OutL + (size_t)(row + 8) * ldw + col) = l1;
                cs[nf][0] += v0 + v2;
                cs[nf][1] += v1 + v3;
            }
#pragma unroll
        for (int o = 4; o < 32; o <<= 1)
#pragma unroll
            for (int nf = 0; nf < 4; nf++) {
                cs[nf][0] += __shfl_xor_sync(0xffffffffu, cs[nf][0], o);
                cs[nf][1] += __shfl_xor_sync(0xffffffffu, cs[nf][1], o);
            }
        __syncthreads();
        float* red = reinterpret_cast<float*>(smem);   // [2][4][32]
        if (lane < 4) {
#pragma unroll
            for (int nf = 0; nf < 4; nf++) {
                red[warp_m * 128 + warp_n * 32 + nf * 8 + lane * 2]     = cs[nf][0];
                red[warp_m * 128 + warp_n * 32 + nf * 8 + lane * 2 + 1] = cs[nf][1];
            }
        }
        __syncthreads();
        if (tid < 128)
            cpart[(size_t)blockIdx.y * DD + n0 + tid] = red[tid] + red[128 + tid];
    } else {
        float rs[8];
#pragma unroll
        for (int k = 0; k < 8; k++) rs[k] = 0.f;
#pragma unroll
        for (int mf = 0; mf < 4; mf++) {
            int row = m0 + warp_m * 64 + mf * 16 + gr;
            float bj0 = (row < Mvalid)     ? bias[row]     : 0.f;
            float bj1 = (row + 8 < Mvalid) ? bias[row + 8] : 0.f;
#pragma unroll
            for (int nf = 0; nf < 4; nf++) {
                rs[mf * 2]     += tanhf(acc[mf][nf][0] + bj0) + tanhf(acc[mf][nf][1] + bj0);
                rs[mf * 2 + 1] += tanhf(acc[mf][nf][2] + bj1) + tanhf(acc[mf][nf][3] + bj1);
            }
        }
#pragma unroll
        for (int o = 1; o < 4; o <<= 1)
#pragma unroll
            for (int k = 0; k < 8; k++) rs[k] += __shfl_xor_sync(0xffffffffu, rs[k], o);
        __syncthreads();
        float* red = reinterpret_cast<float*>(smem);   // [128][4]
        if (q == 0) {
#pragma unroll
            for (int mf = 0; mf < 4; mf++) {
                int lr = warp_m * 64 + mf * 16 + gr;
                red[lr * 4 + warp_n]       = rs[mf * 2];
                red[(lr + 8) * 4 + warp_n] = rs[mf * 2 + 1];
            }
        }
        __syncthreads();
        if (tid < 128) {
            float s = red[tid * 4] + red[tid * 4 + 1] + red[tid * 4 + 2] + red[tid * 4 + 3];
            int f = m0 + tid;
            if (f < Mvalid) tpart[(size_t)f * gridDim.x + blockIdx.x] = s;
        }
    }
}

// ======================= prep: transpose + hi/lo split =======================
// src fp32 [R,C] -> dh/dl [R,C] fp16 and dth/dtl [C,R] fp16
__global__ void tsplit_kernel(const float* __restrict__ src,
                              __half* __restrict__ dh, __half* __restrict__ dl,
                              __half* __restrict__ dth, __half* __restrict__ dtl,
                              int R, int C)
{
    __shared__ float t[32][33];
    int tx = threadIdx.x & 31, ty = threadIdx.x >> 5;
    int x = blockIdx.x * 32 + tx;
    int yb = blockIdx.y * 32;
#pragma unroll
    for (int r = 0; r < 4; r++) {
        int row = yb + ty + r * 8;
        float v = src[(size_t)row * C + x];
        __half h = __float2half_rn(v);
        dh[(size_t)row * C + x] = h;
        dl[(size_t)row * C + x] = __float2half_rn(v - __half2float(h));
        t[ty + r * 8][tx] = v;
    }
    __syncthreads();
    int r_ = yb + tx;
#pragma unroll
    for (int r = 0; r < 4; r++) {
        int c_ = blockIdx.x * 32 + ty + r * 8;
        float v = t[tx][ty + r * 8];
        __half h = __float2half_rn(v);
        dth[(size_t)c_ * R + r_] = h;
        dtl[(size_t)c_ * R + r_] = __float2half_rn(v - __half2float(h));
    }
}

// W [R,C] fp32 -> wh/wl [Rpad,C] fp16, zero-padded rows
__global__ void wsplit_kernel(const float* __restrict__ src,
                              __half* __restrict__ dh, __half* __restrict__ dl,
                              int R, int C, int Rpad)
{
    int idx = blockIdx.x * 256 + threadIdx.x;
    if (idx >= Rpad * C) return;
    int r = idx / C;
    float v = (r < R) ? src[idx] : 0.f;
    __half h = __float2half_rn(v);
    dh[idx] = h;
    dl[idx] = __float2half_rn(v - __half2float(h));
}

// ======================= softmax statistics =======================
__global__ void row_stats_kernel()
{
    int row = blockIdx.x;
    const float* r = g_raw + (size_t)row * N2V;
    int tid = threadIdx.x;
    float m = -1e30f, s = 0.f;
#pragma unroll 4
    for (int j = tid; j < N2V; j += 256) {
        float v = r[j];
        float mn = fmaxf(m, v);
        s = s * __expf(m - mn) + __expf(v - mn);
        m = mn;
    }
#pragma unroll
    for (int o = 16; o; o >>= 1) {
        float mo = __shfl_xor_sync(0xffffffffu, m, o);
        float so = __shfl_xor_sync(0xffffffffu, s, o);
        float mn = fmaxf(m, mo);
        s = s * __expf(m - mn) + so * __expf(mo - mn);
        m = mn;
    }
    __shared__ float sm[8], ss[8];
    if ((tid & 31) == 0) { sm[tid >> 5] = m; ss[tid >> 5] = s; }
    __syncthreads();
    if (tid == 0) {
        float M = sm[0], S = ss[0];
        for (int w = 1; w < 8; w++) {
            float mn = fmaxf(M, sm[w]);
            S = S * __expf(M - mn) + ss[w] * __expf(sm[w] - mn);
            M = mn;
        }
        g_rmax[row] = M;
        g_rinv[row] = 1.0f / S;
    }
}

__global__ void col_stats_kernel()
{
    int lane = threadIdx.x & 31;
    int c = blockIdx.x * 32 + lane;
    int stripe = threadIdx.x >> 5;
    float m = -1e30f, s = 0.f;
#pragma unroll 4
    for (int r = stripe; r < N1V; r += 8) {
        float v = g_raw[(size_t)r * N2V + c];
        float mn = fmaxf(m, v);
        s = s * __expf(m - mn) + __expf(v - mn);
        m = mn;
    }
    __shared__ float sm[8][33], ss[8][33];
    sm[stripe][lane] = m;
    ss[stripe][lane] = s;
    __syncthreads();
    if (threadIdx.x < 32) {
        float M = sm[0][threadIdx.x], S = ss[0][threadIdx.x];
#pragma unroll
        for (int w = 1; w < 8; w++) {
            float mn = fmaxf(M, sm[w][threadIdx.x]);
            S = S * __expf(M - mn) + ss[w][threadIdx.x] * __expf(sm[w][threadIdx.x] - mn);
            M = mn;
        }
        int cc = blockIdx.x * 32 + threadIdx.x;
        g_cmax[cc] = M;
        g_cinv[cc] = 1.0f / S;
    }
}

// alpha2 -> g_a2h fp16; alpha1^T -> g_a1th fp16
__global__ void alpha_kernel()
{
    __shared__ float t[32][33];
    int tx = threadIdx.x & 31, ty = threadIdx.x >> 5;
    int i0 = blockIdx.y * 32, j0 = blockIdx.x * 32;
    int j = j0 + tx;
    float cm = g_cmax[j], ci = g_cinv[j];
#pragma unroll
    for (int r = 0; r < 4; r++) {
        int i = i0 + ty + r * 8;
        size_t off = (size_t)i * N2V + j;
        float v = g_raw[off];
        g_a2h[off] = __float2half_rn(__expf(v - g_rmax[i]) * g_rinv[i]);
        t[ty + r * 8][tx] = __expf(v - cm) * ci;
    }
    __syncthreads();
    int xo = i0 + tx;
#pragma unroll
    for (int r = 0; r < 4; r++) {
        int jr = j0 + ty + r * 8;
        g_a1th[(size_t)jr * N1V + xo] = __float2half_rn(t[tx][ty + r * 8]);
    }
}

// ======================= reduce column partials =======================
__global__ void sumv_kernel()
{
    int i = blockIdx.x * 256 + threadIdx.x;
    if (i < DD) {
        float s = 0.f;
        for (int w = 0; w < 64; w++) s += g_cpart1[w * DD + i];
        g_sumv1[i] = s;
    } else if (i < 2 * DD) {
        int c = i - DD;
        float s = 0.f;
        for (int w = 0; w < 64; w++) s += g_cpart2[w * DD + c];
        g_sumv2[c] = s;
    }
}

// ======================= finalize =======================
__global__ void finalize_kernel(const float* __restrict__ Wf1, const float* __restrict__ bf1,
                                const float* __restrict__ Wf2, const float* __restrict__ bf2,
                                float* __restrict__ out)
{
    int g = blockIdx.x * 8 + (threadIdx.x >> 5);
    int lane = threadIdx.x & 31;
    const float inv = 1.0f / 8192.0f;
    if (g < FF) {
        const float* w = Wf1 + (size_t)g * DD;
        float d = 0.f;
        for (int l = lane; l < DD; l += 32) d += w[l] * g_sumv2[l];
#pragma unroll
        for (int o = 16; o; o >>= 1) d += __shfl_xor_sync(0xffffffffu, d, o);
        if (lane == 0) {
            float filt = 1.0f / (1.0f + __expf(-(d * inv + bf1[g])));
            float t = 0.f;
#pragma unroll
            for (int b = 0; b < 64; b++) t += g_tpart1[g * 64 + b];
            out[g] = t * inv * filt;
        }
    } else if (g < 2 * FF) {
        int f = g - FF;
        const float* w = Wf2 + (size_t)f * DD;
        float d = 0.f;
        for (int l = lane; l < DD; l += 32) d += w[l] * g_sumv1[l];
#pragma unroll
        for (int o = 16; o; o >>= 1) d += __shfl_xor_sync(0xffffffffu, d, o);
        if (lane == 0) {
            float filt = 1.0f / (1.0f + __expf(-(d * inv + bf2[f])));
            float t = 0.f;
#pragma unroll
            for (int b = 0; b < 64; b++) t += g_tpart2[f * 64 + b];
            out[FF + f] = t * inv * filt;
        }
    }
}

// ======================= launch =======================
extern "C" void kernel_launch(void* const* d_in, const int* in_sizes, int n_in,
                              void* d_out, int out_size)
{
    const float* m1  = (const float*)d_in[0];
    const float* m2  = (const float*)d_in[1];
    const float* Wf1 = (const float*)d_in[2];
    const float* bf1 = (const float*)d_in[3];
    const float* Wf2 = (const float*)d_in[4];
    const float* bf2 = (const float*)d_in[5];
    const float* W1  = (const float*)d_in[6];
    const float* b1  = (const float*)d_in[7];
    const float* W2  = (const float*)d_in[8];
    const float* b2  = (const float*)d_in[9];
    float* out = (float*)d_out;

    float *raw, *cpart1, *cpart2, *tpart1, *tpart2;
    __half *a2h, *a1th, *m1h, *m1l, *m2h, *m2l, *m1th, *m1tl, *m2th, *m2tl;
    __half *att1h, *att1l, *att2h, *att2l, *w1h, *w1l, *w2h, *w2l;
    cudaGetSymbolAddress((void**)&raw,   g_raw);
    cudaGetSymbolAddress((void**)&a2h,   g_a2h);
    cudaGetSymbolAddress((void**)&a1th,  g_a1th);
    cudaGetSymbolAddress((void**)&m1h,   g_m1h);
    cudaGetSymbolAddress((void**)&m1l,   g_m1l);
    cudaGetSymbolAddress((void**)&m2h,   g_m2h);
    cudaGetSymbolAddress((void**)&m2l,   g_m2l);
    cudaGetSymbolAddress((void**)&m1th,  g_m1th);
    cudaGetSymbolAddress((void**)&m1tl,  g_m1tl);
    cudaGetSymbolAddress((void**)&m2th,  g_m2th);
    cudaGetSymbolAddress((void**)&m2tl,  g_m2tl);
    cudaGetSymbolAddress((void**)&att1h, g_att1h);
    cudaGetSymbolAddress((void**)&att1l, g_att1l);
    cudaGetSymbolAddress((void**)&att2h, g_att2h);
    cudaGetSymbolAddress((void**)&att2l, g_att2l);
    cudaGetSymbolAddress((void**)&w1h,   g_w1h);
    cudaGetSymbolAddress((void**)&w1l,   g_w1l);
    cudaGetSymbolAddress((void**)&w2h,   g_w2h);
    cudaGetSymbolAddress((void**)&w2l,   g_w2l);
    cudaGetSymbolAddress((void**)&cpart1, g_cpart1);
    cudaGetSymbolAddress((void**)&cpart2, g_cpart2);
    cudaGetSymbolAddress((void**)&tpart1, g_tpart1);
    cudaGetSymbolAddress((void**)&tpart2, g_tpart2);

    cudaFuncSetAttribute(hgemm<3, 0>, cudaFuncAttributeMaxDynamicSharedMemorySize, 81920);
    cudaFuncSetAttribute(hgemm<2, 1>, cudaFuncAttributeMaxDynamicSharedMemorySize, 61440);
    cudaFuncSetAttribute(hgemm<3, 2>, cudaFuncAttributeMaxDynamicSharedMemorySize, 81920);

    // 0) prep: split m1/m2 (plain + transposed), split W1/W2 (padded to 896 rows)
    tsplit_kernel<<<dim3(DD / 32, N1V / 32), 256>>>(m1, m1h, m1l, m1th, m1tl, N1V, DD);
    tsplit_kernel<<<dim3(DD / 32, N2V / 32), 256>>>(m2, m2h, m2l, m2th, m2tl, N2V, DD);
    wsplit_kernel<<<(FPAD * DD + 255) / 256, 256>>>(W1, w1h, w1l, FF, DD, FPAD);
    wsplit_kernel<<<(FPAD * DD + 255) / 256, 256>>>(W2, w2h, w2l, FF, DD, FPAD);

    // 1) raw = m1 @ m2^T  [8192 x 8192], K=1024, 3-term
    hgemm<3, 0><<<dim3(N2V / 128, N1V / 128), 256, 81920>>>(
        m1h, m1l, m2h, m2l, raw, nullptr, nullptr, nullptr, N2V, DD, DD / 32, N1V, nullptr, nullptr);

    // 2) softmax stats + alpha materialization (fp16)
    row_stats_kernel<<<N1V, 256>>>();
    col_stats_kernel<<<N2V / 32, 256>>>();
    alpha_kernel<<<dim3(N2V / 32, N1V / 32), 256>>>();

    // 3) attended_m2 = alpha2 @ m2  [8192 x 1024], K=8192, 2-term, fused colsum + hi/lo out
    hgemm<2, 1><<<dim3(DD / 128, N1V / 128), 256, 61440>>>(
        a2h, nullptr, m2th, m2tl, nullptr, att2h, att2l, cpart2, DD, N2V, N2V / 32, N1V, nullptr, nullptr);

    // 4) attended_m1 = alpha1 @ m1  [8192 x 1024], K=8192, 2-term
    hgemm<2, 1><<<dim3(DD / 128, N2V / 128), 256, 61440>>>(
        a1th, nullptr, m1th, m1tl, nullptr, att1h, att1l, cpart1, DD, N1V, N1V / 32, N2V, nullptr, nullptr);

    // 5) reduce column partials -> sum vectors
    sumv_kernel<<<8, 256>>>();

    // 6) transform: [F x N] = W @ att^T, 3-term, fused tanh+rowsum
    hgemm<3, 2><<<dim3(N2V / 128, FPAD / 128), 256, 81920>>>(
        w1h, w1l, att1h, att1l, nullptr, nullptr, nullptr, nullptr, 0, DD, DD / 32, FF, b1, tpart1);
    hgemm<3, 2><<<dim3(N1V / 128, FPAD / 128), 256, 81920>>>(
        w2h, w2l, att2h, att2l, nullptr, nullptr, nullptr, nullptr, 0, DD, DD / 32, FF, b2, tpart2);

    // 7) filters + outputs
    finalize_kernel<<<200, 256>>>(Wf1, bf1, Wf2, bf2, out);
}

// round 6
// speedup vs baseline: 3.2392x; 1.0867x over previous
#include <cuda_runtime.h>
#include <cuda_fp16.h>
#include <math.h>
#include <stdint.h>
#include <stddef.h>

#define N1V 8192
#define N2V 8192
#define DD  1024
#define FF  800
#define FPAD 896

// ======================= scratch (device globals) =======================
__device__ float  g_raw [(size_t)N1V * N2V];    // raw logits fp32
__device__ __half g_a2h [(size_t)N1V * N2V];    // alpha2 fp16
__device__ __half g_a1th[(size_t)N2V * N1V];    // alpha1^T fp16
__device__ __half g_m1h[(size_t)N1V * DD], g_m1l[(size_t)N1V * DD];
__device__ __half g_m2h[(size_t)N2V * DD], g_m2l[(size_t)N2V * DD];
__device__ __half g_m1th[(size_t)DD * N1V], g_m1tl[(size_t)DD * N1V];
__device__ __half g_m2th[(size_t)DD * N2V], g_m2tl[(size_t)DD * N2V];
__device__ __half g_att1h[(size_t)N2V * DD], g_att1l[(size_t)N2V * DD];
__device__ __half g_att2h[(size_t)N1V * DD], g_att2l[(size_t)N1V * DD];
__device__ __half g_w1h[FPAD * DD], g_w1l[FPAD * DD];
__device__ __half g_w2h[FPAD * DD], g_w2l[FPAD * DD];
__device__ float g_rmax[N1V], g_rinv[N1V];
__device__ float g_cmax[N2V], g_cinv[N2V];
__device__ float g_cpart1[64 * DD], g_cpart2[64 * DD];
__device__ float g_sumv1[DD], g_sumv2[DD];
__device__ float g_tpart1[FPAD * 32], g_tpart2[FPAD * 32];

// ======================= asm helpers =======================
static __device__ __forceinline__ uint32_t smem_u32(const void* p) {
    uint32_t a;
    asm("{ .reg .u64 t; cvta.to.shared.u64 t, %1; cvt.u32.u64 %0, t; }" : "=r"(a) : "l"(p));
    return a;
}
static __device__ __forceinline__ uint64_t gaddr(const void* p) {
    uint64_t a;
    asm("cvta.to.global.u64 %0, %1;" : "=l"(a) : "l"(p));
    return a;
}
static __device__ __forceinline__ void cpa16(uint32_t dst, uint64_t src) {
    asm volatile("cp.async.cg.shared.global [%0], [%1], 16;" :: "r"(dst), "l"(src));
}
static __device__ __forceinline__ void ldsm_x4(uint32_t& r0, uint32_t& r1, uint32_t& r2, uint32_t& r3, uint32_t addr) {
    asm volatile("ldmatrix.sync.aligned.m8n8.x4.shared.b16 {%0,%1,%2,%3}, [%4];"
                 : "=r"(r0), "=r"(r1), "=r"(r2), "=r"(r3) : "r"(addr));
}
static __device__ __forceinline__ void mma16816(float* d, const uint32_t* a, uint32_t b0, uint32_t b1) {
    asm volatile("mma.sync.aligned.m16n8k16.row.col.f32.f16.f16.f32 "
                 "{%0,%1,%2,%3}, {%4,%5,%6,%7}, {%8,%9}, {%0,%1,%2,%3};"
                 : "+f"(d[0]), "+f"(d[1]), "+f"(d[2]), "+f"(d[3])
                 : "r"(a[0]), "r"(a[1]), "r"(a[2]), "r"(a[3]), "r"(b0), "r"(b1));
}

// ======================= HMMA GEMM, 128x256 block, 64x64 warp tiles =======================
// C[M,N] = sum_k A[m,k]*B[n,k]; fp16 hi/lo pre-split operands, k-contig, K%32==0.
// TERMS=3: Ah*Bh + Ah*Bl + Al*Bh.  TERMS=2: Ah*Bh + Ah*Bl.
// 256 threads = 8 warps (2 m x 4 n), 3-stage cp.async pipeline.
// EPI 0: store C fp32 (pitch ldw).
// EPI 1: OutH/OutL fp16 (pitch ldw) + block-row column sums -> cpart[by*DD + n0+c].
// EPI 2: tanh(acc + bias[m]) row-summed over n-tile -> tpart[m*gridDim.x + bx], m < Mvalid.
template<int TERMS, int EPI>
__global__ void __launch_bounds__(256, 1)
hgemm(const __half* __restrict__ Ah, const __half* __restrict__ Al,
      const __half* __restrict__ Bh, const __half* __restrict__ Bl,
      float* __restrict__ C, __half* __restrict__ OutH, __half* __restrict__ OutL,
      float* __restrict__ cpart, long ldw, int K, int NT, int Mvalid,
      const float* __restrict__ bias, float* __restrict__ tpart)
{
    extern __shared__ char smem[];
    const uint32_t sbase = smem_u32(smem);
    const int STGSZ = (TERMS == 3) ? 61440 : 51200;   // A(10240 x terms-1... ) see offsets
    const int OB    = (TERMS == 3) ? 20480 : 10240;   // B-hi offset; B-lo at OB+20480
    const int tid = threadIdx.x, lane = tid & 31, wid = tid >> 5;
    const int warp_m = wid & 1;      // 2 x 64 rows
    const int warp_n = wid >> 1;     // 4 x 64 cols
    const int m0 = blockIdx.y * 128;
    const int n0 = blockIdx.x * 256;

    const int arow = lane & 15, acol = (lane >> 4) << 3;
    const int brow = (lane & 7) + ((lane & 16) >> 1);
    const int bcol = lane & 8;

    const uint64_t gAh = gaddr(Ah);
    const uint64_t gAl = (TERMS == 3) ? gaddr(Al) : 0ull;
    const uint64_t gBh = gaddr(Bh);
    const uint64_t gBl = gaddr(Bl);

    float acc[4][8][4];
#pragma unroll
    for (int i = 0; i < 4; i++)
#pragma unroll
        for (int j = 0; j < 8; j++)
#pragma unroll
            for (int k = 0; k < 4; k++) acc[i][j][k] = 0.f;

    auto load_stage = [&](int kt, int bufi) {
        const int k0 = kt * 32;
        uint32_t sb = sbase + bufi * STGSZ;
#pragma unroll
        for (int i = 0; i < 2; i++) {                 // A: 128 rows x 32k
            int idx = tid + i * 256;
            int r = idx >> 2, c = (idx & 3) << 3;
            uint32_t d = sb + (uint32_t)(r * 40 + c) * 2;
            uint64_t ao = ((uint64_t)(m0 + r) * K + k0 + c) * 2;
            cpa16(d, gAh + ao);
            if (TERMS == 3) cpa16(d + 10240, gAl + ao);
        }
#pragma unroll
        for (int i = 0; i < 4; i++) {                 // B: 256 rows x 32k
            int idx = tid + i * 256;
            int r = idx >> 2, c = (idx & 3) << 3;
            uint32_t d = sb + OB + (uint32_t)(r * 40 + c) * 2;
            uint64_t bo = ((uint64_t)(n0 + r) * K + k0 + c) * 2;
            cpa16(d, gBh + bo);
            cpa16(d + 20480, gBl + bo);
        }
        asm volatile("cp.async.commit_group;" ::: "memory");
    };

    load_stage(0, 0);
    load_stage(1, 1);
    for (int t = 0; t < NT; t++) {
        if (t + 2 < NT) {
            load_stage(t + 2, (t + 2) % 3);
            asm volatile("cp.async.wait_group 2;" ::: "memory");
        } else if (t + 1 < NT) {
            asm volatile("cp.async.wait_group 1;" ::: "memory");
        } else {
            asm volatile("cp.async.wait_group 0;" ::: "memory");
        }
        __syncthreads();
        uint32_t sa = sbase + (t % 3) * STGSZ;
#pragma unroll
        for (int ks = 0; ks < 2; ks++) {
            uint32_t ah[4][4], al[4][4];
#pragma unroll
            for (int mf = 0; mf < 4; mf++) {
                uint32_t addr = sa + (uint32_t)((warp_m * 64 + mf * 16 + arow) * 40 + ks * 16 + acol) * 2;
                ldsm_x4(ah[mf][0], ah[mf][1], ah[mf][2], ah[mf][3], addr);
                if (TERMS == 3)
                    ldsm_x4(al[mf][0], al[mf][1], al[mf][2], al[mf][3], addr + 10240);
            }
            uint32_t bh[4][4], bl[4][4];
#pragma unroll
            for (int nf2 = 0; nf2 < 4; nf2++) {
                uint32_t addr = sa + OB + (uint32_t)((warp_n * 64 + nf2 * 16 + brow) * 40 + ks * 16 + bcol) * 2;
                ldsm_x4(bh[nf2][0], bh[nf2][1], bh[nf2][2], bh[nf2][3], addr);
                ldsm_x4(bl[nf2][0], bl[nf2][1], bl[nf2][2], bl[nf2][3], addr + 20480);
            }
#pragma unroll
            for (int mf = 0; mf < 4; mf++)
#pragma unroll
                for (int nf = 0; nf < 8; nf++) {
                    int nf2 = nf >> 1, o = (nf & 1) * 2;
                    mma16816(acc[mf][nf], ah[mf], bh[nf2][o], bh[nf2][o + 1]);
                    mma16816(acc[mf][nf], ah[mf], bl[nf2][o], bl[nf2][o + 1]);
                    if (TERMS == 3)
                        mma16816(acc[mf][nf], al[mf], bh[nf2][o], bh[nf2][o + 1]);
                }
        }
        __syncthreads();
    }

    const int gr = lane >> 2, q = lane & 3;
    if (EPI == 0) {
#pragma unroll
        for (int mf = 0; mf < 4; mf++)
#pragma unroll
            for (int nf = 0; nf < 8; nf++) {
                int row = m0 + warp_m * 64 + mf * 16 + gr;
                int col = n0 + warp_n * 64 + nf * 8 + q * 2;
                *reinterpret_cast<float2*>(C + (size_t)row * ldw + col) =
                    make_float2(acc[mf][nf][0], acc[mf][nf][1]);
                *reinterpret_cast<float2*>(C + (size_t)(row + 8) * ldw + col) =
                    make_float2(acc[mf][nf][2], acc[mf][nf][3]);
            }
    } else if (EPI == 1) {
        float cs[8][2];
#pragma unroll
        for (int nf = 0; nf < 8; nf++) { cs[nf][0] = 0.f; cs[nf][1] = 0.f; }
#pragma unroll
        for (int mf = 0; mf < 4; mf++)
#pragma unroll
            for (int nf = 0; nf < 8; nf++) {
                int row = m0 + warp_m * 64 + mf * 16 + gr;
                int col = warp_n * 64 + nf * 8 + q * 2;   // ldw == DD, n0 added below
                float v0 = acc[mf][nf][0], v1 = acc[mf][nf][1];
                float v2 = acc[mf][nf][2], v3 = acc[mf][nf][3];
                __half2 h0 = __floats2half2_rn(v0, v1);
                __half2 l0 = __floats2half2_rn(v0 - __low2float(h0), v1 - __high2float(h0));
                __half2 h1 = __floats2half2_rn(v2, v3);
                __half2 l1 = __floats2half2_rn(v2 - __low2float(h1), v3 - __high2float(h1));
                size_t o0 = (size_t)row * ldw + n0 + col;
                size_t o1 = (size_t)(row + 8) * ldw + n0 + col;
                *reinterpret_cast<__half2*>(OutH + o0) = h0;
                *reinterpret_cast<__half2*>(OutL + o0) = l0;
                *reinterpret_cast<__half2*>(OutH + o1) = h1;
                *reinterpret_cast<__half2*>(OutL + o1) = l1;
                cs[nf][0] += v0 + v2;
                cs[nf][1] += v1 + v3;
            }
#pragma unroll
        for (int o = 4; o < 32; o <<= 1)
#pragma unroll
            for (int nf = 0; nf < 8; nf++) {
                cs[nf][0] += __shfl_xor_sync(0xffffffffu, cs[nf][0], o);
                cs[nf][1] += __shfl_xor_sync(0xffffffffu, cs[nf][1], o);
            }
        __syncthreads();
        float* red = reinterpret_cast<float*>(smem);   // [2][256]
        if (lane < 4) {
#pragma unroll
            for (int nf = 0; nf < 8; nf++) {
                red[warp_m * 256 + warp_n * 64 + nf * 8 + lane * 2]     = cs[nf][0];
                red[warp_m * 256 + warp_n * 64 + nf * 8 + lane * 2 + 1] = cs[nf][1];
            }
        }
        __syncthreads();
        cpart[(size_t)blockIdx.y * DD + n0 + tid] = red[tid] + red[256 + tid];
    } else {
        float rs[8];
#pragma unroll
        for (int k = 0; k < 8; k++) rs[k] = 0.f;
#pragma unroll
        for (int mf = 0; mf < 4; mf++) {
            int row = m0 + warp_m * 64 + mf * 16 + gr;
            float bj0 = (row < Mvalid)     ? bias[row]     : 0.f;
            float bj1 = (row + 8 < Mvalid) ? bias[row + 8] : 0.f;
#pragma unroll
            for (int nf = 0; nf < 8; nf++) {
                rs[mf * 2]     += tanhf(acc[mf][nf][0] + bj0) + tanhf(acc[mf][nf][1] + bj0);
                rs[mf * 2 + 1] += tanhf(acc[mf][nf][2] + bj1) + tanhf(acc[mf][nf][3] + bj1);
            }
        }
#pragma unroll
        for (int o = 1; o < 4; o <<= 1)
#pragma unroll
            for (int k = 0; k < 8; k++) rs[k] += __shfl_xor_sync(0xffffffffu, rs[k], o);
        __syncthreads();
        float* red = reinterpret_cast<float*>(smem);   // [128][4]
        if (q == 0) {
#pragma unroll
            for (int mf = 0; mf < 4; mf++) {
                int lr = warp_m * 64 + mf * 16 + gr;
                red[lr * 4 + warp_n]       = rs[mf * 2];
                red[(lr + 8) * 4 + warp_n] = rs[mf * 2 + 1];
            }
        }
        __syncthreads();
        if (tid < 128) {
            float s = red[tid * 4] + red[tid * 4 + 1] + red[tid * 4 + 2] + red[tid * 4 + 3];
            int f = m0 + tid;
            if (f < Mvalid) tpart[(size_t)f * gridDim.x + blockIdx.x] = s;
        }
    }
}

// ======================= prep: transpose + hi/lo split =======================
__global__ void tsplit_kernel(const float* __restrict__ src,
                              __half* __restrict__ dh, __half* __restrict__ dl,
                              __half* __restrict__ dth, __half* __restrict__ dtl,
                              int R, int C)
{
    __shared__ float t[32][33];
    int tx = threadIdx.x & 31, ty = threadIdx.x >> 5;
    int x = blockIdx.x * 32 + tx;
    int yb = blockIdx.y * 32;
#pragma unroll
    for (int r = 0; r < 4; r++) {
        int row = yb + ty + r * 8;
        float v = src[(size_t)row * C + x];
        __half h = __float2half_rn(v);
        dh[(size_t)row * C + x] = h;
        dl[(size_t)row * C + x] = __float2half_rn(v - __half2float(h));
        t[ty + r * 8][tx] = v;
    }
    __syncthreads();
    int r_ = yb + tx;
#pragma unroll
    for (int r = 0; r < 4; r++) {
        int c_ = blockIdx.x * 32 + ty + r * 8;
        float v = t[tx][ty + r * 8];
        __half h = __float2half_rn(v);
        dth[(size_t)c_ * R + r_] = h;
        dtl[(size_t)c_ * R + r_] = __float2half_rn(v - __half2float(h));
    }
}

__global__ void wsplit_kernel(const float* __restrict__ src,
                              __half* __restrict__ dh, __half* __restrict__ dl,
                              int R, int C, int Rpad)
{
    int idx = blockIdx.x * 256 + threadIdx.x;
    if (idx >= Rpad * C) return;
    int r = idx / C;
    float v = (r < R) ? src[idx] : 0.f;
    __half h = __float2half_rn(v);
    dh[idx] = h;
    dl[idx] = __float2half_rn(v - __half2float(h));
}

// ======================= softmax statistics =======================
__global__ void row_stats_kernel()
{
    int row = blockIdx.x;
    const float* r = g_raw + (size_t)row * N2V;
    int tid = threadIdx.x;
    float m = -1e30f, s = 0.f;
#pragma unroll 4
    for (int j = tid; j < N2V; j += 256) {
        float v = r[j];
        float mn = fmaxf(m, v);
        s = s * __expf(m - mn) + __expf(v - mn);
        m = mn;
    }
#pragma unroll
    for (int o = 16; o; o >>= 1) {
        float mo = __shfl_xor_sync(0xffffffffu, m, o);
        float so = __shfl_xor_sync(0xffffffffu, s, o);
        float mn = fmaxf(m, mo);
        s = s * __expf(m - mn) + so * __expf(mo - mn);
        m = mn;
    }
    __shared__ float sm[8], ss[8];
    if ((tid & 31) == 0) { sm[tid >> 5] = m; ss[tid >> 5] = s; }
    __syncthreads();
    if (tid == 0) {
        float M = sm[0], S = ss[0];
        for (int w = 1; w < 8; w++) {
            float mn = fmaxf(M, sm[w]);
            S = S * __expf(M - mn) + ss[w] * __expf(sm[w] - mn);
            M = mn;
        }
        g_rmax[row] = M;
        g_rinv[row] = 1.0f / S;
    }
}

__global__ void col_stats_kernel()
{
    int lane = threadIdx.x & 31;
    int c = blockIdx.x * 32 + lane;
    int stripe = threadIdx.x >> 5;
    float m = -1e30f, s = 0.f;
#pragma unroll 4
    for (int r = stripe; r < N1V; r += 8) {
        float v = g_raw[(size_t)r * N2V + c];
        float mn = fmaxf(m, v);
        s = s * __expf(m - mn) + __expf(v - mn);
        m = mn;
    }
    __shared__ float sm[8][33], ss[8][33];
    sm[stripe][lane] = m;
    ss[stripe][lane] = s;
    __syncthreads();
    if (threadIdx.x < 32) {
        float M = sm[0][threadIdx.x], S = ss[0][threadIdx.x];
#pragma unroll
        for (int w = 1; w < 8; w++) {
            float mn = fmaxf(M, sm[w][threadIdx.x]);
            S = S * __expf(M - mn) + ss[w][threadIdx.x] * __expf(sm[w][threadIdx.x] - mn);
            M = mn;
        }
        int cc = blockIdx.x * 32 + threadIdx.x;
        g_cmax[cc] = M;
        g_cinv[cc] = 1.0f / S;
    }
}

__global__ void alpha_kernel()
{
    __shared__ float t[32][33];
    int tx = threadIdx.x & 31, ty = threadIdx.x >> 5;
    int i0 = blockIdx.y * 32, j0 = blockIdx.x * 32;
    int j = j0 + tx;
    float cm = g_cmax[j], ci = g_cinv[j];
#pragma unroll
    for (int r = 0; r < 4; r++) {
        int i = i0 + ty + r * 8;
        size_t off = (size_t)i * N2V + j;
        float v = g_raw[off];
        g_a2h[off] = __float2half_rn(__expf(v - g_rmax[i]) * g_rinv[i]);
        t[ty + r * 8][tx] = __expf(v - cm) * ci;
    }
    __syncthreads();
    int xo = i0 + tx;
#pragma unroll
    for (int r = 0; r < 4; r++) {
        int jr = j0 + ty + r * 8;
        g_a1th[(size_t)jr * N1V + xo] = __float2half_rn(t[tx][ty + r * 8]);
    }
}

// ======================= reduce column partials =======================
__global__ void sumv_kernel()
{
    int i = blockIdx.x * 256 + threadIdx.x;
    if (i < DD) {
        float s = 0.f;
        for (int w = 0; w < 64; w++) s += g_cpart1[w * DD + i];
        g_sumv1[i] = s;
    } else if (i < 2 * DD) {
        int c = i - DD;
        float s = 0.f;
        for (int w = 0; w < 64; w++) s += g_cpart2[w * DD + c];
        g_sumv2[c] = s;
    }
}

// ======================= finalize =======================
__global__ void finalize_kernel(const float* __restrict__ Wf1, const float* __restrict__ bf1,
                                const float* __restrict__ Wf2, const float* __restrict__ bf2,
                                float* __restrict__ out)
{
    int g = blockIdx.x * 8 + (threadIdx.x >> 5);
    int lane = threadIdx.x & 31;
    const float inv = 1.0f / 8192.0f;
    if (g < FF) {
        const float* w = Wf1 + (size_t)g * DD;
        float d = 0.f;
        for (int l = lane; l < DD; l += 32) d += w[l] * g_sumv2[l];
#pragma unroll
        for (int o = 16; o; o >>= 1) d += __shfl_xor_sync(0xffffffffu, d, o);
        if (lane == 0) {
            float filt = 1.0f / (1.0f + __expf(-(d * inv + bf1[g])));
            float t = 0.f;
#pragma unroll
            for (int b = 0; b < 32; b++) t += g_tpart1[g * 32 + b];
            out[g] = t * inv * filt;
        }
    } else if (g < 2 * FF) {
        int f = g - FF;
        const float* w = Wf2 + (size_t)f * DD;
        float d = 0.f;
        for (int l = lane; l < DD; l += 32) d += w[l] * g_sumv1[l];
#pragma unroll
        for (int o = 16; o; o >>= 1) d += __shfl_xor_sync(0xffffffffu, d, o);
        if (lane == 0) {
            float filt = 1.0f / (1.0f + __expf(-(d * inv + bf2[f])));
            float t = 0.f;
#pragma unroll
            for (int b = 0; b < 32; b++) t += g_tpart2[f * 32 + b];
            out[FF + f] = t * inv * filt;
        }
    }
}

// ======================= launch =======================
extern "C" void kernel_launch(void* const* d_in, const int* in_sizes, int n_in,
                              void* d_out, int out_size)
{
    const float* m1  = (const float*)d_in[0];
    const float* m2  = (const float*)d_in[1];
    const float* Wf1 = (const float*)d_in[2];
    const float* bf1 = (const float*)d_in[3];
    const float* Wf2 = (const float*)d_in[4];
    const float* bf2 = (const float*)d_in[5];
    const float* W1  = (const float*)d_in[6];
    const float* b1  = (const float*)d_in[7];
    const float* W2  = (const float*)d_in[8];
    const float* b2  = (const float*)d_in[9];
    float* out = (float*)d_out;

    float *raw, *cpart1, *cpart2, *tpart1, *tpart2;
    __half *a2h, *a1th, *m1h, *m1l, *m2h, *m2l, *m1th, *m1tl, *m2th, *m2tl;
    __half *att1h, *att1l, *att2h, *att2l, *w1h, *w1l, *w2h, *w2l;
    cudaGetSymbolAddress((void**)&raw,   g_raw);
    cudaGetSymbolAddress((void**)&a2h,   g_a2h);
    cudaGetSymbolAddress((void**)&a1th,  g_a1th);
    cudaGetSymbolAddress((void**)&m1h,   g_m1h);
    cudaGetSymbolAddress((void**)&m1l,   g_m1l);
    cudaGetSymbolAddress((void**)&m2h,   g_m2h);
    cudaGetSymbolAddress((void**)&m2l,   g_m2l);
    cudaGetSymbolAddress((void**)&m1th,  g_m1th);
    cudaGetSymbolAddress((void**)&m1tl,  g_m1tl);
    cudaGetSymbolAddress((void**)&m2th,  g_m2th);
    cudaGetSymbolAddress((void**)&m2tl,  g_m2tl);
    cudaGetSymbolAddress((void**)&att1h, g_att1h);
    cudaGetSymbolAddress((void**)&att1l, g_att1l);
    cudaGetSymbolAddress((void**)&att2h, g_att2h);
    cudaGetSymbolAddress((void**)&att2l, g_att2l);
    cudaGetSymbolAddress((void**)&w1h,   g_w1h);
    cudaGetSymbolAddress((void**)&w1l,   g_w1l);
    cudaGetSymbolAddress((void**)&w2h,   g_w2h);
    cudaGetSymbolAddress((void**)&w2l,   g_w2l);
    cudaGetSymbolAddress((void**)&cpart1, g_cpart1);
    cudaGetSymbolAddress((void**)&cpart2, g_cpart2);
    cudaGetSymbolAddress((void**)&tpart1, g_tpart1);
    cudaGetSymbolAddress((void**)&tpart2, g_tpart2);

    cudaFuncSetAttribute(hgemm<2, 0>, cudaFuncAttributeMaxDynamicSharedMemorySize, 153600);
    cudaFuncSetAttribute(hgemm<2, 1>, cudaFuncAttributeMaxDynamicSharedMemorySize, 153600);
    cudaFuncSetAttribute(hgemm<3, 2>, cudaFuncAttributeMaxDynamicSharedMemorySize, 184320);

    // 0) prep: split inputs
    tsplit_kernel<<<dim3(DD / 32, N1V / 32), 256>>>(m1, m1h, m1l, m1th, m1tl, N1V, DD);
    tsplit_kernel<<<dim3(DD / 32, N2V / 32), 256>>>(m2, m2h, m2l, m2th, m2tl, N2V, DD);
    wsplit_kernel<<<(FPAD * DD + 255) / 256, 256>>>(W1, w1h, w1l, FF, DD, FPAD);
    wsplit_kernel<<<(FPAD * DD + 255) / 256, 256>>>(W2, w2h, w2l, FF, DD, FPAD);

    // 1) raw = m1 @ m2^T  [8192 x 8192], K=1024, 2-term
    hgemm<2, 0><<<dim3(N2V / 256, N1V / 128), 256, 153600>>>(
        m1h, nullptr, m2h, m2l, raw, nullptr, nullptr, nullptr, N2V, DD, DD / 32, N1V, nullptr, nullptr);

    // 2) softmax stats + alpha materialization (fp16)
    row_stats_kernel<<<N1V, 256>>>();
    col_stats_kernel<<<N2V / 32, 256>>>();
    alpha_kernel<<<dim3(N2V / 32, N1V / 32), 256>>>();

    // 3) attended_m2 = alpha2 @ m2  [8192 x 1024], K=8192, 2-term, fused colsum + hi/lo out
    hgemm<2, 1><<<dim3(DD / 256, N1V / 128), 256, 153600>>>(
        a2h, nullptr, m2th, m2tl, nullptr, att2h, att2l, cpart2, DD, N2V, N2V / 32, N1V, nullptr, nullptr);

    // 4) attended_m1 = alpha1 @ m1  [8192 x 1024], K=8192, 2-term
    hgemm<2, 1><<<dim3(DD / 256, N2V / 128), 256, 153600>>>(
        a1th, nullptr, m1th, m1tl, nullptr, att1h, att1l, cpart1, DD, N1V, N1V / 32, N2V, nullptr, nullptr);

    // 5) reduce column partials
    sumv_kernel<<<8, 256>>>();

    // 6) transform: [F x N] = W @ att^T, 3-term, fused tanh+rowsum
    hgemm<3, 2><<<dim3(N2V / 256, FPAD / 128), 256, 184320>>>(
        w1h, w1l, att1h, att1l, nullptr, nullptr, nullptr, nullptr, 0, DD, DD / 32, FF, b1, tpart1);
    hgemm<3, 2><<<dim3(N1V / 256, FPAD / 128), 256, 184320>>>(
        w2h, w2l, att2h, att2l, nullptr, nullptr, nullptr, nullptr, 0, DD, DD / 32, FF, b2, tpart2);

    // 7) filters + outputs
    finalize_kernel<<<200, 256>>>(Wf1, bf1, Wf2, bf2, out);
}

// round 7
// speedup vs baseline: 3.8615x; 1.1921x over previous
#include <cuda_runtime.h>
#include <cuda_fp16.h>
#include <math.h>
#include <stdint.h>
#include <stddef.h>

#define N1V 8192
#define N2V 8192
#define DD  1024
#define FF  800
#define FPAD 896

// ======================= scratch (device globals) =======================
__device__ float  g_raw [(size_t)N1V * N2V];    // raw logits fp32
__device__ __half g_a2h [(size_t)N1V * N2V];    // alpha2 fp16
__device__ __half g_a1th[(size_t)N2V * N1V];    // alpha1^T fp16
__device__ __half g_m1h[(size_t)N1V * DD], g_m1l[(size_t)N1V * DD];
__device__ __half g_m2h[(size_t)N2V * DD], g_m2l[(size_t)N2V * DD];
__device__ __half g_m1th[(size_t)DD * N1V];
__device__ __half g_m2th[(size_t)DD * N2V];
__device__ __half g_att1h[(size_t)N2V * DD];
__device__ __half g_att2h[(size_t)N1V * DD];
__device__ __half g_w1h[FPAD * DD], g_w1l[FPAD * DD];
__device__ __half g_w2h[FPAD * DD], g_w2l[FPAD * DD];
__device__ float g_rmax[N1V], g_rinv[N1V];
__device__ float g_cmax[N2V], g_cinv[N2V];
__device__ float g_cpart1[64 * DD], g_cpart2[64 * DD];
__device__ float g_sumv1[DD], g_sumv2[DD];
__device__ float g_tpart1[FPAD * 32], g_tpart2[FPAD * 32];

// ======================= asm helpers =======================
static __device__ __forceinline__ uint32_t smem_u32(const void* p) {
    uint32_t a;
    asm("{ .reg .u64 t; cvta.to.shared.u64 t, %1; cvt.u32.u64 %0, t; }" : "=r"(a) : "l"(p));
    return a;
}
static __device__ __forceinline__ uint64_t gaddr(const void* p) {
    uint64_t a;
    asm("cvta.to.global.u64 %0, %1;" : "=l"(a) : "l"(p));
    return a;
}
static __device__ __forceinline__ void cpa16(uint32_t dst, uint64_t src) {
    asm volatile("cp.async.cg.shared.global [%0], [%1], 16;" :: "r"(dst), "l"(src));
}
static __device__ __forceinline__ void ldsm_x4(uint32_t& r0, uint32_t& r1, uint32_t& r2, uint32_t& r3, uint32_t addr) {
    asm volatile("ldmatrix.sync.aligned.m8n8.x4.shared.b16 {%0,%1,%2,%3}, [%4];"
                 : "=r"(r0), "=r"(r1), "=r"(r2), "=r"(r3) : "r"(addr));
}
static __device__ __forceinline__ void mma16816(float* d, const uint32_t* a, uint32_t b0, uint32_t b1) {
    asm volatile("mma.sync.aligned.m16n8k16.row.col.f32.f16.f16.f32 "
                 "{%0,%1,%2,%3}, {%4,%5,%6,%7}, {%8,%9}, {%0,%1,%2,%3};"
                 : "+f"(d[0]), "+f"(d[1]), "+f"(d[2]), "+f"(d[3])
                 : "r"(a[0]), "r"(a[1]), "r"(a[2]), "r"(a[3]), "r"(b0), "r"(b1));
}

// ======================= HMMA GEMM, 128x256 block, 64x64 warp tiles =======================
// C[M,N] = sum_k A[m,k]*B[n,k]; fp16 pre-split operands, k-contig, K%32==0.
// Terms: Ah*Bh always; + Ah*Bl if BT==2; + Al*Bh if AT==2.
// 256 threads = 8 warps (2 m x 4 n), 3-stage cp.async pipeline.
// EPI 0: store C fp32 (pitch ldw).
// EPI 1: OutH fp16 (pitch ldw) + block-row column sums -> cpart[by*DD + n0+c].
// EPI 2: tanh(acc + bias[m]) row-summed over n-tile -> tpart[m*gridDim.x + bx], m < Mvalid.
template<int AT, int BT, int EPI>
__global__ void __launch_bounds__(256, 1)
hgemm(const __half* __restrict__ Ah, const __half* __restrict__ Al,
      const __half* __restrict__ Bh, const __half* __restrict__ Bl,
      float* __restrict__ C, __half* __restrict__ OutH,
      float* __restrict__ cpart, long ldw, int K, int NT, int Mvalid,
      const float* __restrict__ bias, float* __restrict__ tpart)
{
    extern __shared__ char smem[];
    const uint32_t sbase = smem_u32(smem);
    const int OB    = AT * 10240;                 // B-hi offset; B-lo at OB+20480
    const int STGSZ = AT * 10240 + BT * 20480;
    const int tid = threadIdx.x, lane = tid & 31, wid = tid >> 5;
    const int warp_m = wid & 1;      // 2 x 64 rows
    const int warp_n = wid >> 1;     // 4 x 64 cols
    const int m0 = blockIdx.y * 128;
    const int n0 = blockIdx.x * 256;

    const int arow = lane & 15, acol = (lane >> 4) << 3;
    const int brow = (lane & 7) + ((lane & 16) >> 1);
    const int bcol = lane & 8;

    const uint64_t gAh = gaddr(Ah);
    const uint64_t gAl = (AT == 2) ? gaddr(Al) : 0ull;
    const uint64_t gBh = gaddr(Bh);
    const uint64_t gBl = (BT == 2) ? gaddr(Bl) : 0ull;

    float acc[4][8][4];
#pragma unroll
    for (int i = 0; i < 4; i++)
#pragma unroll
        for (int j = 0; j < 8; j++)
#pragma unroll
            for (int k = 0; k < 4; k++) acc[i][j][k] = 0.f;

    auto load_stage = [&](int kt, int bufi) {
        const int k0 = kt * 32;
        uint32_t sb = sbase + bufi * STGSZ;
#pragma unroll
        for (int i = 0; i < 2; i++) {                 // A: 128 rows x 32k
            int idx = tid + i * 256;
            int r = idx >> 2, c = (idx & 3) << 3;
            uint32_t d = sb + (uint32_t)(r * 40 + c) * 2;
            uint64_t ao = ((uint64_t)(m0 + r) * K + k0 + c) * 2;
            cpa16(d, gAh + ao);
            if (AT == 2) cpa16(d + 10240, gAl + ao);
        }
#pragma unroll
        for (int i = 0; i < 4; i++) {                 // B: 256 rows x 32k
            int idx = tid + i * 256;
            int r = idx >> 2, c = (idx & 3) << 3;
            uint32_t d = sb + OB + (uint32_t)(r * 40 + c) * 2;
            uint64_t bo = ((uint64_t)(n0 + r) * K + k0 + c) * 2;
            cpa16(d, gBh + bo);
            if (BT == 2) cpa16(d + 20480, gBl + bo);
        }
        asm volatile("cp.async.commit_group;" ::: "memory");
    };

    load_stage(0, 0);
    load_stage(1, 1);
    for (int t = 0; t < NT; t++) {
        if (t + 2 < NT) {
            load_stage(t + 2, (t + 2) % 3);
            asm volatile("cp.async.wait_group 2;" ::: "memory");
        } else if (t + 1 < NT) {
            asm volatile("cp.async.wait_group 1;" ::: "memory");
        } else {
            asm volatile("cp.async.wait_group 0;" ::: "memory");
        }
        __syncthreads();
        uint32_t sa = sbase + (t % 3) * STGSZ;
#pragma unroll
        for (int ks = 0; ks < 2; ks++) {
            uint32_t ah[4][4], al[4][4];
#pragma unroll
            for (int mf = 0; mf < 4; mf++) {
                uint32_t addr = sa + (uint32_t)((warp_m * 64 + mf * 16 + arow) * 40 + ks * 16 + acol) * 2;
                ldsm_x4(ah[mf][0], ah[mf][1], ah[mf][2], ah[mf][3], addr);
                if (AT == 2)
                    ldsm_x4(al[mf][0], al[mf][1], al[mf][2], al[mf][3], addr + 10240);
            }
            uint32_t bh[4][4], bl[4][4];
#pragma unroll
            for (int nf2 = 0; nf2 < 4; nf2++) {
                uint32_t addr = sa + OB + (uint32_t)((warp_n * 64 + nf2 * 16 + brow) * 40 + ks * 16 + bcol) * 2;
                ldsm_x4(bh[nf2][0], bh[nf2][1], bh[nf2][2], bh[nf2][3], addr);
                if (BT == 2)
                    ldsm_x4(bl[nf2][0], bl[nf2][1], bl[nf2][2], bl[nf2][3], addr + 20480);
            }
#pragma unroll
            for (int mf = 0; mf < 4; mf++)
#pragma unroll
                for (int nf = 0; nf < 8; nf++) {
                    int nf2 = nf >> 1, o = (nf & 1) * 2;
                    mma16816(acc[mf][nf], ah[mf], bh[nf2][o], bh[nf2][o + 1]);
                    if (BT == 2)
                        mma16816(acc[mf][nf], ah[mf], bl[nf2][o], bl[nf2][o + 1]);
                    if (AT == 2)
                        mma16816(acc[mf][nf], al[mf], bh[nf2][o], bh[nf2][o + 1]);
                }
        }
        __syncthreads();
    }

    const int gr = lane >> 2, q = lane & 3;
    if (EPI == 0) {
#pragma unroll
        for (int mf = 0; mf < 4; mf++)
#pragma unroll
            for (int nf = 0; nf < 8; nf++) {
                int row = m0 + warp_m * 64 + mf * 16 + gr;
                int col = n0 + warp_n * 64 + nf * 8 + q * 2;
                *reinterpret_cast<float2*>(C + (size_t)row * ldw + col) =
                    make_float2(acc[mf][nf][0], acc[mf][nf][1]);
                *reinterpret_cast<float2*>(C + (size_t)(row + 8) * ldw + col) =
                    make_float2(acc[mf][nf][2], acc[mf][nf][3]);
            }
    } else if (EPI == 1) {
        float cs[8][2];
#pragma unroll
        for (int nf = 0; nf < 8; nf++) { cs[nf][0] = 0.f; cs[nf][1] = 0.f; }
#pragma unroll
        for (int mf = 0; mf < 4; mf++)
#pragma unroll
            for (int nf = 0; nf < 8; nf++) {
                int row = m0 + warp_m * 64 + mf * 16 + gr;
                int col = warp_n * 64 + nf * 8 + q * 2;
                float v0 = acc[mf][nf][0], v1 = acc[mf][nf][1];
                float v2 = acc[mf][nf][2], v3 = acc[mf][nf][3];
                size_t o0 = (size_t)row * ldw + n0 + col;
                size_t o1 = (size_t)(row + 8) * ldw + n0 + col;
                *reinterpret_cast<__half2*>(OutH + o0) = __floats2half2_rn(v0, v1);
                *reinterpret_cast<__half2*>(OutH + o1) = __floats2half2_rn(v2, v3);
                cs[nf][0] += v0 + v2;
                cs[nf][1] += v1 + v3;
            }
#pragma unroll
        for (int o = 4; o < 32; o <<= 1)
#pragma unroll
            for (int nf = 0; nf < 8; nf++) {
                cs[nf][0] += __shfl_xor_sync(0xffffffffu, cs[nf][0], o);
                cs[nf][1] += __shfl_xor_sync(0xffffffffu, cs[nf][1], o);
            }
        __syncthreads();
        float* red = reinterpret_cast<float*>(smem);   // [2][256]
        if (lane < 4) {
#pragma unroll
            for (int nf = 0; nf < 8; nf++) {
                red[warp_m * 256 + warp_n * 64 + nf * 8 + lane * 2]     = cs[nf][0];
                red[warp_m * 256 + warp_n * 64 + nf * 8 + lane * 2 + 1] = cs[nf][1];
            }
        }
        __syncthreads();
        cpart[(size_t)blockIdx.y * DD + n0 + tid] = red[tid] + red[256 + tid];
    } else {
        float rs[8];
#pragma unroll
        for (int k = 0; k < 8; k++) rs[k] = 0.f;
#pragma unroll
        for (int mf = 0; mf < 4; mf++) {
            int row = m0 + warp_m * 64 + mf * 16 + gr;
            float bj0 = (row < Mvalid)     ? bias[row]     : 0.f;
            float bj1 = (row + 8 < Mvalid) ? bias[row + 8] : 0.f;
#pragma unroll
            for (int nf = 0; nf < 8; nf++) {
                rs[mf * 2]     += tanhf(acc[mf][nf][0] + bj0) + tanhf(acc[mf][nf][1] + bj0);
                rs[mf * 2 + 1] += tanhf(acc[mf][nf][2] + bj1) + tanhf(acc[mf][nf][3] + bj1);
            }
        }
#pragma unroll
        for (int o = 1; o < 4; o <<= 1)
#pragma unroll
            for (int k = 0; k < 8; k++) rs[k] += __shfl_xor_sync(0xffffffffu, rs[k], o);
        __syncthreads();
        float* red = reinterpret_cast<float*>(smem);   // [128][4]
        if (q == 0) {
#pragma unroll
            for (int mf = 0; mf < 4; mf++) {
                int lr = warp_m * 64 + mf * 16 + gr;
                red[lr * 4 + warp_n]       = rs[mf * 2];
                red[(lr + 8) * 4 + warp_n] = rs[mf * 2 + 1];
            }
        }
        __syncthreads();
        if (tid < 128) {
            float s = red[tid * 4] + red[tid * 4 + 1] + red[tid * 4 + 2] + red[tid * 4 + 3];
            int f = m0 + tid;
            if (f < Mvalid) tpart[(size_t)f * gridDim.x + blockIdx.x] = s;
        }
    }
}

// ======================= prep: transpose + hi/lo split =======================
__global__ void tsplit_kernel(const float* __restrict__ src,
                              __half* __restrict__ dh, __half* __restrict__ dl,
                              __half* __restrict__ dth,
                              int R, int C)
{
    __shared__ float t[32][33];
    int tx = threadIdx.x & 31, ty = threadIdx.x >> 5;
    int x = blockIdx.x * 32 + tx;
    int yb = blockIdx.y * 32;
#pragma unroll
    for (int r = 0; r < 4; r++) {
        int row = yb + ty + r * 8;
        float v = src[(size_t)row * C + x];
        __half h = __float2half_rn(v);
        dh[(size_t)row * C + x] = h;
        dl[(size_t)row * C + x] = __float2half_rn(v - __half2float(h));
        t[ty + r * 8][tx] = v;
    }
    __syncthreads();
    int r_ = yb + tx;
#pragma unroll
    for (int r = 0; r < 4; r++) {
        int c_ = blockIdx.x * 32 + ty + r * 8;
        dth[(size_t)c_ * R + r_] = __float2half_rn(t[tx][ty + r * 8]);
    }
}

__global__ void wsplit_kernel(const float* __restrict__ src,
                              __half* __restrict__ dh, __half* __restrict__ dl,
                              int R, int C, int Rpad)
{
    int idx = blockIdx.x * 256 + threadIdx.x;
    if (idx >= Rpad * C) return;
    int r = idx / C;
    float v = (r < R) ? src[idx] : 0.f;
    __half h = __float2half_rn(v);
    dh[idx] = h;
    dl[idx] = __float2half_rn(v - __half2float(h));
}

// ======================= softmax statistics =======================
__global__ void row_stats_kernel()
{
    int row = blockIdx.x;
    const float* r = g_raw + (size_t)row * N2V;
    int tid = threadIdx.x;
    float m = -1e30f, s = 0.f;
#pragma unroll 4
    for (int j = tid; j < N2V; j += 256) {
        float v = r[j];
        float mn = fmaxf(m, v);
        s = s * __expf(m - mn) + __expf(v - mn);
        m = mn;
    }
#pragma unroll
    for (int o = 16; o; o >>= 1) {
        float mo = __shfl_xor_sync(0xffffffffu, m, o);
        float so = __shfl_xor_sync(0xffffffffu, s, o);
        float mn = fmaxf(m, mo);
        s = s * __expf(m - mn) + so * __expf(mo - mn);
        m = mn;
    }
    __shared__ float sm[8], ss[8];
    if ((tid & 31) == 0) { sm[tid >> 5] = m; ss[tid >> 5] = s; }
    __syncthreads();
    if (tid == 0) {
        float M = sm[0], S = ss[0];
        for (int w = 1; w < 8; w++) {
            float mn = fmaxf(M, sm[w]);
            S = S * __expf(M - mn) + ss[w] * __expf(sm[w] - mn);
            M = mn;
        }
        g_rmax[row] = M;
        g_rinv[row] = 1.0f / S;
    }
}

__global__ void col_stats_kernel()
{
    int lane = threadIdx.x & 31;
    int c = blockIdx.x * 32 + lane;
    int stripe = threadIdx.x >> 5;
    float m = -1e30f, s = 0.f;
#pragma unroll 4
    for (int r = stripe; r < N1V; r += 8) {
        float v = g_raw[(size_t)r * N2V + c];
        float mn = fmaxf(m, v);
        s = s * __expf(m - mn) + __expf(v - mn);
        m = mn;
    }
    __shared__ float sm[8][33], ss[8][33];
    sm[stripe][lane] = m;
    ss[stripe][lane] = s;
    __syncthreads();
    if (threadIdx.x < 32) {
        float M = sm[0][threadIdx.x], S = ss[0][threadIdx.x];
#pragma unroll
        for (int w = 1; w < 8; w++) {
            float mn = fmaxf(M, sm[w][threadIdx.x]);
            S = S * __expf(M - mn) + ss[w][threadIdx.x] * __expf(sm[w][threadIdx.x] - mn);
            M = mn;
        }
        int cc = blockIdx.x * 32 + threadIdx.x;
        g_cmax[cc] = M;
        g_cinv[cc] = 1.0f / S;
    }
}

__global__ void alpha_kernel()
{
    __shared__ float t[32][33];
    int tx = threadIdx.x & 31, ty = threadIdx.x >> 5;
    int i0 = blockIdx.y * 32, j0 = blockIdx.x * 32;
    int j = j0 + tx;
    float cm = g_cmax[j], ci = g_cinv[j];
#pragma unroll
    for (int r = 0; r < 4; r++) {
        int i = i0 + ty + r * 8;
        size_t off = (size_t)i * N2V + j;
        float v = g_raw[off];
        g_a2h[off] = __float2half_rn(__expf(v - g_rmax[i]) * g_rinv[i]);
        t[ty + r * 8][tx] = __expf(v - cm) * ci;
    }
    __syncthreads();
    int xo = i0 + tx;
#pragma unroll
    for (int r = 0; r < 4; r++) {
        int jr = j0 + ty + r * 8;
        g_a1th[(size_t)jr * N1V + xo] = __float2half_rn(t[tx][ty + r * 8]);
    }
}

// ======================= reduce column partials =======================
__global__ void sumv_kernel()
{
    int i = blockIdx.x * 256 + threadIdx.x;
    if (i < DD) {
        float s = 0.f;
        for (int w = 0; w < 64; w++) s += g_cpart1[w * DD + i];
        g_sumv1[i] = s;
    } else if (i < 2 * DD) {
        int c = i - DD;
        float s = 0.f;
        for (int w = 0; w < 64; w++) s += g_cpart2[w * DD + c];
        g_sumv2[c] = s;
    }
}

// ======================= finalize =======================
__global__ void finalize_kernel(const float* __restrict__ Wf1, const float* __restrict__ bf1,
                                const float* __restrict__ Wf2, const float* __restrict__ bf2,
                                float* __restrict__ out)
{
    int g = blockIdx.x * 8 + (threadIdx.x >> 5);
    int lane = threadIdx.x & 31;
    const float inv = 1.0f / 8192.0f;
    if (g < FF) {
        const float* w = Wf1 + (size_t)g * DD;
        float d = 0.f;
        for (int l = lane; l < DD; l += 32) d += w[l] * g_sumv2[l];
#pragma unroll
        for (int o = 16; o; o >>= 1) d += __shfl_xor_sync(0xffffffffu, d, o);
        if (lane == 0) {
            float filt = 1.0f / (1.0f + __expf(-(d * inv + bf1[g])));
            float t = 0.f;
#pragma unroll
            for (int b = 0; b < 32; b++) t += g_tpart1[g * 32 + b];
            out[g] = t * inv * filt;
        }
    } else if (g < 2 * FF) {
        int f = g - FF;
        const float* w = Wf2 + (size_t)f * DD;
        float d = 0.f;
        for (int l = lane; l < DD; l += 32) d += w[l] * g_sumv1[l];
#pragma unroll
        for (int o = 16; o; o >>= 1) d += __shfl_xor_sync(0xffffffffu, d, o);
        if (lane == 0) {
            float filt = 1.0f / (1.0f + __expf(-(d * inv + bf2[f])));
            float t = 0.f;
#pragma unroll
            for (int b = 0; b < 32; b++) t += g_tpart2[f * 32 + b];
            out[FF + f] = t * inv * filt;
        }
    }
}

// ======================= launch =======================
extern "C" void kernel_launch(void* const* d_in, const int* in_sizes, int n_in,
                              void* d_out, int out_size)
{
    const float* m1  = (const float*)d_in[0];
    const float* m2  = (const float*)d_in[1];
    const float* Wf1 = (const float*)d_in[2];
    const float* bf1 = (const float*)d_in[3];
    const float* Wf2 = (const float*)d_in[4];
    const float* bf2 = (const float*)d_in[5];
    const float* W1  = (const float*)d_in[6];
    const float* b1  = (const float*)d_in[7];
    const float* W2  = (const float*)d_in[8];
    const float* b2  = (const float*)d_in[9];
    float* out = (float*)d_out;

    float *raw, *cpart1, *cpart2, *tpart1, *tpart2;
    __half *a2h, *a1th, *m1h, *m1l, *m2h, *m2l, *m1th, *m2th;
    __half *att1h, *att2h, *w1h, *w1l, *w2h, *w2l;
    cudaGetSymbolAddress((void**)&raw,   g_raw);
    cudaGetSymbolAddress((void**)&a2h,   g_a2h);
    cudaGetSymbolAddress((void**)&a1th,  g_a1th);
    cudaGetSymbolAddress((void**)&m1h,   g_m1h);
    cudaGetSymbolAddress((void**)&m1l,   g_m1l);
    cudaGetSymbolAddress((void**)&m2h,   g_m2h);
    cudaGetSymbolAddress((void**)&m2l,   g_m2l);
    cudaGetSymbolAddress((void**)&m1th,  g_m1th);
    cudaGetSymbolAddress((void**)&m2th,  g_m2th);
    cudaGetSymbolAddress((void**)&att1h, g_att1h);
    cudaGetSymbolAddress((void**)&att2h, g_att2h);
    cudaGetSymbolAddress((void**)&w1h,   g_w1h);
    cudaGetSymbolAddress((void**)&w1l,   g_w1l);
    cudaGetSymbolAddress((void**)&w2h,   g_w2h);
    cudaGetSymbolAddress((void**)&w2l,   g_w2l);
    cudaGetSymbolAddress((void**)&cpart1, g_cpart1);
    cudaGetSymbolAddress((void**)&cpart2, g_cpart2);
    cudaGetSymbolAddress((void**)&tpart1, g_tpart1);
    cudaGetSymbolAddress((void**)&tpart2, g_tpart2);

    cudaFuncSetAttribute(hgemm<2, 2, 0>, cudaFuncAttributeMaxDynamicSharedMemorySize, 184320);
    cudaFuncSetAttribute(hgemm<1, 1, 1>, cudaFuncAttributeMaxDynamicSharedMemorySize, 92160);
    cudaFuncSetAttribute(hgemm<2, 1, 2>, cudaFuncAttributeMaxDynamicSharedMemorySize, 122880);

    // 0) prep: split inputs (m transposes now hi-only)
    tsplit_kernel<<<dim3(DD / 32, N1V / 32), 256>>>(m1, m1h, m1l, m1th, N1V, DD);
    tsplit_kernel<<<dim3(DD / 32, N2V / 32), 256>>>(m2, m2h, m2l, m2th, N2V, DD);
    wsplit_kernel<<<(FPAD * DD + 255) / 256, 256>>>(W1, w1h, w1l, FF, DD, FPAD);
    wsplit_kernel<<<(FPAD * DD + 255) / 256, 256>>>(W2, w2h, w2l, FF, DD, FPAD);

    // 1) raw = m1 @ m2^T  [8192 x 8192], K=1024, 3-term (logit path: precision-critical)
    hgemm<2, 2, 0><<<dim3(N2V / 256, N1V / 128), 256, 184320>>>(
        m1h, m1l, m2h, m2l, raw, nullptr, nullptr, N2V, DD, DD / 32, N1V, nullptr, nullptr);

    // 2) softmax stats + alpha materialization (fp16)
    row_stats_kernel<<<N1V, 256>>>();
    col_stats_kernel<<<N2V / 32, 256>>>();
    alpha_kernel<<<dim3(N2V / 32, N1V / 32), 256>>>();

    // 3) attended_m2 = alpha2 @ m2  [8192 x 1024], K=8192, 1-term, fused colsum + fp16 out
    hgemm<1, 1, 1><<<dim3(DD / 256, N1V / 128), 256, 92160>>>(
        a2h, nullptr, m2th, nullptr, nullptr, att2h, cpart2, DD, N2V, N2V / 32, N1V, nullptr, nullptr);

    // 4) attended_m1 = alpha1 @ m1  [8192 x 1024], K=8192, 1-term
    hgemm<1, 1, 1><<<dim3(DD / 256, N2V / 128), 256, 92160>>>(
        a1th, nullptr, m1th, nullptr, nullptr, att1h, cpart1, DD, N1V, N1V / 32, N2V, nullptr, nullptr);

    // 5) reduce column partials
    sumv_kernel<<<8, 256>>>();

    // 6) transform: [F x N] = W @ att^T, 2-term (W h/l x att_h), fused tanh+rowsum
    hgemm<2, 1, 2><<<dim3(N2V / 256, FPAD / 128), 256, 122880>>>(
        w1h, w1l, att1h, nullptr, nullptr, nullptr, nullptr, 0, DD, DD / 32, FF, b1, tpart1);
    hgemm<2, 1, 2><<<dim3(N1V / 256, FPAD / 128), 256, 122880>>>(
        w2h, w2l, att2h, nullptr, nullptr, nullptr, nullptr, 0, DD, DD / 32, FF, b2, tpart2);

    // 7) filters + outputs
    finalize_kernel<<<200, 256>>>(Wf1, bf1, Wf2, bf2, out);
}

// round 8
// speedup vs baseline: 4.1838x; 1.0835x over previous
#include <cuda_runtime.h>
#include <cuda_fp16.h>
#include <math.h>
#include <stdint.h>
#include <stddef.h>

#define N1V 8192
#define N2V 8192
#define DD  1024
#define FF  800
#define FPAD 896

// ======================= scratch (device globals) =======================
__device__ float  g_raw [(size_t)N1V * N2V];    // raw logits fp32
__device__ __half g_a2h [(size_t)N1V * N2V];    // alpha2 fp16
__device__ __half g_a1th[(size_t)N2V * N1V];    // alpha1^T fp16
__device__ __half g_m1h[(size_t)N1V * DD], g_m1l[(size_t)N1V * DD];
__device__ __half g_m2h[(size_t)N2V * DD], g_m2l[(size_t)N2V * DD];
__device__ __half g_m1th[(size_t)DD * N1V];
__device__ __half g_m2th[(size_t)DD * N2V];
__device__ __half g_att1h[(size_t)N2V * DD];
__device__ __half g_att2h[(size_t)N1V * DD];
__device__ __half g_w1h[FPAD * DD];
__device__ __half g_w2h[FPAD * DD];
__device__ float g_rmax[N1V], g_rinv[N1V];
__device__ float g_cmax[N2V], g_cinv[N2V];
__device__ float g_rpm[(size_t)N1V * 32], g_rps[(size_t)N1V * 32];   // row stat partials
__device__ float g_cpm[(size_t)N2V * 64], g_cps[(size_t)N2V * 64];   // col stat partials
__device__ float g_cpart1[64 * DD], g_cpart2[64 * DD];
__device__ float g_sumv1[DD], g_sumv2[DD];
__device__ float g_tpart1[FPAD * 32], g_tpart2[FPAD * 32];

// ======================= asm helpers =======================
static __device__ __forceinline__ uint32_t smem_u32(const void* p) {
    uint32_t a;
    asm("{ .reg .u64 t; cvta.to.shared.u64 t, %1; cvt.u32.u64 %0, t; }" : "=r"(a) : "l"(p));
    return a;
}
static __device__ __forceinline__ uint64_t gaddr(const void* p) {
    uint64_t a;
    asm("cvta.to.global.u64 %0, %1;" : "=l"(a) : "l"(p));
    return a;
}
static __device__ __forceinline__ void cpa16(uint32_t dst, uint64_t src) {
    asm volatile("cp.async.cg.shared.global [%0], [%1], 16;" :: "r"(dst), "l"(src));
}
static __device__ __forceinline__ void ldsm_x4(uint32_t& r0, uint32_t& r1, uint32_t& r2, uint32_t& r3, uint32_t addr) {
    asm volatile("ldmatrix.sync.aligned.m8n8.x4.shared.b16 {%0,%1,%2,%3}, [%4];"
                 : "=r"(r0), "=r"(r1), "=r"(r2), "=r"(r3) : "r"(addr));
}
static __device__ __forceinline__ void mma16816(float* d, const uint32_t* a, uint32_t b0, uint32_t b1) {
    asm volatile("mma.sync.aligned.m16n8k16.row.col.f32.f16.f16.f32 "
                 "{%0,%1,%2,%3}, {%4,%5,%6,%7}, {%8,%9}, {%0,%1,%2,%3};"
                 : "+f"(d[0]), "+f"(d[1]), "+f"(d[2]), "+f"(d[3])
                 : "r"(a[0]), "r"(a[1]), "r"(a[2]), "r"(a[3]), "r"(b0), "r"(b1));
}
// online softmax-stat merge: (m,s) <- merge((m,s), (mo,so))
static __device__ __forceinline__ void msmerge(float& m, float& s, float mo, float so) {
    float mn = fmaxf(m, mo);
    s = s * __expf(m - mn) + so * __expf(mo - mn);
    m = mn;
}

// ======================= HMMA GEMM, 128x256 block, 64x64 warp tiles =======================
// C[M,N] = sum_k A[m,k]*B[n,k]; fp16 pre-split operands, k-contig, K%32==0.
// Terms: Ah*Bh always; + Ah*Bl if BT==2; + Al*Bh if AT==2.
// 256 threads = 8 warps (2 m x 4 n), 3-stage cp.async pipeline.
// EPI 0: store C fp32 (pitch ldw) + softmax partials:
//        rpm/rps[m*32 + bx] row (max,sumexp) over this 256-col slice,
//        cpm/cps[n*64 + by] col (max,sumexp) over this 128-row slice.
// EPI 1: OutH fp16 (pitch ldw) + block-row column sums -> cpart[by*DD + n0+c].
// EPI 2: tanh(acc + bias[m]) row-summed over n-tile -> tpart[m*gridDim.x + bx], m < Mvalid.
template<int AT, int BT, int EPI>
__global__ void __launch_bounds__(256, 1)
hgemm(const __half* __restrict__ Ah, const __half* __restrict__ Al,
      const __half* __restrict__ Bh, const __half* __restrict__ Bl,
      float* __restrict__ C, __half* __restrict__ OutH,
      float* __restrict__ cpart, long ldw, int K, int NT, int Mvalid,
      const float* __restrict__ bias, float* __restrict__ tpart,
      float* __restrict__ rpm, float* __restrict__ rps,
      float* __restrict__ cpm, float* __restrict__ cps)
{
    extern __shared__ char smem[];
    const uint32_t sbase = smem_u32(smem);
    const int OB    = AT * 10240;                 // B-hi offset; B-lo at OB+20480
    const int STGSZ = AT * 10240 + BT * 20480;
    const int tid = threadIdx.x, lane = tid & 31, wid = tid >> 5;
    const int warp_m = wid & 1;      // 2 x 64 rows
    const int warp_n = wid >> 1;     // 4 x 64 cols
    const int m0 = blockIdx.y * 128;
    const int n0 = blockIdx.x * 256;

    const int arow = lane & 15, acol = (lane >> 4) << 3;
    const int brow = (lane & 7) + ((lane & 16) >> 1);
    const int bcol = lane & 8;

    const uint64_t gAh = gaddr(Ah);
    const uint64_t gAl = (AT == 2) ? gaddr(Al) : 0ull;
    const uint64_t gBh = gaddr(Bh);
    const uint64_t gBl = (BT == 2) ? gaddr(Bl) : 0ull;

    float acc[4][8][4];
#pragma unroll
    for (int i = 0; i < 4; i++)
#pragma unroll
        for (int j = 0; j < 8; j++)
#pragma unroll
            for (int k = 0; k < 4; k++) acc[i][j][k] = 0.f;

    auto load_stage = [&](int kt, int bufi) {
        const int k0 = kt * 32;
        uint32_t sb = sbase + bufi * STGSZ;
#pragma unroll
        for (int i = 0; i < 2; i++) {                 // A: 128 rows x 32k
            int idx = tid + i * 256;
            int r = idx >> 2, c = (idx & 3) << 3;
            uint32_t d = sb + (uint32_t)(r * 40 + c) * 2;
            uint64_t ao = ((uint64_t)(m0 + r) * K + k0 + c) * 2;
            cpa16(d, gAh + ao);
            if (AT == 2) cpa16(d + 10240, gAl + ao);
        }
#pragma unroll
        for (int i = 0; i < 4; i++) {                 // B: 256 rows x 32k
            int idx = tid + i * 256;
            int r = idx >> 2, c = (idx & 3) << 3;
            uint32_t d = sb + OB + (uint32_t)(r * 40 + c) * 2;
            uint64_t bo = ((uint64_t)(n0 + r) * K + k0 + c) * 2;
            cpa16(d, gBh + bo);
            if (BT == 2) cpa16(d + 20480, gBl + bo);
        }
        asm volatile("cp.async.commit_group;" ::: "memory");
    };

    load_stage(0, 0);
    load_stage(1, 1);
    for (int t = 0; t < NT; t++) {
        if (t + 2 < NT) {
            load_stage(t + 2, (t + 2) % 3);
            asm volatile("cp.async.wait_group 2;" ::: "memory");
        } else if (t + 1 < NT) {
            asm volatile("cp.async.wait_group 1;" ::: "memory");
        } else {
            asm volatile("cp.async.wait_group 0;" ::: "memory");
        }
        __syncthreads();
        uint32_t sa = sbase + (t % 3) * STGSZ;
#pragma unroll
        for (int ks = 0; ks < 2; ks++) {
            uint32_t ah[4][4], al[4][4];
#pragma unroll
            for (int mf = 0; mf < 4; mf++) {
                uint32_t addr = sa + (uint32_t)((warp_m * 64 + mf * 16 + arow) * 40 + ks * 16 + acol) * 2;
                ldsm_x4(ah[mf][0], ah[mf][1], ah[mf][2], ah[mf][3], addr);
                if (AT == 2)
                    ldsm_x4(al[mf][0], al[mf][1], al[mf][2], al[mf][3], addr + 10240);
            }
            uint32_t bh[4][4], bl[4][4];
#pragma unroll
            for (int nf2 = 0; nf2 < 4; nf2++) {
                uint32_t addr = sa + OB + (uint32_t)((warp_n * 64 + nf2 * 16 + brow) * 40 + ks * 16 + bcol) * 2;
                ldsm_x4(bh[nf2][0], bh[nf2][1], bh[nf2][2], bh[nf2][3], addr);
                if (BT == 2)
                    ldsm_x4(bl[nf2][0], bl[nf2][1], bl[nf2][2], bl[nf2][3], addr + 20480);
            }
#pragma unroll
            for (int mf = 0; mf < 4; mf++)
#pragma unroll
                for (int nf = 0; nf < 8; nf++) {
                    int nf2 = nf >> 1, o = (nf & 1) * 2;
                    mma16816(acc[mf][nf], ah[mf], bh[nf2][o], bh[nf2][o + 1]);
                    if (BT == 2)
                        mma16816(acc[mf][nf], ah[mf], bl[nf2][o], bl[nf2][o + 1]);
                    if (AT == 2)
                        mma16816(acc[mf][nf], al[mf], bh[nf2][o], bh[nf2][o + 1]);
                }
        }
        __syncthreads();
    }

    const int gr = lane >> 2, q = lane & 3;
    if (EPI == 0) {
        // ---- store C ----
#pragma unroll
        for (int mf = 0; mf < 4; mf++)
#pragma unroll
            for (int nf = 0; nf < 8; nf++) {
                int row = m0 + warp_m * 64 + mf * 16 + gr;
                int col = n0 + warp_n * 64 + nf * 8 + q * 2;
                *reinterpret_cast<float2*>(C + (size_t)row * ldw + col) =
                    make_float2(acc[mf][nf][0], acc[mf][nf][1]);
                *reinterpret_cast<float2*>(C + (size_t)(row + 8) * ldw + col) =
                    make_float2(acc[mf][nf][2], acc[mf][nf][3]);
            }
        // ---- row softmax partials (per-thread over its 16 cols, then q-lanes, then warp_n) ----
        float rm[8], rs[8];
#pragma unroll
        for (int mf = 0; mf < 4; mf++) {
            float ma = -1e30f, mb = -1e30f;
#pragma unroll
            for (int nf = 0; nf < 8; nf++) {
                ma = fmaxf(ma, fmaxf(acc[mf][nf][0], acc[mf][nf][1]));
                mb = fmaxf(mb, fmaxf(acc[mf][nf][2], acc[mf][nf][3]));
            }
            float sa = 0.f, sb = 0.f;
#pragma unroll
            for (int nf = 0; nf < 8; nf++) {
                sa += __expf(acc[mf][nf][0] - ma) + __expf(acc[mf][nf][1] - ma);
                sb += __expf(acc[mf][nf][2] - mb) + __expf(acc[mf][nf][3] - mb);
            }
            rm[2 * mf] = ma;  rs[2 * mf] = sa;
            rm[2 * mf + 1] = mb;  rs[2 * mf + 1] = sb;
        }
#pragma unroll
        for (int o = 1; o < 4; o <<= 1)
#pragma unroll
            for (int k = 0; k < 8; k++) {
                float mo = __shfl_xor_sync(0xffffffffu, rm[k], o);
                float so = __shfl_xor_sync(0xffffffffu, rs[k], o);
                msmerge(rm[k], rs[k], mo, so);
            }
        // ---- col softmax partials (per-thread over its 8 rows, then gr-lanes, then warp_m) ----
        float cm[16], cs[16];
#pragma unroll
        for (int nf = 0; nf < 8; nf++)
#pragma unroll
            for (int b = 0; b < 2; b++) {
                int i = nf * 2 + b;
                float mv = -1e30f;
#pragma unroll
                for (int mf = 0; mf < 4; mf++)
                    mv = fmaxf(mv, fmaxf(acc[mf][nf][b], acc[mf][nf][b + 2]));
                float sv = 0.f;
#pragma unroll
                for (int mf = 0; mf < 4; mf++)
                    sv += __expf(acc[mf][nf][b] - mv) + __expf(acc[mf][nf][b + 2] - mv);
                cm[i] = mv;  cs[i] = sv;
            }
#pragma unroll
        for (int o = 4; o < 32; o <<= 1)
#pragma unroll
            for (int k = 0; k < 16; k++) {
                float mo = __shfl_xor_sync(0xffffffffu, cm[k], o);
                float so = __shfl_xor_sync(0xffffffffu, cs[k], o);
                msmerge(cm[k], cs[k], mo, so);
            }
        // ---- smem cross-warp reduction ----
        float* rowm  = reinterpret_cast<float*>(smem);    // [128][4]
        float* rows_ = rowm + 512;                        // [128][4]
        float* colm  = rows_ + 512;                       // [2][256]
        float* cols_ = colm + 512;                        // [2][256]
        if (q == 0) {
#pragma unroll
            for (int mf = 0; mf < 4; mf++) {
                int lr = warp_m * 64 + mf * 16 + gr;
                rowm [lr * 4 + warp_n] = rm[2 * mf];
                rows_[lr * 4 + warp_n] = rs[2 * mf];
                rowm [(lr + 8) * 4 + warp_n] = rm[2 * mf + 1];
                rows_[(lr + 8) * 4 + warp_n] = rs[2 * mf + 1];
            }
        }
        if (lane < 4) {
#pragma unroll
            for (int nf = 0; nf < 8; nf++)
#pragma unroll
                for (int b = 0; b < 2; b++) {
                    int cc = warp_n * 64 + nf * 8 + lane * 2 + b;
                    colm [warp_m * 256 + cc] = cm[nf * 2 + b];
                    cols_[warp_m * 256 + cc] = cs[nf * 2 + b];
                }
        }
        __syncthreads();
        if (tid < 128) {
            float M = rowm[tid * 4], S = rows_[tid * 4];
#pragma unroll
            for (int w = 1; w < 4; w++) msmerge(M, S, rowm[tid * 4 + w], rows_[tid * 4 + w]);
            rpm[(size_t)(m0 + tid) * 32 + blockIdx.x] = M;
            rps[(size_t)(m0 + tid) * 32 + blockIdx.x] = S;
        }
        {
            float M = colm[tid], S = cols_[tid];
            msmerge(M, S, colm[256 + tid], cols_[256 + tid]);
            cpm[(size_t)(n0 + tid) * 64 + blockIdx.y] = M;
            cps[(size_t)(n0 + tid) * 64 + blockIdx.y] = S;
        }
    } else if (EPI == 1) {
        float csum[8][2];
#pragma unroll
        for (int nf = 0; nf < 8; nf++) { csum[nf][0] = 0.f; csum[nf][1] = 0.f; }
#pragma unroll
        for (int mf = 0; mf < 4; mf++)
#pragma unroll
            for (int nf = 0; nf < 8; nf++) {
                int row = m0 + warp_m * 64 + mf * 16 + gr;
                int col = warp_n * 64 + nf * 8 + q * 2;
                float v0 = acc[mf][nf][0], v1 = acc[mf][nf][1];
                float v2 = acc[mf][nf][2], v3 = acc[mf][nf][3];
                size_t o0 = (size_t)row * ldw + n0 + col;
                size_t o1 = (size_t)(row + 8) * ldw + n0 + col;
                *reinterpret_cast<__half2*>(OutH + o0) = __floats2half2_rn(v0, v1);
                *reinterpret_cast<__half2*>(OutH + o1) = __floats2half2_rn(v2, v3);
                csum[nf][0] += v0 + v2;
                csum[nf][1] += v1 + v3;
            }
#pragma unroll
        for (int o = 4; o < 32; o <<= 1)
#pragma unroll
            for (int nf = 0; nf < 8; nf++) {
                csum[nf][0] += __shfl_xor_sync(0xffffffffu, csum[nf][0], o);
                csum[nf][1] += __shfl_xor_sync(0xffffffffu, csum[nf][1], o);
            }
        __syncthreads();
        float* red = reinterpret_cast<float*>(smem);   // [2][256]
        if (lane < 4) {
#pragma unroll
            for (int nf = 0; nf < 8; nf++) {
                red[warp_m * 256 + warp_n * 64 + nf * 8 + lane * 2]     = csum[nf][0];
                red[warp_m * 256 + warp_n * 64 + nf * 8 + lane * 2 + 1] = csum[nf][1];
            }
        }
        __syncthreads();
        cpart[(size_t)blockIdx.y * DD + n0 + tid] = red[tid] + red[256 + tid];
    } else {
        float rsum[8];
#pragma unroll
        for (int k = 0; k < 8; k++) rsum[k] = 0.f;
#pragma unroll
        for (int mf = 0; mf < 4; mf++) {
            int row = m0 + warp_m * 64 + mf * 16 + gr;
            float bj0 = (row < Mvalid)     ? bias[row]     : 0.f;
            float bj1 = (row + 8 < Mvalid) ? bias[row + 8] : 0.f;
#pragma unroll
            for (int nf = 0; nf < 8; nf++) {
                rsum[mf * 2]     += tanhf(acc[mf][nf][0] + bj0) + tanhf(acc[mf][nf][1] + bj0);
                rsum[mf * 2 + 1] += tanhf(acc[mf][nf][2] + bj1) + tanhf(acc[mf][nf][3] + bj1);
            }
        }
#pragma unroll
        for (int o = 1; o < 4; o <<= 1)
#pragma unroll
            for (int k = 0; k < 8; k++) rsum[k] += __shfl_xor_sync(0xffffffffu, rsum[k], o);
        __syncthreads();
        float* red = reinterpret_cast<float*>(smem);   // [128][4]
        if (q == 0) {
#pragma unroll
            for (int mf = 0; mf < 4; mf++) {
                int lr = warp_m * 64 + mf * 16 + gr;
                red[lr * 4 + warp_n]       = rsum[mf * 2];
                red[(lr + 8) * 4 + warp_n] = rsum[mf * 2 + 1];
            }
        }
        __syncthreads();
        if (tid < 128) {
            float s = red[tid * 4] + red[tid * 4 + 1] + red[tid * 4 + 2] + red[tid * 4 + 3];
            int f = m0 + tid;
            if (f < Mvalid) tpart[(size_t)f * gridDim.x + blockIdx.x] = s;
        }
    }
}

// ======================= merge softmax stat partials =======================
__global__ void stats_merge_kernel()
{
    int g = blockIdx.x * 8 + (threadIdx.x >> 5);
    int lane = threadIdx.x & 31;
    if (g < N1V) {
        float m = g_rpm[(size_t)g * 32 + lane];
        float s = g_rps[(size_t)g * 32 + lane];
#pragma unroll
        for (int o = 16; o; o >>= 1) {
            float mo = __shfl_xor_sync(0xffffffffu, m, o);
            float so = __shfl_xor_sync(0xffffffffu, s, o);
            msmerge(m, s, mo, so);
        }
        if (lane == 0) { g_rmax[g] = m; g_rinv[g] = 1.0f / s; }
    } else {
        int c = g - N1V;
        float m = g_cpm[(size_t)c * 64 + lane];
        float s = g_cps[(size_t)c * 64 + lane];
        msmerge(m, s, g_cpm[(size_t)c * 64 + 32 + lane], g_cps[(size_t)c * 64 + 32 + lane]);
#pragma unroll
        for (int o = 16; o; o >>= 1) {
            float mo = __shfl_xor_sync(0xffffffffu, m, o);
            float so = __shfl_xor_sync(0xffffffffu, s, o);
            msmerge(m, s, mo, so);
        }
        if (lane == 0) { g_cmax[c] = m; g_cinv[c] = 1.0f / s; }
    }
}

// ======================= prep: transpose + hi/lo split =======================
__global__ void tsplit_kernel(const float* __restrict__ src,
                              __half* __restrict__ dh, __half* __restrict__ dl,
                              __half* __restrict__ dth,
                              int R, int C)
{
    __shared__ float t[32][33];
    int tx = threadIdx.x & 31, ty = threadIdx.x >> 5;
    int x = blockIdx.x * 32 + tx;
    int yb = blockIdx.y * 32;
#pragma unroll
    for (int r = 0; r < 4; r++) {
        int row = yb + ty + r * 8;
        float v = src[(size_t)row * C + x];
        __half h = __float2half_rn(v);
        dh[(size_t)row * C + x] = h;
        dl[(size_t)row * C + x] = __float2half_rn(v - __half2float(h));
        t[ty + r * 8][tx] = v;
    }
    __syncthreads();
    int r_ = yb + tx;
#pragma unroll
    for (int r = 0; r < 4; r++) {
        int c_ = blockIdx.x * 32 + ty + r * 8;
        dth[(size_t)c_ * R + r_] = __float2half_rn(t[tx][ty + r * 8]);
    }
}

__global__ void wsplit_kernel(const float* __restrict__ src,
                              __half* __restrict__ dh,
                              int R, int C, int Rpad)
{
    int idx = blockIdx.x * 256 + threadIdx.x;
    if (idx >= Rpad * C) return;
    int r = idx / C;
    float v = (r < R) ? src[idx] : 0.f;
    dh[idx] = __float2half_rn(v);
}

// alpha2 -> g_a2h fp16; alpha1^T -> g_a1th fp16
__global__ void alpha_kernel()
{
    __shared__ float t[32][33];
    int tx = threadIdx.x & 31, ty = threadIdx.x >> 5;
    int i0 = blockIdx.y * 32, j0 = blockIdx.x * 32;
    int j = j0 + tx;
    float cm = g_cmax[j], ci = g_cinv[j];
#pragma unroll
    for (int r = 0; r < 4; r++) {
        int i = i0 + ty + r * 8;
        size_t off = (size_t)i * N2V + j;
        float v = g_raw[off];
        g_a2h[off] = __float2half_rn(__expf(v - g_rmax[i]) * g_rinv[i]);
        t[ty + r * 8][tx] = __expf(v - cm) * ci;
    }
    __syncthreads();
    int xo = i0 + tx;
#pragma unroll
    for (int r = 0; r < 4; r++) {
        int jr = j0 + ty + r * 8;
        g_a1th[(size_t)jr * N1V + xo] = __float2half_rn(t[tx][ty + r * 8]);
    }
}

// ======================= reduce column partials =======================
__global__ void sumv_kernel()
{
    int i = blockIdx.x * 256 + threadIdx.x;
    if (i < DD) {
        float s = 0.f;
        for (int w = 0; w < 64; w++) s += g_cpart1[w * DD + i];
        g_sumv1[i] = s;
    } else if (i < 2 * DD) {
        int c = i - DD;
        float s = 0.f;
        for (int w = 0; w < 64; w++) s += g_cpart2[w * DD + c];
        g_sumv2[c] = s;
    }
}

// ======================= finalize =======================
__global__ void finalize_kernel(const float* __restrict__ Wf1, const float* __restrict__ bf1,
                                const float* __restrict__ Wf2, const float* __restrict__ bf2,
                                float* __restrict__ out)
{
    int g = blockIdx.x * 8 + (threadIdx.x >> 5);
    int lane = threadIdx.x & 31;
    const float inv = 1.0f / 8192.0f;
    if (g < FF) {
        const float* w = Wf1 + (size_t)g * DD;
        float d = 0.f;
        for (int l = lane; l < DD; l += 32) d += w[l] * g_sumv2[l];
#pragma unroll
        for (int o = 16; o; o >>= 1) d += __shfl_xor_sync(0xffffffffu, d, o);
        if (lane == 0) {
            float filt = 1.0f / (1.0f + __expf(-(d * inv + bf1[g])));
            float t = 0.f;
#pragma unroll
            for (int b = 0; b < 32; b++) t += g_tpart1[g * 32 + b];
            out[g] = t * inv * filt;
        }
    } else if (g < 2 * FF) {
        int f = g - FF;
        const float* w = Wf2 + (size_t)f * DD;
        float d = 0.f;
        for (int l = lane; l < DD; l += 32) d += w[l] * g_sumv1[l];
#pragma unroll
        for (int o = 16; o; o >>= 1) d += __shfl_xor_sync(0xffffffffu, d, o);
        if (lane == 0) {
            float filt = 1.0f / (1.0f + __expf(-(d * inv + bf2[f])));
            float t = 0.f;
#pragma unroll
            for (int b = 0; b < 32; b++) t += g_tpart2[f * 32 + b];
            out[FF + f] = t * inv * filt;
        }
    }
}

// ======================= launch =======================
extern "C" void kernel_launch(void* const* d_in, const int* in_sizes, int n_in,
                              void* d_out, int out_size)
{
    const float* m1  = (const float*)d_in[0];
    const float* m2  = (const float*)d_in[1];
    const float* Wf1 = (const float*)d_in[2];
    const float* bf1 = (const float*)d_in[3];
    const float* Wf2 = (const float*)d_in[4];
    const float* bf2 = (const float*)d_in[5];
    const float* W1  = (const float*)d_in[6];
    const float* b1  = (const float*)d_in[7];
    const float* W2  = (const float*)d_in[8];
    const float* b2  = (const float*)d_in[9];
    float* out = (float*)d_out;

    float *raw, *cpart1, *cpart2, *tpart1, *tpart2, *rpm, *rps, *cpm, *cps;
    __half *a2h, *a1th, *m1h, *m1l, *m2h, *m2l, *m1th, *m2th;
    __half *att1h, *att2h, *w1h, *w2h;
    cudaGetSymbolAddress((void**)&raw,   g_raw);
    cudaGetSymbolAddress((void**)&a2h,   g_a2h);
    cudaGetSymbolAddress((void**)&a1th,  g_a1th);
    cudaGetSymbolAddress((void**)&m1h,   g_m1h);
    cudaGetSymbolAddress((void**)&m1l,   g_m1l);
    cudaGetSymbolAddress((void**)&m2h,   g_m2h);
    cudaGetSymbolAddress((void**)&m2l,   g_m2l);
    cudaGetSymbolAddress((void**)&m1th,  g_m1th);
    cudaGetSymbolAddress((void**)&m2th,  g_m2th);
    cudaGetSymbolAddress((void**)&att1h, g_att1h);
    cudaGetSymbolAddress((void**)&att2h, g_att2h);
    cudaGetSymbolAddress((void**)&w1h,   g_w1h);
    cudaGetSymbolAddress((void**)&w2h,   g_w2h);
    cudaGetSymbolAddress((void**)&cpart1, g_cpart1);
    cudaGetSymbolAddress((void**)&cpart2, g_cpart2);
    cudaGetSymbolAddress((void**)&tpart1, g_tpart1);
    cudaGetSymbolAddress((void**)&tpart2, g_tpart2);
    cudaGetSymbolAddress((void**)&rpm, g_rpm);
    cudaGetSymbolAddress((void**)&rps, g_rps);
    cudaGetSymbolAddress((void**)&cpm, g_cpm);
    cudaGetSymbolAddress((void**)&cps, g_cps);

    cudaFuncSetAttribute(hgemm<2, 2, 0>, cudaFuncAttributeMaxDynamicSharedMemorySize, 184320);
    cudaFuncSetAttribute(hgemm<1, 1, 1>, cudaFuncAttributeMaxDynamicSharedMemorySize, 92160);
    cudaFuncSetAttribute(hgemm<1, 1, 2>, cudaFuncAttributeMaxDynamicSharedMemorySize, 92160);

    // 0) prep: split inputs
    tsplit_kernel<<<dim3(DD / 32, N1V / 32), 256>>>(m1, m1h, m1l, m1th, N1V, DD);
    tsplit_kernel<<<dim3(DD / 32, N2V / 32), 256>>>(m2, m2h, m2l, m2th, N2V, DD);
    wsplit_kernel<<<(FPAD * DD + 255) / 256, 256>>>(W1, w1h, FF, DD, FPAD);
    wsplit_kernel<<<(FPAD * DD + 255) / 256, 256>>>(W2, w2h, FF, DD, FPAD);

    // 1) raw = m1 @ m2^T, K=1024, 3-term, fused softmax stat partials
    hgemm<2, 2, 0><<<dim3(N2V / 256, N1V / 128), 256, 184320>>>(
        m1h, m1l, m2h, m2l, raw, nullptr, nullptr, N2V, DD, DD / 32, N1V,
        nullptr, nullptr, rpm, rps, cpm, cps);

    // 2) merge stat partials, materialize alphas (fp16)
    stats_merge_kernel<<<(N1V + N2V) / 8, 256>>>();
    alpha_kernel<<<dim3(N2V / 32, N1V / 32), 256>>>();

    // 3) attended_m2 = alpha2 @ m2, K=8192, 1-term, fused colsum + fp16 out
    hgemm<1, 1, 1><<<dim3(DD / 256, N1V / 128), 256, 92160>>>(
        a2h, nullptr, m2th, nullptr, nullptr, att2h, cpart2, DD, N2V, N2V / 32, N1V,
        nullptr, nullptr, nullptr, nullptr, nullptr, nullptr);

    // 4) attended_m1 = alpha1 @ m1, K=8192, 1-term
    hgemm<1, 1, 1><<<dim3(DD / 256, N2V / 128), 256, 92160>>>(
        a1th, nullptr, m1th, nullptr, nullptr, att1h, cpart1, DD, N1V, N1V / 32, N2V,
        nullptr, nullptr, nullptr, nullptr, nullptr, nullptr);

    // 5) reduce column partials
    sumv_kernel<<<8, 256>>>();

    // 6) transform: [F x N] = W @ att^T, 1-term, fused tanh+rowsum
    hgemm<1, 1, 2><<<dim3(N2V / 256, FPAD / 128), 256, 92160>>>(
        w1h, nullptr, att1h, nullptr, nullptr, nullptr, nullptr, 0, DD, DD / 32, FF,
        b1, tpart1, nullptr, nullptr, nullptr, nullptr);
    hgemm<1, 1, 2><<<dim3(N1V / 256, FPAD / 128), 256, 92160>>>(
        w2h, nullptr, att2h, nullptr, nullptr, nullptr, nullptr, 0, DD, DD / 32, FF,
        b2, tpart2, nullptr, nullptr, nullptr, nullptr);

    // 7) filters + outputs
    finalize_kernel<<<200, 256>>>(Wf1, bf1, Wf2, bf2, out);
}

// round 9
// speedup vs baseline: 4.3671x; 1.0438x over previous
#include <cuda_runtime.h>
#include <cuda_fp16.h>
#include <math.h>
#include <stdint.h>
#include <stddef.h>

#define N1V 8192
#define N2V 8192
#define DD  1024
#define FF  800
#define FPAD 896
#define SCAP 512
#define STHR 20.0f

// ======================= scratch (device globals) =======================
__device__ float  g_raw [(size_t)N1V * N2V];    // raw logits fp32
__device__ __half g_m1h[(size_t)N1V * DD], g_m1l[(size_t)N1V * DD];
__device__ __half g_m2h[(size_t)N2V * DD], g_m2l[(size_t)N2V * DD];
__device__ __half g_att1h[(size_t)N2V * DD];
__device__ __half g_att2h[(size_t)N1V * DD];
__device__ __half g_w1h[FPAD * DD];
__device__ __half g_w2h[FPAD * DD];
__device__ float g_rmax[N1V], g_rinv[N1V];
__device__ float g_cmax[N2V], g_cinv[N2V];
__device__ float g_rpm[(size_t)N1V * 32], g_rps[(size_t)N1V * 32];   // row stat partials
__device__ float g_cpm[(size_t)N2V * 64], g_cps[(size_t)N2V * 64];   // col stat partials
__device__ int   g_sel2_idx[(size_t)N1V * SCAP];   // row-softmax (alpha2) selections
__device__ float g_sel2_w  [(size_t)N1V * SCAP];
__device__ int   g_sel2_cnt[N1V];
__device__ int   g_sel1_idx[(size_t)N2V * SCAP];   // col-softmax (alpha1) selections
__device__ float g_sel1_w  [(size_t)N2V * SCAP];
__device__ int   g_sel1_cnt[N2V];
__device__ float g_sumv1[DD], g_sumv2[DD];
__device__ float g_tpart1[FPAD * 32], g_tpart2[FPAD * 32];

// ======================= asm helpers =======================
static __device__ __forceinline__ uint32_t smem_u32(const void* p) {
    uint32_t a;
    asm("{ .reg .u64 t; cvta.to.shared.u64 t, %1; cvt.u32.u64 %0, t; }" : "=r"(a) : "l"(p));
    return a;
}
static __device__ __forceinline__ uint64_t gaddr(const void* p) {
    uint64_t a;
    asm("cvta.to.global.u64 %0, %1;" : "=l"(a) : "l"(p));
    return a;
}
static __device__ __forceinline__ void cpa16(uint32_t dst, uint64_t src) {
    asm volatile("cp.async.cg.shared.global [%0], [%1], 16;" :: "r"(dst), "l"(src));
}
static __device__ __forceinline__ void ldsm_x4(uint32_t& r0, uint32_t& r1, uint32_t& r2, uint32_t& r3, uint32_t addr) {
    asm volatile("ldmatrix.sync.aligned.m8n8.x4.shared.b16 {%0,%1,%2,%3}, [%4];"
                 : "=r"(r0), "=r"(r1), "=r"(r2), "=r"(r3) : "r"(addr));
}
static __device__ __forceinline__ void mma16816(float* d, const uint32_t* a, uint32_t b0, uint32_t b1) {
    asm volatile("mma.sync.aligned.m16n8k16.row.col.f32.f16.f16.f32 "
                 "{%0,%1,%2,%3}, {%4,%5,%6,%7}, {%8,%9}, {%0,%1,%2,%3};"
                 : "+f"(d[0]), "+f"(d[1]), "+f"(d[2]), "+f"(d[3])
                 : "r"(a[0]), "r"(a[1]), "r"(a[2]), "r"(a[3]), "r"(b0), "r"(b1));
}
static __device__ __forceinline__ void msmerge(float& m, float& s, float mo, float so) {
    float mn = fmaxf(m, mo);
    s = s * __expf(m - mn) + so * __expf(mo - mn);
    m = mn;
}

// ======================= HMMA GEMM, 128x256 block, 64x64 warp tiles =======================
// C[M,N] = sum_k A[m,k]*B[n,k]; fp16 pre-split operands, k-contig, K%32==0.
// Terms: Ah*Bh always; + Ah*Bl if BT==2; + Al*Bh if AT==2.
// EPI 0: store C fp32 (pitch ldw) + row/col softmax stat partials.
// EPI 2: tanh(acc + bias[m]) row-summed over n-tile -> tpart[m*gridDim.x + bx], m < Mvalid.
template<int AT, int BT, int EPI>
__global__ void __launch_bounds__(256, 1)
hgemm(const __half* __restrict__ Ah, const __half* __restrict__ Al,
      const __half* __restrict__ Bh, const __half* __restrict__ Bl,
      float* __restrict__ C, long ldw, int K, int NT, int Mvalid,
      const float* __restrict__ bias, float* __restrict__ tpart,
      float* __restrict__ rpm, float* __restrict__ rps,
      float* __restrict__ cpm, float* __restrict__ cps)
{
    extern __shared__ char smem[];
    const uint32_t sbase = smem_u32(smem);
    const int OB    = AT * 10240;
    const int STGSZ = AT * 10240 + BT * 20480;
    const int tid = threadIdx.x, lane = tid & 31, wid = tid >> 5;
    const int warp_m = wid & 1;
    const int warp_n = wid >> 1;
    const int m0 = blockIdx.y * 128;
    const int n0 = blockIdx.x * 256;

    const int arow = lane & 15, acol = (lane >> 4) << 3;
    const int brow = (lane & 7) + ((lane & 16) >> 1);
    const int bcol = lane & 8;

    const uint64_t gAh = gaddr(Ah);
    const uint64_t gAl = (AT == 2) ? gaddr(Al) : 0ull;
    const uint64_t gBh = gaddr(Bh);
    const uint64_t gBl = (BT == 2) ? gaddr(Bl) : 0ull;

    float acc[4][8][4];
#pragma unroll
    for (int i = 0; i < 4; i++)
#pragma unroll
        for (int j = 0; j < 8; j++)
#pragma unroll
            for (int k = 0; k < 4; k++) acc[i][j][k] = 0.f;

    auto load_stage = [&](int kt, int bufi) {
        const int k0 = kt * 32;
        uint32_t sb = sbase + bufi * STGSZ;
#pragma unroll
        for (int i = 0; i < 2; i++) {
            int idx = tid + i * 256;
            int r = idx >> 2, c = (idx & 3) << 3;
            uint32_t d = sb + (uint32_t)(r * 40 + c) * 2;
            uint64_t ao = ((uint64_t)(m0 + r) * K + k0 + c) * 2;
            cpa16(d, gAh + ao);
            if (AT == 2) cpa16(d + 10240, gAl + ao);
        }
#pragma unroll
        for (int i = 0; i < 4; i++) {
            int idx = tid + i * 256;
            int r = idx >> 2, c = (idx & 3) << 3;
            uint32_t d = sb + OB + (uint32_t)(r * 40 + c) * 2;
            uint64_t bo = ((uint64_t)(n0 + r) * K + k0 + c) * 2;
            cpa16(d, gBh + bo);
            if (BT == 2) cpa16(d + 20480, gBl + bo);
        }
        asm volatile("cp.async.commit_group;" ::: "memory");
    };

    load_stage(0, 0);
    load_stage(1, 1);
    for (int t = 0; t < NT; t++) {
        if (t + 2 < NT) {
            load_stage(t + 2, (t + 2) % 3);
            asm volatile("cp.async.wait_group 2;" ::: "memory");
        } else if (t + 1 < NT) {
            asm volatile("cp.async.wait_group 1;" ::: "memory");
        } else {
            asm volatile("cp.async.wait_group 0;" ::: "memory");
        }
        __syncthreads();
        uint32_t sa = sbase + (t % 3) * STGSZ;
#pragma unroll
        for (int ks = 0; ks < 2; ks++) {
            uint32_t ah[4][4], al[4][4];
#pragma unroll
            for (int mf = 0; mf < 4; mf++) {
                uint32_t addr = sa + (uint32_t)((warp_m * 64 + mf * 16 + arow) * 40 + ks * 16 + acol) * 2;
                ldsm_x4(ah[mf][0], ah[mf][1], ah[mf][2], ah[mf][3], addr);
                if (AT == 2)
                    ldsm_x4(al[mf][0], al[mf][1], al[mf][2], al[mf][3], addr + 10240);
            }
            uint32_t bh[4][4], bl[4][4];
#pragma unroll
            for (int nf2 = 0; nf2 < 4; nf2++) {
                uint32_t addr = sa + OB + (uint32_t)((warp_n * 64 + nf2 * 16 + brow) * 40 + ks * 16 + bcol) * 2;
                ldsm_x4(bh[nf2][0], bh[nf2][1], bh[nf2][2], bh[nf2][3], addr);
                if (BT == 2)
                    ldsm_x4(bl[nf2][0], bl[nf2][1], bl[nf2][2], bl[nf2][3], addr + 20480);
            }
#pragma unroll
            for (int mf = 0; mf < 4; mf++)
#pragma unroll
                for (int nf = 0; nf < 8; nf++) {
                    int nf2 = nf >> 1, o = (nf & 1) * 2;
                    mma16816(acc[mf][nf], ah[mf], bh[nf2][o], bh[nf2][o + 1]);
                    if (BT == 2)
                        mma16816(acc[mf][nf], ah[mf], bl[nf2][o], bl[nf2][o + 1]);
                    if (AT == 2)
                        mma16816(acc[mf][nf], al[mf], bh[nf2][o], bh[nf2][o + 1]);
                }
        }
        __syncthreads();
    }

    const int gr = lane >> 2, q = lane & 3;
    if (EPI == 0) {
#pragma unroll
        for (int mf = 0; mf < 4; mf++)
#pragma unroll
            for (int nf = 0; nf < 8; nf++) {
                int row = m0 + warp_m * 64 + mf * 16 + gr;
                int col = n0 + warp_n * 64 + nf * 8 + q * 2;
                *reinterpret_cast<float2*>(C + (size_t)row * ldw + col) =
                    make_float2(acc[mf][nf][0], acc[mf][nf][1]);
                *reinterpret_cast<float2*>(C + (size_t)(row + 8) * ldw + col) =
                    make_float2(acc[mf][nf][2], acc[mf][nf][3]);
            }
        float rm[8], rs[8];
#pragma unroll
        for (int mf = 0; mf < 4; mf++) {
            float ma = -1e30f, mb = -1e30f;
#pragma unroll
            for (int nf = 0; nf < 8; nf++) {
                ma = fmaxf(ma, fmaxf(acc[mf][nf][0], acc[mf][nf][1]));
                mb = fmaxf(mb, fmaxf(acc[mf][nf][2], acc[mf][nf][3]));
            }
            float sa = 0.f, sb = 0.f;
#pragma unroll
            for (int nf = 0; nf < 8; nf++) {
                sa += __expf(acc[mf][nf][0] - ma) + __expf(acc[mf][nf][1] - ma);
                sb += __expf(acc[mf][nf][2] - mb) + __expf(acc[mf][nf][3] - mb);
            }
            rm[2 * mf] = ma;  rs[2 * mf] = sa;
            rm[2 * mf + 1] = mb;  rs[2 * mf + 1] = sb;
        }
#pragma unroll
        for (int o = 1; o < 4; o <<= 1)
#pragma unroll
            for (int k = 0; k < 8; k++) {
                float mo = __shfl_xor_sync(0xffffffffu, rm[k], o);
                float so = __shfl_xor_sync(0xffffffffu, rs[k], o);
                msmerge(rm[k], rs[k], mo, so);
            }
        float cm[16], cs[16];
#pragma unroll
        for (int nf = 0; nf < 8; nf++)
#pragma unroll
            for (int b = 0; b < 2; b++) {
                int i = nf * 2 + b;
                float mv = -1e30f;
#pragma unroll
                for (int mf = 0; mf < 4; mf++)
                    mv = fmaxf(mv, fmaxf(acc[mf][nf][b], acc[mf][nf][b + 2]));
                float sv = 0.f;
#pragma unroll
                for (int mf = 0; mf < 4; mf++)
                    sv += __expf(acc[mf][nf][b] - mv) + __expf(acc[mf][nf][b + 2] - mv);
                cm[i] = mv;  cs[i] = sv;
            }
#pragma unroll
        for (int o = 4; o < 32; o <<= 1)
#pragma unroll
            for (int k = 0; k < 16; k++) {
                float mo = __shfl_xor_sync(0xffffffffu, cm[k], o);
                float so = __shfl_xor_sync(0xffffffffu, cs[k], o);
                msmerge(cm[k], cs[k], mo, so);
            }
        float* rowm  = reinterpret_cast<float*>(smem);
        float* rows_ = rowm + 512;
        float* colm  = rows_ + 512;
        float* cols_ = colm + 512;
        if (q == 0) {
#pragma unroll
            for (int mf = 0; mf < 4; mf++) {
                int lr = warp_m * 64 + mf * 16 + gr;
                rowm [lr * 4 + warp_n] = rm[2 * mf];
                rows_[lr * 4 + warp_n] = rs[2 * mf];
                rowm [(lr + 8) * 4 + warp_n] = rm[2 * mf + 1];
                rows_[(lr + 8) * 4 + warp_n] = rs[2 * mf + 1];
            }
        }
        if (lane < 4) {
#pragma unroll
            for (int nf = 0; nf < 8; nf++)
#pragma unroll
                for (int b = 0; b < 2; b++) {
                    int cc = warp_n * 64 + nf * 8 + lane * 2 + b;
                    colm [warp_m * 256 + cc] = cm[nf * 2 + b];
                    cols_[warp_m * 256 + cc] = cs[nf * 2 + b];
                }
        }
        __syncthreads();
        if (tid < 128) {
            float M = rowm[tid * 4], S = rows_[tid * 4];
#pragma unroll
            for (int w = 1; w < 4; w++) msmerge(M, S, rowm[tid * 4 + w], rows_[tid * 4 + w]);
            rpm[(size_t)(m0 + tid) * 32 + blockIdx.x] = M;
            rps[(size_t)(m0 + tid) * 32 + blockIdx.x] = S;
        }
        {
            float M = colm[tid], S = cols_[tid];
            msmerge(M, S, colm[256 + tid], cols_[256 + tid]);
            cpm[(size_t)(n0 + tid) * 64 + blockIdx.y] = M;
            cps[(size_t)(n0 + tid) * 64 + blockIdx.y] = S;
        }
    } else {
        float rsum[8];
#pragma unroll
        for (int k = 0; k < 8; k++) rsum[k] = 0.f;
#pragma unroll
        for (int mf = 0; mf < 4; mf++) {
            int row = m0 + warp_m * 64 + mf * 16 + gr;
            float bj0 = (row < Mvalid)     ? bias[row]     : 0.f;
            float bj1 = (row + 8 < Mvalid) ? bias[row + 8] : 0.f;
#pragma unroll
            for (int nf = 0; nf < 8; nf++) {
                rsum[mf * 2]     += tanhf(acc[mf][nf][0] + bj0) + tanhf(acc[mf][nf][1] + bj0);
                rsum[mf * 2 + 1] += tanhf(acc[mf][nf][2] + bj1) + tanhf(acc[mf][nf][3] + bj1);
            }
        }
#pragma unroll
        for (int o = 1; o < 4; o <<= 1)
#pragma unroll
            for (int k = 0; k < 8; k++) rsum[k] += __shfl_xor_sync(0xffffffffu, rsum[k], o);
        __syncthreads();
        float* red = reinterpret_cast<float*>(smem);
        if (q == 0) {
#pragma unroll
            for (int mf = 0; mf < 4; mf++) {
                int lr = warp_m * 64 + mf * 16 + gr;
                red[lr * 4 + warp_n]       = rsum[mf * 2];
                red[(lr + 8) * 4 + warp_n] = rsum[mf * 2 + 1];
            }
        }
        __syncthreads();
        if (tid < 128) {
            float s = red[tid * 4] + red[tid * 4 + 1] + red[tid * 4 + 2] + red[tid * 4 + 3];
            int f = m0 + tid;
            if (f < Mvalid) tpart[(size_t)f * gridDim.x + blockIdx.x] = s;
        }
    }
}

// ======================= merge softmax stat partials =======================
__global__ void stats_merge_kernel()
{
    int g = blockIdx.x * 8 + (threadIdx.x >> 5);
    int lane = threadIdx.x & 31;
    if (g < N1V) {
        float m = g_rpm[(size_t)g * 32 + lane];
        float s = g_rps[(size_t)g * 32 + lane];
#pragma unroll
        for (int o = 16; o; o >>= 1) {
            float mo = __shfl_xor_sync(0xffffffffu, m, o);
            float so = __shfl_xor_sync(0xffffffffu, s, o);
            msmerge(m, s, mo, so);
        }
        if (lane == 0) { g_rmax[g] = m; g_rinv[g] = 1.0f / s; }
    } else {
        int c = g - N1V;
        float m = g_cpm[(size_t)c * 64 + lane];
        float s = g_cps[(size_t)c * 64 + lane];
        msmerge(m, s, g_cpm[(size_t)c * 64 + 32 + lane], g_cps[(size_t)c * 64 + 32 + lane]);
#pragma unroll
        for (int o = 16; o; o >>= 1) {
            float mo = __shfl_xor_sync(0xffffffffu, m, o);
            float so = __shfl_xor_sync(0xffffffffu, s, o);
            msmerge(m, s, mo, so);
        }
        if (lane == 0) { g_cmax[c] = m; g_cinv[c] = 1.0f / s; }
    }
}

// ======================= selection: rows (alpha2) =======================
// one block per row; deterministic ordered compaction of j with raw[i][j] > rmax - THR
__global__ void select_rows_kernel()
{
    int row = blockIdx.x;
    int t = threadIdx.x, lane = t & 31, w = t >> 5;
    const float* r = g_raw + (size_t)row * N2V;
    float rm = g_rmax[row], ri = g_rinv[row];
    float thr = rm - STHR;
    int base = t * 32;
    int c = 0;
#pragma unroll 8
    for (int k = 0; k < 32; k++) c += (r[base + k] > thr) ? 1 : 0;
    int v = c;
#pragma unroll
    for (int o = 1; o < 32; o <<= 1) {
        int u = __shfl_up_sync(0xffffffffu, v, o);
        if (lane >= o) v += u;
    }
    __shared__ int wt[8];
    if (lane == 31) wt[w] = v;
    __syncthreads();
    int woff = 0;
#pragma unroll
    for (int s = 0; s < 8; s++) if (s < w) woff += wt[s];
    int off = woff + v - c;
    for (int k = 0; k < 32; k++) {
        float x = r[base + k];
        if (x > thr) {
            if (off < SCAP) {
                g_sel2_idx[(size_t)row * SCAP + off] = base + k;
                g_sel2_w  [(size_t)row * SCAP + off] = __expf(x - rm) * ri;
            }
            off++;
        }
    }
    if (t == 0) {
        int total = wt[0] + wt[1] + wt[2] + wt[3] + wt[4] + wt[5] + wt[6] + wt[7];
        g_sel1_cnt[0] += 0;  // no-op keep symmetric
        g_sel2_cnt[row] = total < SCAP ? total : SCAP;
    }
}

// ======================= selection: cols (alpha1) =======================
// block handles 32 columns; warp w scans rows [w*1024, (w+1)*1024)
__global__ void select_cols_kernel()
{
    int lane = threadIdx.x & 31, w = threadIdx.x >> 5;
    int col = blockIdx.x * 32 + lane;
    float cm = g_cmax[col], ci = g_cinv[col];
    float thr = cm - STHR;
    int r0 = w * 1024;
    int c = 0;
#pragma unroll 8
    for (int r = 0; r < 1024; r++)
        c += (g_raw[(size_t)(r0 + r) * N2V + col] > thr) ? 1 : 0;
    __shared__ int scnt[8][32];
    scnt[w][lane] = c;
    __syncthreads();
    int off = 0, total = 0;
#pragma unroll
    for (int s = 0; s < 8; s++) {
        if (s < w) off += scnt[s][lane];
        total += scnt[s][lane];
    }
    for (int r = 0; r < 1024; r++) {
        float x = g_raw[(size_t)(r0 + r) * N2V + col];
        if (x > thr) {
            if (off < SCAP) {
                g_sel1_idx[(size_t)col * SCAP + off] = r0 + r;
                g_sel1_w  [(size_t)col * SCAP + off] = __expf(x - cm) * ci;
            }
            off++;
        }
    }
    if (w == 0) g_sel1_cnt[col] = total < SCAP ? total : SCAP;
}

// ======================= gather: att[row] = sum_t w_t * src[idx_t] =======================
__global__ void gather_att_kernel(const int* __restrict__ cnt, const int* __restrict__ idx,
                                  const float* __restrict__ wgt, const float* __restrict__ src,
                                  __half* __restrict__ dst)
{
    int row = blockIdx.x;
    int t = threadIdx.x;
    int n = cnt[row];
    float a0 = 0.f, a1 = 0.f, a2 = 0.f, a3 = 0.f;
    for (int k = 0; k < n; k++) {
        int j = idx[(size_t)row * SCAP + k];
        float w = wgt[(size_t)row * SCAP + k];
        float4 v = *reinterpret_cast<const float4*>(src + (size_t)j * DD + t * 4);
        a0 += w * v.x; a1 += w * v.y; a2 += w * v.z; a3 += w * v.w;
    }
    __half2* d = reinterpret_cast<__half2*>(dst + (size_t)row * DD + t * 4);
    d[0] = __floats2half2_rn(a0, a1);
    d[1] = __floats2half2_rn(a2, a3);
}

// ======================= column sums of fp16 att -> sumv =======================
__global__ void colsum_kernel(const __half* __restrict__ att, float* __restrict__ sumv)
{
    int lane = threadIdx.x & 31, w = threadIdx.x >> 5;
    int col = blockIdx.x * 32 + lane;
    float s = 0.f;
#pragma unroll 8
    for (int r = 0; r < 1024; r++)
        s += __half2float(att[(size_t)(w * 1024 + r) * DD + col]);
    __shared__ float sh[8][33];
    sh[w][lane] = s;
    __syncthreads();
    if (threadIdx.x < 32) {
        float t = 0.f;
#pragma unroll
        for (int q = 0; q < 8; q++) t += sh[q][threadIdx.x];
        sumv[blockIdx.x * 32 + threadIdx.x] = t;
    }
}

// ======================= prep: hi/lo split (no transpose) =======================
__global__ void split_hl_kernel(const float* __restrict__ src,
                                __half* __restrict__ dh, __half* __restrict__ dl, int n4)
{
    int i = blockIdx.x * 256 + threadIdx.x;
    if (i >= n4) return;
    float4 v = reinterpret_cast<const float4*>(src)[i];
    __half2 h0 = __floats2half2_rn(v.x, v.y);
    __half2 h1 = __floats2half2_rn(v.z, v.w);
    float2 f0 = __half22float2(h0), f1 = __half22float2(h1);
    __half2 l0 = __floats2half2_rn(v.x - f0.x, v.y - f0.y);
    __half2 l1 = __floats2half2_rn(v.z - f1.x, v.w - f1.y);
    reinterpret_cast<__half2*>(dh)[i * 2]     = h0;
    reinterpret_cast<__half2*>(dh)[i * 2 + 1] = h1;
    reinterpret_cast<__half2*>(dl)[i * 2]     = l0;
    reinterpret_cast<__half2*>(dl)[i * 2 + 1] = l1;
}

__global__ void wsplit_kernel(const float* __restrict__ src,
                              __half* __restrict__ dh,
                              int R, int C, int Rpad)
{
    int idx = blockIdx.x * 256 + threadIdx.x;
    if (idx >= Rpad * C) return;
    int r = idx / C;
    float v = (r < R) ? src[idx] : 0.f;
    dh[idx] = __float2half_rn(v);
}

// ======================= finalize =======================
__global__ void finalize_kernel(const float* __restrict__ Wf1, const float* __restrict__ bf1,
                                const float* __restrict__ Wf2, const float* __restrict__ bf2,
                                float* __restrict__ out)
{
    int g = blockIdx.x * 8 + (threadIdx.x >> 5);
    int lane = threadIdx.x & 31;
    const float inv = 1.0f / 8192.0f;
    if (g < FF) {
        const float* w = Wf1 + (size_t)g * DD;
        float d = 0.f;
        for (int l = lane; l < DD; l += 32) d += w[l] * g_sumv2[l];
#pragma unroll
        for (int o = 16; o; o >>= 1) d += __shfl_xor_sync(0xffffffffu, d, o);
        if (lane == 0) {
            float filt = 1.0f / (1.0f + __expf(-(d * inv + bf1[g])));
            float t = 0.f;
#pragma unroll
            for (int b = 0; b < 32; b++) t += g_tpart1[g * 32 + b];
            out[g] = t * inv * filt;
        }
    } else if (g < 2 * FF) {
        int f = g - FF;
        const float* w = Wf2 + (size_t)f * DD;
        float d = 0.f;
        for (int l = lane; l < DD; l += 32) d += w[l] * g_sumv1[l];
#pragma unroll
        for (int o = 16; o; o >>= 1) d += __shfl_xor_sync(0xffffffffu, d, o);
        if (lane == 0) {
            float filt = 1.0f / (1.0f + __expf(-(d * inv + bf2[f])));
            float t = 0.f;
#pragma unroll
            for (int b = 0; b < 32; b++) t += g_tpart2[f * 32 + b];
            out[FF + f] = t * inv * filt;
        }
    }
}

// ======================= launch =======================
extern "C" void kernel_launch(void* const* d_in, const int* in_sizes, int n_in,
                              void* d_out, int out_size)
{
    const float* m1  = (const float*)d_in[0];
    const float* m2  = (const float*)d_in[1];
    const float* Wf1 = (const float*)d_in[2];
    const float* bf1 = (const float*)d_in[3];
    const float* Wf2 = (const float*)d_in[4];
    const float* bf2 = (const float*)d_in[5];
    const float* W1  = (const float*)d_in[6];
    const float* b1  = (const float*)d_in[7];
    const float* W2  = (const float*)d_in[8];
    const float* b2  = (const float*)d_in[9];
    float* out = (float*)d_out;

    float *raw, *tpart1, *tpart2, *rpm, *rps, *cpm, *cps, *sumv1, *sumv2;
    float *sel2w, *sel1w;
    int *sel2i, *sel2c, *sel1i, *sel1c;
    __half *m1h, *m1l, *m2h, *m2l, *att1h, *att2h, *w1h, *w2h;
    cudaGetSymbolAddress((void**)&raw,   g_raw);
    cudaGetSymbolAddress((void**)&m1h,   g_m1h);
    cudaGetSymbolAddress((void**)&m1l,   g_m1l);
    cudaGetSymbolAddress((void**)&m2h,   g_m2h);
    cudaGetSymbolAddress((void**)&m2l,   g_m2l);
    cudaGetSymbolAddress((void**)&att1h, g_att1h);
    cudaGetSymbolAddress((void**)&att2h, g_att2h);
    cudaGetSymbolAddress((void**)&w1h,   g_w1h);
    cudaGetSymbolAddress((void**)&w2h,   g_w2h);
    cudaGetSymbolAddress((void**)&tpart1, g_tpart1);
    cudaGetSymbolAddress((void**)&tpart2, g_tpart2);
    cudaGetSymbolAddress((void**)&rpm, g_rpm);
    cudaGetSymbolAddress((void**)&rps, g_rps);
    cudaGetSymbolAddress((void**)&cpm, g_cpm);
    cudaGetSymbolAddress((void**)&cps, g_cps);
    cudaGetSymbolAddress((void**)&sel2i, g_sel2_idx);
    cudaGetSymbolAddress((void**)&sel2w, g_sel2_w);
    cudaGetSymbolAddress((void**)&sel2c, g_sel2_cnt);
    cudaGetSymbolAddress((void**)&sel1i, g_sel1_idx);
    cudaGetSymbolAddress((void**)&sel1w, g_sel1_w);
    cudaGetSymbolAddress((void**)&sel1c, g_sel1_cnt);
    cudaGetSymbolAddress((void**)&sumv1, g_sumv1);
    cudaGetSymbolAddress((void**)&sumv2, g_sumv2);

    cudaFuncSetAttribute(hgemm<2, 2, 0>, cudaFuncAttributeMaxDynamicSharedMemorySize, 184320);
    cudaFuncSetAttribute(hgemm<1, 1, 2>, cudaFuncAttributeMaxDynamicSharedMemorySize, 92160);

    // 0) prep: split inputs
    split_hl_kernel<<<(N1V * DD / 4 + 255) / 256, 256>>>(m1, m1h, m1l, N1V * DD / 4);
    split_hl_kernel<<<(N2V * DD / 4 + 255) / 256, 256>>>(m2, m2h, m2l, N2V * DD / 4);
    wsplit_kernel<<<(FPAD * DD + 255) / 256, 256>>>(W1, w1h, FF, DD, FPAD);
    wsplit_kernel<<<(FPAD * DD + 255) / 256, 256>>>(W2, w2h, FF, DD, FPAD);

    // 1) raw = m1 @ m2^T, K=1024, 3-term, fused softmax stat partials
    hgemm<2, 2, 0><<<dim3(N2V / 256, N1V / 128), 256, 184320>>>(
        m1h, m1l, m2h, m2l, raw, N2V, DD, DD / 32, N1V,
        nullptr, nullptr, rpm, rps, cpm, cps);

    // 2) merge stat partials
    stats_merge_kernel<<<(N1V + N2V) / 8, 256>>>();

    // 3) threshold selection (sparse alpha support)
    select_rows_kernel<<<N1V, 256>>>();
    select_cols_kernel<<<N2V / 32, 256>>>();

    // 4) gather attended matrices in fp32, store fp16
    gather_att_kernel<<<N1V, 256>>>(sel2c, sel2i, sel2w, m2, att2h);
    gather_att_kernel<<<N2V, 256>>>(sel1c, sel1i, sel1w, m1, att1h);

    // 5) column sums for the filter path
    colsum_kernel<<<DD / 32, 256>>>(att1h, sumv1);
    colsum_kernel<<<DD / 32, 256>>>(att2h, sumv2);

    // 6) transform: [F x N] = W @ att^T, 1-term, fused tanh+rowsum
    hgemm<1, 1, 2><<<dim3(N2V / 256, FPAD / 128), 256, 92160>>>(
        w1h, nullptr, att1h, nullptr, nullptr, 0, DD, DD / 32, FF,
        b1, tpart1, nullptr, nullptr, nullptr, nullptr);
    hgemm<1, 1, 2><<<dim3(N1V / 256, FPAD / 128), 256, 92160>>>(
        w2h, nullptr, att2h, nullptr, nullptr, 0, DD, DD / 32, FF,
        b2, tpart2, nullptr, nullptr, nullptr, nullptr);

    // 7) filters + outputs
    finalize_kernel<<<200, 256>>>(Wf1, bf1, Wf2, bf2, out);
}

// round 10
// speedup vs baseline: 7.7607x; 1.7771x over previous
#include <cuda_runtime.h>
#include <cuda_fp16.h>
#include <math.h>
#include <stdint.h>
#include <stddef.h>

#define N1V 8192
#define N2V 8192
#define DD  1024
#define FF  800
#define FPAD 896
#define SCAP 512
#define STHR 20.0f

// ======================= scratch (device globals) =======================
__device__ float  g_raw [(size_t)N1V * N2V];    // approx logits fp32 (1-term fp16 GEMM)
__device__ __half g_m1h[(size_t)N1V * DD];
__device__ __half g_m2h[(size_t)N2V * DD];
__device__ __half g_att1h[(size_t)N2V * DD];
__device__ __half g_att2h[(size_t)N1V * DD];
__device__ __half g_w1h[FPAD * DD];
__device__ __half g_w2h[FPAD * DD];
__device__ float g_rmax[N1V], g_rsum[N1V];
__device__ float g_cmax[N2V], g_csum[N2V];
__device__ float g_rpm[(size_t)N1V * 32], g_rps[(size_t)N1V * 32];   // row stat partials
__device__ float g_cpm[(size_t)N2V * 64], g_cps[(size_t)N2V * 64];   // col stat partials
__device__ int   g_sel2_idx[(size_t)N1V * SCAP];   // row-softmax (alpha2) selections
__device__ float g_sel2_w  [(size_t)N1V * SCAP];
__device__ int   g_sel2_cnt[N1V];
__device__ int   g_sel1_idx[(size_t)N2V * SCAP];   // col-softmax (alpha1) selections
__device__ float g_sel1_w  [(size_t)N2V * SCAP];
__device__ int   g_sel1_cnt[N2V];
__device__ float g_sumv1[DD], g_sumv2[DD];
__device__ float g_tpart1[FPAD * 32], g_tpart2[FPAD * 32];

// ======================= asm helpers =======================
static __device__ __forceinline__ uint32_t smem_u32(const void* p) {
    uint32_t a;
    asm("{ .reg .u64 t; cvta.to.shared.u64 t, %1; cvt.u32.u64 %0, t; }" : "=r"(a) : "l"(p));
    return a;
}
static __device__ __forceinline__ uint64_t gaddr(const void* p) {
    uint64_t a;
    asm("cvta.to.global.u64 %0, %1;" : "=l"(a) : "l"(p));
    return a;
}
static __device__ __forceinline__ void cpa16(uint32_t dst, uint64_t src) {
    asm volatile("cp.async.cg.shared.global [%0], [%1], 16;" :: "r"(dst), "l"(src));
}
static __device__ __forceinline__ void ldsm_x4(uint32_t& r0, uint32_t& r1, uint32_t& r2, uint32_t& r3, uint32_t addr) {
    asm volatile("ldmatrix.sync.aligned.m8n8.x4.shared.b16 {%0,%1,%2,%3}, [%4];"
                 : "=r"(r0), "=r"(r1), "=r"(r2), "=r"(r3) : "r"(addr));
}
static __device__ __forceinline__ void mma16816(float* d, const uint32_t* a, uint32_t b0, uint32_t b1) {
    asm volatile("mma.sync.aligned.m16n8k16.row.col.f32.f16.f16.f32 "
                 "{%0,%1,%2,%3}, {%4,%5,%6,%7}, {%8,%9}, {%0,%1,%2,%3};"
                 : "+f"(d[0]), "+f"(d[1]), "+f"(d[2]), "+f"(d[3])
                 : "r"(a[0]), "r"(a[1]), "r"(a[2]), "r"(a[3]), "r"(b0), "r"(b1));
}
static __device__ __forceinline__ void msmerge(float& m, float& s, float mo, float so) {
    float mn = fmaxf(m, mo);
    s = s * __expf(m - mn) + so * __expf(mo - mn);
    m = mn;
}

// ======================= HMMA GEMM, 128x256 block, 64x64 warp tiles =======================
// C[M,N] = sum_k A[m,k]*B[n,k]; fp16 operands, k-contig, K%32==0.
// Terms: Ah*Bh always; + Ah*Bl if BT==2; + Al*Bh if AT==2.
// EPI 0: store C fp32 (pitch ldw) + row/col softmax stat partials.
// EPI 2: tanh(acc + bias[m]) row-summed over n-tile -> tpart[m*gridDim.x + bx], m < Mvalid.
template<int AT, int BT, int EPI>
__global__ void __launch_bounds__(256, 1)
hgemm(const __half* __restrict__ Ah, const __half* __restrict__ Al,
      const __half* __restrict__ Bh, const __half* __restrict__ Bl,
      float* __restrict__ C, long ldw, int K, int NT, int Mvalid,
      const float* __restrict__ bias, float* __restrict__ tpart,
      float* __restrict__ rpm, float* __restrict__ rps,
      float* __restrict__ cpm, float* __restrict__ cps)
{
    extern __shared__ char smem[];
    const uint32_t sbase = smem_u32(smem);
    const int OB    = AT * 10240;
    const int STGSZ = AT * 10240 + BT * 20480;
    const int tid = threadIdx.x, lane = tid & 31, wid = tid >> 5;
    const int warp_m = wid & 1;
    const int warp_n = wid >> 1;
    const int m0 = blockIdx.y * 128;
    const int n0 = blockIdx.x * 256;

    const int arow = lane & 15, acol = (lane >> 4) << 3;
    const int brow = (lane & 7) + ((lane & 16) >> 1);
    const int bcol = lane & 8;

    const uint64_t gAh = gaddr(Ah);
    const uint64_t gAl = (AT == 2) ? gaddr(Al) : 0ull;
    const uint64_t gBh = gaddr(Bh);
    const uint64_t gBl = (BT == 2) ? gaddr(Bl) : 0ull;

    float acc[4][8][4];
#pragma unroll
    for (int i = 0; i < 4; i++)
#pragma unroll
        for (int j = 0; j < 8; j++)
#pragma unroll
            for (int k = 0; k < 4; k++) acc[i][j][k] = 0.f;

    auto load_stage = [&](int kt, int bufi) {
        const int k0 = kt * 32;
        uint32_t sb = sbase + bufi * STGSZ;
#pragma unroll
        for (int i = 0; i < 2; i++) {
            int idx = tid + i * 256;
            int r = idx >> 2, c = (idx & 3) << 3;
            uint32_t d = sb + (uint32_t)(r * 40 + c) * 2;
            uint64_t ao = ((uint64_t)(m0 + r) * K + k0 + c) * 2;
            cpa16(d, gAh + ao);
            if (AT == 2) cpa16(d + 10240, gAl + ao);
        }
#pragma unroll
        for (int i = 0; i < 4; i++) {
            int idx = tid + i * 256;
            int r = idx >> 2, c = (idx & 3) << 3;
            uint32_t d = sb + OB + (uint32_t)(r * 40 + c) * 2;
            uint64_t bo = ((uint64_t)(n0 + r) * K + k0 + c) * 2;
            cpa16(d, gBh + bo);
            if (BT == 2) cpa16(d + 20480, gBl + bo);
        }
        asm volatile("cp.async.commit_group;" ::: "memory");
    };

    load_stage(0, 0);
    load_stage(1, 1);
    for (int t = 0; t < NT; t++) {
        if (t + 2 < NT) {
            load_stage(t + 2, (t + 2) % 3);
            asm volatile("cp.async.wait_group 2;" ::: "memory");
        } else if (t + 1 < NT) {
            asm volatile("cp.async.wait_group 1;" ::: "memory");
        } else {
            asm volatile("cp.async.wait_group 0;" ::: "memory");
        }
        __syncthreads();
        uint32_t sa = sbase + (t % 3) * STGSZ;
#pragma unroll
        for (int ks = 0; ks < 2; ks++) {
            uint32_t ah[4][4], al[4][4];
#pragma unroll
            for (int mf = 0; mf < 4; mf++) {
                uint32_t addr = sa + (uint32_t)((warp_m * 64 + mf * 16 + arow) * 40 + ks * 16 + acol) * 2;
                ldsm_x4(ah[mf][0], ah[mf][1], ah[mf][2], ah[mf][3], addr);
                if (AT == 2)
                    ldsm_x4(al[mf][0], al[mf][1], al[mf][2], al[mf][3], addr + 10240);
            }
            uint32_t bh[4][4], bl[4][4];
#pragma unroll
            for (int nf2 = 0; nf2 < 4; nf2++) {
                uint32_t addr = sa + OB + (uint32_t)((warp_n * 64 + nf2 * 16 + brow) * 40 + ks * 16 + bcol) * 2;
                ldsm_x4(bh[nf2][0], bh[nf2][1], bh[nf2][2], bh[nf2][3], addr);
                if (BT == 2)
                    ldsm_x4(bl[nf2][0], bl[nf2][1], bl[nf2][2], bl[nf2][3], addr + 20480);
            }
#pragma unroll
            for (int mf = 0; mf < 4; mf++)
#pragma unroll
                for (int nf = 0; nf < 8; nf++) {
                    int nf2 = nf >> 1, o = (nf & 1) * 2;
                    mma16816(acc[mf][nf], ah[mf], bh[nf2][o], bh[nf2][o + 1]);
                    if (BT == 2)
                        mma16816(acc[mf][nf], ah[mf], bl[nf2][o], bl[nf2][o + 1]);
                    if (AT == 2)
                        mma16816(acc[mf][nf], al[mf], bh[nf2][o], bh[nf2][o + 1]);
                }
        }
        __syncthreads();
    }

    const int gr = lane >> 2, q = lane & 3;
    if (EPI == 0) {
#pragma unroll
        for (int mf = 0; mf < 4; mf++)
#pragma unroll
            for (int nf = 0; nf < 8; nf++) {
                int row = m0 + warp_m * 64 + mf * 16 + gr;
                int col = n0 + warp_n * 64 + nf * 8 + q * 2;
                *reinterpret_cast<float2*>(C + (size_t)row * ldw + col) =
                    make_float2(acc[mf][nf][0], acc[mf][nf][1]);
                *reinterpret_cast<float2*>(C + (size_t)(row + 8) * ldw + col) =
                    make_float2(acc[mf][nf][2], acc[mf][nf][3]);
            }
        float rm[8], rs[8];
#pragma unroll
        for (int mf = 0; mf < 4; mf++) {
            float ma = -1e30f, mb = -1e30f;
#pragma unroll
            for (int nf = 0; nf < 8; nf++) {
                ma = fmaxf(ma, fmaxf(acc[mf][nf][0], acc[mf][nf][1]));
                mb = fmaxf(mb, fmaxf(acc[mf][nf][2], acc[mf][nf][3]));
            }
            float sa = 0.f, sb = 0.f;
#pragma unroll
            for (int nf = 0; nf < 8; nf++) {
                sa += __expf(acc[mf][nf][0] - ma) + __expf(acc[mf][nf][1] - ma);
                sb += __expf(acc[mf][nf][2] - mb) + __expf(acc[mf][nf][3] - mb);
            }
            rm[2 * mf] = ma;  rs[2 * mf] = sa;
            rm[2 * mf + 1] = mb;  rs[2 * mf + 1] = sb;
        }
#pragma unroll
        for (int o = 1; o < 4; o <<= 1)
#pragma unroll
            for (int k = 0; k < 8; k++) {
                float mo = __shfl_xor_sync(0xffffffffu, rm[k], o);
                float so = __shfl_xor_sync(0xffffffffu, rs[k], o);
                msmerge(rm[k], rs[k], mo, so);
            }
        float cm[16], cs[16];
#pragma unroll
        for (int nf = 0; nf < 8; nf++)
#pragma unroll
            for (int b = 0; b < 2; b++) {
                int i = nf * 2 + b;
                float mv = -1e30f;
#pragma unroll
                for (int mf = 0; mf < 4; mf++)
                    mv = fmaxf(mv, fmaxf(acc[mf][nf][b], acc[mf][nf][b + 2]));
                float sv = 0.f;
#pragma unroll
                for (int mf = 0; mf < 4; mf++)
                    sv += __expf(acc[mf][nf][b] - mv) + __expf(acc[mf][nf][b + 2] - mv);
                cm[i] = mv;  cs[i] = sv;
            }
#pragma unroll
        for (int o = 4; o < 32; o <<= 1)
#pragma unroll
            for (int k = 0; k < 16; k++) {
                float mo = __shfl_xor_sync(0xffffffffu, cm[k], o);
                float so = __shfl_xor_sync(0xffffffffu, cs[k], o);
                msmerge(cm[k], cs[k], mo, so);
            }
        float* rowm  = reinterpret_cast<float*>(smem);
        float* rows_ = rowm + 512;
        float* colm  = rows_ + 512;
        float* cols_ = colm + 512;
        if (q == 0) {
#pragma unroll
            for (int mf = 0; mf < 4; mf++) {
                int lr = warp_m * 64 + mf * 16 + gr;
                rowm [lr * 4 + warp_n] = rm[2 * mf];
                rows_[lr * 4 + warp_n] = rs[2 * mf];
                rowm [(lr + 8) * 4 + warp_n] = rm[2 * mf + 1];
                rows_[(lr + 8) * 4 + warp_n] = rs[2 * mf + 1];
            }
        }
        if (lane < 4) {
#pragma unroll
            for (int nf = 0; nf < 8; nf++)
#pragma unroll
                for (int b = 0; b < 2; b++) {
                    int cc = warp_n * 64 + nf * 8 + lane * 2 + b;
                    colm [warp_m * 256 + cc] = cm[nf * 2 + b];
                    cols_[warp_m * 256 + cc] = cs[nf * 2 + b];
                }
        }
        __syncthreads();
        if (tid < 128) {
            float M = rowm[tid * 4], S = rows_[tid * 4];
#pragma unroll
            for (int w = 1; w < 4; w++) msmerge(M, S, rowm[tid * 4 + w], rows_[tid * 4 + w]);
            rpm[(size_t)(m0 + tid) * 32 + blockIdx.x] = M;
            rps[(size_t)(m0 + tid) * 32 + blockIdx.x] = S;
        }
        {
            float M = colm[tid], S = cols_[tid];
            msmerge(M, S, colm[256 + tid], cols_[256 + tid]);
            cpm[(size_t)(n0 + tid) * 64 + blockIdx.y] = M;
            cps[(size_t)(n0 + tid) * 64 + blockIdx.y] = S;
        }
    } else {
        float rsum[8];
#pragma unroll
        for (int k = 0; k < 8; k++) rsum[k] = 0.f;
#pragma unroll
        for (int mf = 0; mf < 4; mf++) {
            int row = m0 + warp_m * 64 + mf * 16 + gr;
            float bj0 = (row < Mvalid)     ? bias[row]     : 0.f;
            float bj1 = (row + 8 < Mvalid) ? bias[row + 8] : 0.f;
#pragma unroll
            for (int nf = 0; nf < 8; nf++) {
                rsum[mf * 2]     += tanhf(acc[mf][nf][0] + bj0) + tanhf(acc[mf][nf][1] + bj0);
                rsum[mf * 2 + 1] += tanhf(acc[mf][nf][2] + bj1) + tanhf(acc[mf][nf][3] + bj1);
            }
        }
#pragma unroll
        for (int o = 1; o < 4; o <<= 1)
#pragma unroll
            for (int k = 0; k < 8; k++) rsum[k] += __shfl_xor_sync(0xffffffffu, rsum[k], o);
        __syncthreads();
        float* red = reinterpret_cast<float*>(smem);
        if (q == 0) {
#pragma unroll
            for (int mf = 0; mf < 4; mf++) {
                int lr = warp_m * 64 + mf * 16 + gr;
                red[lr * 4 + warp_n]       = rsum[mf * 2];
                red[(lr + 8) * 4 + warp_n] = rsum[mf * 2 + 1];
            }
        }
        __syncthreads();
        if (tid < 128) {
            float s = red[tid * 4] + red[tid * 4 + 1] + red[tid * 4 + 2] + red[tid * 4 + 3];
            int f = m0 + tid;
            if (f < Mvalid) tpart[(size_t)f * gridDim.x + blockIdx.x] = s;
        }
    }
}

// ======================= merge softmax stat partials (store M and S) =======================
__global__ void stats_merge_kernel()
{
    int g = blockIdx.x * 8 + (threadIdx.x >> 5);
    int lane = threadIdx.x & 31;
    if (g < N1V) {
        float m = g_rpm[(size_t)g * 32 + lane];
        float s = g_rps[(size_t)g * 32 + lane];
#pragma unroll
        for (int o = 16; o; o >>= 1) {
            float mo = __shfl_xor_sync(0xffffffffu, m, o);
            float so = __shfl_xor_sync(0xffffffffu, s, o);
            msmerge(m, s, mo, so);
        }
        if (lane == 0) { g_rmax[g] = m; g_rsum[g] = s; }
    } else {
        int c = g - N1V;
        float m = g_cpm[(size_t)c * 64 + lane];
        float s = g_cps[(size_t)c * 64 + lane];
        msmerge(m, s, g_cpm[(size_t)c * 64 + 32 + lane], g_cps[(size_t)c * 64 + 32 + lane]);
#pragma unroll
        for (int o = 16; o; o >>= 1) {
            float mo = __shfl_xor_sync(0xffffffffu, m, o);
            float so = __shfl_xor_sync(0xffffffffu, s, o);
            msmerge(m, s, mo, so);
        }
        if (lane == 0) { g_cmax[c] = m; g_csum[c] = s; }
    }
}

// ======================= selection: rows (alpha2), single pass, indices only =======================
__global__ void select_rows_kernel()
{
    int row = blockIdx.x;
    int t = threadIdx.x, lane = t & 31, w = t >> 5;
    const float* r = g_raw + (size_t)row * N2V;
    float thr = g_rmax[row] - STHR;
    int base = t * 32;
    uint32_t mask = 0;
    int c = 0;
#pragma unroll 8
    for (int k = 0; k < 32; k++) {
        bool p = r[base + k] > thr;
        mask |= (uint32_t)p << k;
        c += p ? 1 : 0;
    }
    int v = c;
#pragma unroll
    for (int o = 1; o < 32; o <<= 1) {
        int u = __shfl_up_sync(0xffffffffu, v, o);
        if (lane >= o) v += u;
    }
    __shared__ int wt[8];
    if (lane == 31) wt[w] = v;
    __syncthreads();
    int woff = 0;
#pragma unroll
    for (int s = 0; s < 8; s++) if (s < w) woff += wt[s];
    int off = woff + v - c;
    while (mask) {
        int k = __ffs(mask) - 1;
        mask &= mask - 1;
        if (off < SCAP) g_sel2_idx[(size_t)row * SCAP + off] = base + k;
        off++;
    }
    if (t == 0) {
        int total = wt[0] + wt[1] + wt[2] + wt[3] + wt[4] + wt[5] + wt[6] + wt[7];
        g_sel2_cnt[row] = total < SCAP ? total : SCAP;
    }
}

// ======================= selection: cols (alpha1), single pass via smem bitmasks =======================
__global__ void select_cols_kernel()
{
    __shared__ uint32_t masks[256][32];
    __shared__ int scnt[8][32];
    int lane = threadIdx.x & 31, w = threadIdx.x >> 5;
    int col = blockIdx.x * 32 + lane;
    float thr = g_cmax[col] - STHR;
    int r0 = w * 1024;
    int c = 0;
    for (int word = 0; word < 32; word++) {
        uint32_t m = 0;
#pragma unroll 8
        for (int b = 0; b < 32; b++) {
            bool p = g_raw[(size_t)(r0 + word * 32 + b) * N2V + col] > thr;
            m |= (uint32_t)p << b;
            c += p ? 1 : 0;
        }
        masks[threadIdx.x][word] = m;
    }
    scnt[w][lane] = c;
    __syncthreads();
    int off = 0, total = 0;
#pragma unroll
    for (int s = 0; s < 8; s++) {
        if (s < w) off += scnt[s][lane];
        total += scnt[s][lane];
    }
    for (int word = 0; word < 32; word++) {
        uint32_t m = masks[threadIdx.x][word];
        while (m) {
            int b = __ffs(m) - 1;
            m &= m - 1;
            if (off < SCAP) g_sel1_idx[(size_t)col * SCAP + off] = r0 + word * 32 + b;
            off++;
        }
    }
    if (w == 0) g_sel1_cnt[col] = total < SCAP ? total : SCAP;
}

// ======================= refine: exact fp32 logits + exact stats for selected entries =======================
// A[row]·B[j] for each selected j; rebuild (M, S) exactly; write exact weights.
__global__ void refine_kernel(const float* __restrict__ Arow, const float* __restrict__ Bmat,
                              const int* __restrict__ cnt, const int* __restrict__ idx,
                              float* __restrict__ wgt,
                              const float* __restrict__ gM, const float* __restrict__ gS,
                              const float* __restrict__ rawp, long rawPitch, int rawIsRow)
{
    __shared__ float a[DD];
    __shared__ float xs[SCAP];
    __shared__ float red[8];
    int row = blockIdx.x;
    int t = threadIdx.x, lane = t & 31, w = t >> 5;
    int n = cnt[row];
#pragma unroll
    for (int k = 0; k < 4; k++) a[t + k * 256] = Arow[(size_t)row * DD + t + k * 256];
    __syncthreads();
    for (int s = 0; s < n; s++) {
        int j = idx[(size_t)row * SCAP + s];
        const float* b = Bmat + (size_t)j * DD;
        float p = 0.f;
#pragma unroll
        for (int k = 0; k < 4; k++) p += a[t + k * 256] * b[t + k * 256];
#pragma unroll
        for (int o = 16; o; o >>= 1) p += __shfl_xor_sync(0xffffffffu, p, o);
        if (lane == 0) red[w] = p;
        __syncthreads();
        if (t == 0) xs[s] = red[0] + red[1] + red[2] + red[3] + red[4] + red[5] + red[6] + red[7];
        __syncthreads();
    }
    if (t == 0) {
        float Mapp = gM[row], Sapp = gS[row];
        float Mn = -1e30f;
        for (int s = 0; s < n; s++) Mn = fmaxf(Mn, xs[s]);
        float S = Sapp * __expf(Mapp - Mn);
        for (int s = 0; s < n; s++) {
            int j = idx[(size_t)row * SCAP + s];
            float xa = rawIsRow ? rawp[(size_t)row * rawPitch + j]
                                : rawp[(size_t)j * rawPitch + row];
            S += __expf(xs[s] - Mn) - __expf(xa - Mn);
        }
        float inv = 1.0f / S;
        for (int s = 0; s < n; s++)
            wgt[(size_t)row * SCAP + s] = __expf(xs[s] - Mn) * inv;
    }
}

// ======================= gather: att[row] = sum_t w_t * src[idx_t] =======================
__global__ void gather_att_kernel(const int* __restrict__ cnt, const int* __restrict__ idx,
                                  const float* __restrict__ wgt, const float* __restrict__ src,
                                  __half* __restrict__ dst)
{
    int row = blockIdx.x;
    int t = threadIdx.x;
    int n = cnt[row];
    float a0 = 0.f, a1 = 0.f, a2 = 0.f, a3 = 0.f;
    for (int k = 0; k < n; k++) {
        int j = idx[(size_t)row * SCAP + k];
        float w = wgt[(size_t)row * SCAP + k];
        float4 v = *reinterpret_cast<const float4*>(src + (size_t)j * DD + t * 4);
        a0 += w * v.x; a1 += w * v.y; a2 += w * v.z; a3 += w * v.w;
    }
    __half2* d = reinterpret_cast<__half2*>(dst + (size_t)row * DD + t * 4);
    d[0] = __floats2half2_rn(a0, a1);
    d[1] = __floats2half2_rn(a2, a3);
}

// ======================= column sums of fp16 att -> sumv =======================
__global__ void colsum_kernel(const __half* __restrict__ att, float* __restrict__ sumv)
{
    int lane = threadIdx.x & 31, w = threadIdx.x >> 5;
    int col = blockIdx.x * 32 + lane;
    float s = 0.f;
#pragma unroll 8
    for (int r = 0; r < 1024; r++)
        s += __half2float(att[(size_t)(w * 1024 + r) * DD + col]);
    __shared__ float sh[8][33];
    sh[w][lane] = s;
    __syncthreads();
    if (threadIdx.x < 32) {
        float t = 0.f;
#pragma unroll
        for (int q = 0; q < 8; q++) t += sh[q][threadIdx.x];
        sumv[blockIdx.x * 32 + threadIdx.x] = t;
    }
}

// ======================= prep: fp32 -> fp16 cast (optionally row-padded) =======================
__global__ void cast_kernel(const float* __restrict__ src, __half* __restrict__ dh,
                            int R, int C, int Rpad)
{
    int idx = blockIdx.x * 256 + threadIdx.x;
    if (idx >= Rpad * C) return;
    int r = idx / C;
    float v = (r < R) ? src[idx] : 0.f;
    dh[idx] = __float2half_rn(v);
}

// ======================= finalize =======================
__global__ void finalize_kernel(const float* __restrict__ Wf1, const float* __restrict__ bf1,
                                const float* __restrict__ Wf2, const float* __restrict__ bf2,
                                float* __restrict__ out)
{
    int g = blockIdx.x * 8 + (threadIdx.x >> 5);
    int lane = threadIdx.x & 31;
    const float inv = 1.0f / 8192.0f;
    if (g < FF) {
        const float* w = Wf1 + (size_t)g * DD;
        float d = 0.f;
        for (int l = lane; l < DD; l += 32) d += w[l] * g_sumv2[l];
#pragma unroll
        for (int o = 16; o; o >>= 1) d += __shfl_xor_sync(0xffffffffu, d, o);
        if (lane == 0) {
            float filt = 1.0f / (1.0f + __expf(-(d * inv + bf1[g])));
            float t = 0.f;
#pragma unroll
            for (int b = 0; b < 32; b++) t += g_tpart1[g * 32 + b];
            out[g] = t * inv * filt;
        }
    } else if (g < 2 * FF) {
        int f = g - FF;
        const float* w = Wf2 + (size_t)f * DD;
        float d = 0.f;
        for (int l = lane; l < DD; l += 32) d += w[l] * g_sumv1[l];
#pragma unroll
        for (int o = 16; o; o >>= 1) d += __shfl_xor_sync(0xffffffffu, d, o);
        if (lane == 0) {
            float filt = 1.0f / (1.0f + __expf(-(d * inv + bf2[f])));
            float t = 0.f;
#pragma unroll
            for (int b = 0; b < 32; b++) t += g_tpart2[f * 32 + b];
            out[FF + f] = t * inv * filt;
        }
    }
}

// ======================= launch =======================
extern "C" void kernel_launch(void* const* d_in, const int* in_sizes, int n_in,
                              void* d_out, int out_size)
{
    const float* m1  = (const float*)d_in[0];
    const float* m2  = (const float*)d_in[1];
    const float* Wf1 = (const float*)d_in[2];
    const float* bf1 = (const float*)d_in[3];
    const float* Wf2 = (const float*)d_in[4];
    const float* bf2 = (const float*)d_in[5];
    const float* W1  = (const float*)d_in[6];
    const float* b1  = (const float*)d_in[7];
    const float* W2  = (const float*)d_in[8];
    const float* b2  = (const float*)d_in[9];
    float* out = (float*)d_out;

    float *raw, *tpart1, *tpart2, *rpm, *rps, *cpm, *cps, *sumv1, *sumv2;
    float *sel2w, *sel1w, *rmax, *rsum, *cmax, *csum;
    int *sel2i, *sel2c, *sel1i, *sel1c;
    __half *m1h, *m2h, *att1h, *att2h, *w1h, *w2h;
    cudaGetSymbolAddress((void**)&raw,   g_raw);
    cudaGetSymbolAddress((void**)&m1h,   g_m1h);
    cudaGetSymbolAddress((void**)&m2h,   g_m2h);
    cudaGetSymbolAddress((void**)&att1h, g_att1h);
    cudaGetSymbolAddress((void**)&att2h, g_att2h);
    cudaGetSymbolAddress((void**)&w1h,   g_w1h);
    cudaGetSymbolAddress((void**)&w2h,   g_w2h);
    cudaGetSymbolAddress((void**)&tpart1, g_tpart1);
    cudaGetSymbolAddress((void**)&tpart2, g_tpart2);
    cudaGetSymbolAddress((void**)&rpm, g_rpm);
    cudaGetSymbolAddress((void**)&rps, g_rps);
    cudaGetSymbolAddress((void**)&cpm, g_cpm);
    cudaGetSymbolAddress((void**)&cps, g_cps);
    cudaGetSymbolAddress((void**)&sel2i, g_sel2_idx);
    cudaGetSymbolAddress((void**)&sel2w, g_sel2_w);
    cudaGetSymbolAddress((void**)&sel2c, g_sel2_cnt);
    cudaGetSymbolAddress((void**)&sel1i, g_sel1_idx);
    cudaGetSymbolAddress((void**)&sel1w, g_sel1_w);
    cudaGetSymbolAddress((void**)&sel1c, g_sel1_cnt);
    cudaGetSymbolAddress((void**)&sumv1, g_sumv1);
    cudaGetSymbolAddress((void**)&sumv2, g_sumv2);
    cudaGetSymbolAddress((void**)&rmax, g_rmax);
    cudaGetSymbolAddress((void**)&rsum, g_rsum);
    cudaGetSymbolAddress((void**)&cmax, g_cmax);
    cudaGetSymbolAddress((void**)&csum, g_csum);

    cudaFuncSetAttribute(hgemm<1, 1, 0>, cudaFuncAttributeMaxDynamicSharedMemorySize, 92160);
    cudaFuncSetAttribute(hgemm<1, 1, 2>, cudaFuncAttributeMaxDynamicSharedMemorySize, 92160);

    // 0) prep: cast inputs to fp16 (hi only)
    cast_kernel<<<(N1V * DD + 255) / 256, 256>>>(m1, m1h, N1V, DD, N1V);
    cast_kernel<<<(N2V * DD + 255) / 256, 256>>>(m2, m2h, N2V, DD, N2V);
    cast_kernel<<<(FPAD * DD + 255) / 256, 256>>>(W1, w1h, FF, DD, FPAD);
    cast_kernel<<<(FPAD * DD + 255) / 256, 256>>>(W2, w2h, FF, DD, FPAD);

    // 1) approx raw = m1 @ m2^T, K=1024, pure fp16 1-term + fused softmax stat partials
    hgemm<1, 1, 0><<<dim3(N2V / 256, N1V / 128), 256, 92160>>>(
        m1h, nullptr, m2h, nullptr, raw, N2V, DD, DD / 32, N1V,
        nullptr, nullptr, rpm, rps, cpm, cps);

    // 2) merge approx stats (M, S)
    stats_merge_kernel<<<(N1V + N2V) / 8, 256>>>();

    // 3) threshold selection (20-nat margin; approx errors ~7e-3 are irrelevant)
    select_rows_kernel<<<N1V, 256>>>();
    select_cols_kernel<<<N2V / 32, 256>>>();

    // 4) refine: exact fp32 logits for selected entries, exact (M, S), exact weights
    refine_kernel<<<N1V, 256>>>(m1, m2, sel2c, sel2i, sel2w, rmax, rsum, raw, N2V, 1);
    refine_kernel<<<N2V, 256>>>(m2, m1, sel1c, sel1i, sel1w, cmax, csum, raw, N2V, 0);

    // 5) gather attended matrices in fp32, store fp16
    gather_att_kernel<<<N1V, 256>>>(sel2c, sel2i, sel2w, m2, att2h);
    gather_att_kernel<<<N2V, 256>>>(sel1c, sel1i, sel1w, m1, att1h);

    // 6) column sums for the filter path
    colsum_kernel<<<DD / 32, 256>>>(att1h, sumv1);
    colsum_kernel<<<DD / 32, 256>>>(att2h, sumv2);

    // 7) transform: [F x N] = W @ att^T, fp16, fused tanh+rowsum
    hgemm<1, 1, 2><<<dim3(N2V / 256, FPAD / 128), 256, 92160>>>(
        w1h, nullptr, att1h, nullptr, nullptr, 0, DD, DD / 32, FF,
        b1, tpart1, nullptr, nullptr, nullptr, nullptr);
    hgemm<1, 1, 2><<<dim3(N1V / 256, FPAD / 128), 256, 92160>>>(
        w2h, nullptr, att2h, nullptr, nullptr, 0, DD, DD / 32, FF,
        b2, tpart2, nullptr, nullptr, nullptr, nullptr);

    // 8) filters + outputs
    finalize_kernel<<<200, 256>>>(Wf1, bf1, Wf2, bf2, out);
}